// round 4
// baseline (speedup 1.0000x reference)
#include <cuda_runtime.h>
#include <cstdint>

// ODE-RNN fused persistent scan kernel, round 4.
// grid 256 x 8 rows x 256 threads, 2 CTAs/SM. Per-thread tiles r=4 (weight
// reuse: l1tex demand ~132 B/cyc vs 128 budget), K-split + shfl.bfly f32x2
// reduction to keep threads busy, fast exp-based tanh/sigmoid.

#define R_PER_CTA 8
#define NSTEPS 199
#define TT 200
#define DD 64
#define HH 100

typedef unsigned long long u64;

__device__ __forceinline__ void fma2(u64& d, u64 a, u64 b) {
    asm("fma.rn.f32x2 %0, %1, %2, %0;" : "+l"(d) : "l"(a), "l"(b));
}
__device__ __forceinline__ u64 dup2(float x) {
    u64 r; asm("mov.b64 %0, {%1, %1};" : "=l"(r) : "f"(x)); return r;
}
__device__ __forceinline__ float2 unpack2(u64 v) {
    float2 r; asm("mov.b64 {%0, %1}, %2;" : "=f"(r.x), "=f"(r.y) : "l"(v)); return r;
}
__device__ __forceinline__ float tanh_fast(float x) {
    // tanh(x) = 1 - 2/(exp(2x)+1); exact at both saturation ends with __expf/__fdividef.
    const float e = __expf(2.0f * x);
    return 1.0f - __fdividef(2.0f, e + 1.0f);
}
__device__ __forceinline__ float sigmoid_fast(float x) {
    return __fdividef(1.0f, 1.0f + __expf(-x));
}

template<int N>
__device__ __forceinline__ void bfly_add(u64* a, int mask) {
#pragma unroll
    for (int i = 0; i < N; ++i) {
        u64 o = __shfl_xor_sync(0xffffffffu, a[i], mask);
        asm("add.rn.f32x2 %0, %0, %1;" : "+l"(a[i]) : "l"(o));
    }
}

// 4-row x 4-col tile over k in [k0,k1), cols packed pairwise (acc[row*2+half]).
template<int LDW>
__device__ __forceinline__ void acc_r4c4(
    const float* __restrict__ w,
    const float* __restrict__ s0, const float* __restrict__ s1,
    const float* __restrict__ s2, const float* __restrict__ s3,
    int k0, int k1, u64 acc[8])
{
    for (int k = k0; k < k1; k += 4) {
        const float4 y0 = *reinterpret_cast<const float4*>(s0 + k);
        const float4 y1 = *reinterpret_cast<const float4*>(s1 + k);
        const float4 y2 = *reinterpret_cast<const float4*>(s2 + k);
        const float4 y3 = *reinterpret_cast<const float4*>(s3 + k);
        const float y0a[4] = {y0.x, y0.y, y0.z, y0.w};
        const float y1a[4] = {y1.x, y1.y, y1.z, y1.w};
        const float y2a[4] = {y2.x, y2.y, y2.z, y2.w};
        const float y3a[4] = {y3.x, y3.y, y3.z, y3.w};
#pragma unroll
        for (int j = 0; j < 4; ++j) {
            const ulonglong2 wv = *reinterpret_cast<const ulonglong2*>(w + (k + j) * LDW);
            const u64 d0 = dup2(y0a[j]);
            const u64 d1 = dup2(y1a[j]);
            const u64 d2 = dup2(y2a[j]);
            const u64 d3 = dup2(y3a[j]);
            fma2(acc[0], d0, wv.x); fma2(acc[1], d0, wv.y);
            fma2(acc[2], d1, wv.x); fma2(acc[3], d1, wv.y);
            fma2(acc[4], d2, wv.x); fma2(acc[5], d2, wv.y);
            fma2(acc[6], d3, wv.x); fma2(acc[7], d3, wv.y);
        }
    }
}

// 4-row x 2-col tile (acc[row]).
template<int LDW>
__device__ __forceinline__ void acc_r4c2(
    const float* __restrict__ w,
    const float* __restrict__ s0, const float* __restrict__ s1,
    const float* __restrict__ s2, const float* __restrict__ s3,
    int k0, int k1, u64 acc[4])
{
    for (int k = k0; k < k1; k += 4) {
        const float4 y0 = *reinterpret_cast<const float4*>(s0 + k);
        const float4 y1 = *reinterpret_cast<const float4*>(s1 + k);
        const float4 y2 = *reinterpret_cast<const float4*>(s2 + k);
        const float4 y3 = *reinterpret_cast<const float4*>(s3 + k);
        const float y0a[4] = {y0.x, y0.y, y0.z, y0.w};
        const float y1a[4] = {y1.x, y1.y, y1.z, y1.w};
        const float y2a[4] = {y2.x, y2.y, y2.z, y2.w};
        const float y3a[4] = {y3.x, y3.y, y3.z, y3.w};
#pragma unroll
        for (int j = 0; j < 4; ++j) {
            const u64 wv = *reinterpret_cast<const u64*>(w + (k + j) * LDW);
            fma2(acc[0], dup2(y0a[j]), wv);
            fma2(acc[1], dup2(y1a[j]), wv);
            fma2(acc[2], dup2(y2a[j]), wv);
            fma2(acc[3], dup2(y3a[j]), wv);
        }
    }
}

__global__ void __launch_bounds__(256, 2) ode_rnn_kernel(
    const float* __restrict__ data, const float* __restrict__ ts,
    const float* __restrict__ Wf1, const float* __restrict__ bf1,
    const float* __restrict__ Wf2, const float* __restrict__ bf2,
    const float* __restrict__ Wz1, const float* __restrict__ bz1,
    const float* __restrict__ Wz2, const float* __restrict__ bz2,
    const float* __restrict__ Wr1, const float* __restrict__ br1,
    const float* __restrict__ Wr2, const float* __restrict__ br2,
    const float* __restrict__ Wh1, const float* __restrict__ bh1,
    const float* __restrict__ Wh2, const float* __restrict__ bh2,
    float* __restrict__ yi_out, float* __restrict__ lat_out)
{
    __shared__ float sY [R_PER_CTA][68];   // latent y
    __shared__ float sYO[R_PER_CTA][68];   // y_ode
    __shared__ float sC [R_PER_CTA][132];  // [0:64) y_ode (later y_ode*r), [64:128) x
    __shared__ float sH [R_PER_CTA][204];  // hidden acts (z-hid | r-hid, or f/h hid)
    __shared__ float sZ [R_PER_CTA][68];   // z gate
    __shared__ float sbf1[HH], sbz1[HH], sbr1[HH], sbh1[HH];
    __shared__ float sbf2[DD], sbz2[DD], sbr2[DD], sbh2[DD];
    __shared__ float sts[TT];

    const int tid = threadIdx.x;
    const int lane = tid & 31;
    const int wid = tid >> 5;
    const int rowbase = blockIdx.x * R_PER_CTA;

    for (int i = tid; i < HH; i += 256) {
        sbf1[i] = bf1[i]; sbz1[i] = bz1[i]; sbr1[i] = br1[i]; sbh1[i] = bh1[i];
    }
    for (int i = tid; i < DD; i += 256) {
        sbf2[i] = bf2[i]; sbz2[i] = bz2[i]; sbr2[i] = br2[i]; sbh2[i] = bh2[i];
    }
    for (int i = tid; i < TT; i += 256) sts[i] = ts[i];
    for (int i = tid; i < R_PER_CTA * 68; i += 256) (&sY[0][0])[i] = 0.0f;
    __syncthreads();

    // copy lanes: first 128 threads move 8 rows x 64 cols as float4
    const int cr  = tid >> 4;          // row (valid when tid<128)
    const int cd4 = (tid & 15) * 4;

    // ks4 mapping: raw tile = wid*8 + (lane&7); part = lane>>3 (bfly 8,16)
    const int raw8  = wid * 8 + (lane & 7);
    const int part4 = lane >> 3;
    // ks2 mapping: raw tile = wid*16 + (lane&15); part = lane>>4 (bfly 16)
    const int raw16 = wid * 16 + (lane & 15);
    const int part2 = lane >> 4;

    // K=100 split into 4 aligned parts: [0,28) [28,52) [52,76) [76,100)
    const int k0_100 = part4 ? 28 + (part4 - 1) * 24 : 0;
    const int k1_100 = 28 + part4 * 24;

    for (int step = 0; step < NSTEPS; ++step) {
        const float dt = (step == 0) ? (sts[1] - sts[0]) : (sts[step - 1] - sts[step]);

        // load x(t=step+1) into sC[:,64:128)
        if (tid < 128) {
            const float4 v = *reinterpret_cast<const float4*>(
                data + (((size_t)(rowbase + cr)) * TT + (step + 1)) * DD + cd4);
            *reinterpret_cast<float4*>(&sC[cr][64 + cd4]) = v;
        }

        // ---- P1: sH[:,0:100) = tanh(bf1 + Y @ Wf1); K=64. r4c4, ks4 (NT=50) ----
        {
            const int tile = raw8 < 50 ? raw8 : 49;
            const int r0 = (tile / 25) * 4, n0 = (tile % 25) * 4;
            const int k0 = part4 * 16, k1 = k0 + 16;
            u64 acc[8] = {};
            acc_r4c4<100>(Wf1 + n0, &sY[r0][0], &sY[r0+1][0], &sY[r0+2][0], &sY[r0+3][0],
                          k0, k1, acc);
            bfly_add<8>(acc, 8); bfly_add<8>(acc, 16);
            if (part4 == 0 && raw8 < 50) {
#pragma unroll
                for (int rr = 0; rr < 4; ++rr) {
                    const float2 p0 = unpack2(acc[rr*2]), p1 = unpack2(acc[rr*2+1]);
                    sH[r0+rr][n0  ] = tanh_fast(p0.x + sbf1[n0  ]);
                    sH[r0+rr][n0+1] = tanh_fast(p0.y + sbf1[n0+1]);
                    sH[r0+rr][n0+2] = tanh_fast(p1.x + sbf1[n0+2]);
                    sH[r0+rr][n0+3] = tanh_fast(p1.y + sbf1[n0+3]);
                }
            }
        }
        __syncthreads();

        // ---- P2: y_ode = Y + dt*(bf2 + H @ Wf2); K=100, N=64. r4c2, ks4 (NT=64) ----
        {
            const int r0 = (raw8 >> 5) * 4, n0 = (raw8 & 31) * 2;
            u64 acc[4] = {};
            acc_r4c2<64>(Wf2 + n0, &sH[r0][0], &sH[r0+1][0], &sH[r0+2][0], &sH[r0+3][0],
                         k0_100, k1_100, acc);
            bfly_add<4>(acc, 8); bfly_add<4>(acc, 16);
            if (part4 == 0) {
#pragma unroll
                for (int rr = 0; rr < 4; ++rr) {
                    const float2 p = unpack2(acc[rr]);
                    const float v0 = sY[r0+rr][n0  ] + dt * (p.x + sbf2[n0  ]);
                    const float v1 = sY[r0+rr][n0+1] + dt * (p.y + sbf2[n0+1]);
                    sYO[r0+rr][n0  ] = v0; sC[r0+rr][n0  ] = v0;
                    sYO[r0+rr][n0+1] = v1; sC[r0+rr][n0+1] = v1;
                }
            }
        }
        __syncthreads();

        // ---- P3: z/r hidden = tanh(b + C @ W1); K=128, 200 logical cols. r4c4, ks2 (NT=100) ----
        {
            const int tile = raw16 < 100 ? raw16 : 99;
            const int r0 = (tile / 50) * 4;
            const int n0l = (tile % 50) * 4;
            const bool isz = (n0l < 100);
            const int m0 = isz ? n0l : n0l - 100;
            const float* w  = (isz ? Wz1 : Wr1) + m0;
            const float* bb = isz ? sbz1 : sbr1;
            const int k0 = part2 * 64, k1 = k0 + 64;
            u64 acc[8] = {};
            acc_r4c4<100>(w, &sC[r0][0], &sC[r0+1][0], &sC[r0+2][0], &sC[r0+3][0],
                          k0, k1, acc);
            bfly_add<8>(acc, 16);
            if (part2 == 0 && raw16 < 100) {
#pragma unroll
                for (int rr = 0; rr < 4; ++rr) {
                    const float2 p0 = unpack2(acc[rr*2]), p1 = unpack2(acc[rr*2+1]);
                    sH[r0+rr][n0l  ] = tanh_fast(p0.x + bb[m0  ]);
                    sH[r0+rr][n0l+1] = tanh_fast(p0.y + bb[m0+1]);
                    sH[r0+rr][n0l+2] = tanh_fast(p1.x + bb[m0+2]);
                    sH[r0+rr][n0l+3] = tanh_fast(p1.y + bb[m0+3]);
                }
            }
        }
        __syncthreads();

        // ---- P4: z = sig(bz2 + Hz@Wz2) -> sZ; r = sig(br2 + Hr@Wr2), sC[:,0:64)=y_ode*r
        //          K=100, 128 logical cols. r4c4, ks4 (NT=64) ----
        {
            const int r0 = (raw8 >> 5) * 4;
            const int n0 = (raw8 & 31) * 4;       // 0..124
            const bool isr = (n0 >= 64);
            const int m0 = n0 & 63;
            const float* w = (isr ? Wr2 : Wz2) + m0;
            const int ho = isr ? 100 : 0;
            u64 acc[8] = {};
            acc_r4c4<64>(w, &sH[r0][ho], &sH[r0+1][ho], &sH[r0+2][ho], &sH[r0+3][ho],
                         k0_100, k1_100, acc);
            bfly_add<8>(acc, 8); bfly_add<8>(acc, 16);
            if (part4 == 0) {
#pragma unroll
                for (int rr = 0; rr < 4; ++rr) {
                    const float2 p0 = unpack2(acc[rr*2]), p1 = unpack2(acc[rr*2+1]);
                    if (!isr) {
                        sZ[r0+rr][m0  ] = sigmoid_fast(p0.x + sbz2[m0  ]);
                        sZ[r0+rr][m0+1] = sigmoid_fast(p0.y + sbz2[m0+1]);
                        sZ[r0+rr][m0+2] = sigmoid_fast(p1.x + sbz2[m0+2]);
                        sZ[r0+rr][m0+3] = sigmoid_fast(p1.y + sbz2[m0+3]);
                    } else {
                        sC[r0+rr][m0  ] = sYO[r0+rr][m0  ] * sigmoid_fast(p0.x + sbr2[m0  ]);
                        sC[r0+rr][m0+1] = sYO[r0+rr][m0+1] * sigmoid_fast(p0.y + sbr2[m0+1]);
                        sC[r0+rr][m0+2] = sYO[r0+rr][m0+2] * sigmoid_fast(p1.x + sbr2[m0+2]);
                        sC[r0+rr][m0+3] = sYO[r0+rr][m0+3] * sigmoid_fast(p1.y + sbr2[m0+3]);
                    }
                }
            }
        }
        __syncthreads();

        // ---- P6: sH[:,0:100) = tanh(bh1 + CH @ Wh1); K=128. r4c4, ks4 (NT=50) ----
        {
            const int tile = raw8 < 50 ? raw8 : 49;
            const int r0 = (tile / 25) * 4, n0 = (tile % 25) * 4;
            const int k0 = part4 * 32, k1 = k0 + 32;
            u64 acc[8] = {};
            acc_r4c4<100>(Wh1 + n0, &sC[r0][0], &sC[r0+1][0], &sC[r0+2][0], &sC[r0+3][0],
                          k0, k1, acc);
            bfly_add<8>(acc, 8); bfly_add<8>(acc, 16);
            if (part4 == 0 && raw8 < 50) {
#pragma unroll
                for (int rr = 0; rr < 4; ++rr) {
                    const float2 p0 = unpack2(acc[rr*2]), p1 = unpack2(acc[rr*2+1]);
                    sH[r0+rr][n0  ] = tanh_fast(p0.x + sbh1[n0  ]);
                    sH[r0+rr][n0+1] = tanh_fast(p0.y + sbh1[n0+1]);
                    sH[r0+rr][n0+2] = tanh_fast(p1.x + sbh1[n0+2]);
                    sH[r0+rr][n0+3] = tanh_fast(p1.y + sbh1[n0+3]);
                }
            }
        }
        __syncthreads();

        // ---- P7: h = tanh(bh2 + H @ Wh2); y = (1-z)*h + z*y_ode; K=100, N=64. r4c2, ks4 ----
        {
            const int r0 = (raw8 >> 5) * 4, n0 = (raw8 & 31) * 2;
            u64 acc[4] = {};
            acc_r4c2<64>(Wh2 + n0, &sH[r0][0], &sH[r0+1][0], &sH[r0+2][0], &sH[r0+3][0],
                         k0_100, k1_100, acc);
            bfly_add<4>(acc, 8); bfly_add<4>(acc, 16);
            if (part4 == 0) {
#pragma unroll
                for (int rr = 0; rr < 4; ++rr) {
                    const float2 p = unpack2(acc[rr]);
#pragma unroll
                    for (int q = 0; q < 2; ++q) {
                        const int nn = n0 + q;
                        const float h = tanh_fast(((q == 0) ? p.x : p.y) + sbh2[nn]);
                        const float z = sZ[r0+rr][nn];
                        sY[r0+rr][nn] = (1.0f - z) * h + z * sYO[r0+rr][nn];
                    }
                }
            }
        }
        __syncthreads();

        // ---- write latent_ys[b][step][:] ----
        if (lat_out && tid < 128) {
            const float4 v = *reinterpret_cast<const float4*>(&sY[cr][cd4]);
            *reinterpret_cast<float4*>(
                lat_out + (((size_t)(rowbase + cr)) * NSTEPS + step) * DD + cd4) = v;
        }
    }

    if (yi_out && tid < 128) {
        const float4 v = *reinterpret_cast<const float4*>(&sY[cr][cd4]);
        *reinterpret_cast<float4*>(yi_out + ((size_t)(rowbase + cr)) * DD + cd4) = v;
    }
}

extern "C" void kernel_launch(void* const* d_in, const int* in_sizes, int n_in,
                              void* d_out, int out_size)
{
    const float* data = (const float*)d_in[0];
    const float* ts   = (const float*)d_in[1];
    const float* Wf1  = (const float*)d_in[2];
    const float* bf1  = (const float*)d_in[3];
    const float* Wf2  = (const float*)d_in[4];
    const float* bf2  = (const float*)d_in[5];
    const float* Wz1  = (const float*)d_in[6];
    const float* bz1  = (const float*)d_in[7];
    const float* Wz2  = (const float*)d_in[8];
    const float* bz2  = (const float*)d_in[9];
    const float* Wr1  = (const float*)d_in[10];
    const float* br1  = (const float*)d_in[11];
    const float* Wr2  = (const float*)d_in[12];
    const float* br2  = (const float*)d_in[13];
    const float* Wh1  = (const float*)d_in[14];
    const float* bh1  = (const float*)d_in[15];
    const float* Wh2  = (const float*)d_in[16];
    const float* bh2  = (const float*)d_in[17];

    const long long latN = 2048LL * 199 * 64;
    const long long yiN  = 2048LL * 64;
    float* out = (float*)d_out;
    float* yi_out = nullptr;
    float* lat_out = nullptr;
    if ((long long)out_size == latN + yiN) { yi_out = out; lat_out = out + yiN; }
    else if ((long long)out_size == latN)  { lat_out = out; }
    else if ((long long)out_size == yiN)   { yi_out = out; }
    else if ((long long)out_size > latN)   { yi_out = out; lat_out = out + yiN; }
    else                                   { lat_out = out; }

    ode_rnn_kernel<<<2048 / R_PER_CTA, 256>>>(
        data, ts, Wf1, bf1, Wf2, bf2, Wz1, bz1, Wz2, bz2,
        Wr1, br1, Wr2, br2, Wh1, bh1, Wh2, bh2, yi_out, lat_out);
}

// round 5
// speedup vs baseline: 1.0535x; 1.0535x over previous
#include <cuda_runtime.h>
#include <cstdint>

// ODE-RNN fused persistent scan, round 5.
// 256 CTAs x 256 threads, 8 rows/CTA, 2 CTAs/SM. r=4 row tiles everywhere,
// minimal K-split (bfly f32x2 reduce) for thread fill, fast tanh/sigmoid.

#define R_PER_CTA 8
#define NSTEPS 199
#define TT 200
#define DD 64
#define HH 100

typedef unsigned long long u64;

__device__ __forceinline__ void fma2(u64& d, u64 a, u64 b) {
    asm("fma.rn.f32x2 %0, %1, %2, %0;" : "+l"(d) : "l"(a), "l"(b));
}
__device__ __forceinline__ u64 dup2(float x) {
    u64 r; asm("mov.b64 %0, {%1, %1};" : "=l"(r) : "f"(x)); return r;
}
__device__ __forceinline__ float2 unpack2(u64 v) {
    float2 r; asm("mov.b64 {%0, %1}, %2;" : "=f"(r.x), "=f"(r.y) : "l"(v)); return r;
}
__device__ __forceinline__ float tanh_fast(float x) {
    const float e = __expf(2.0f * x);
    return 1.0f - __fdividef(2.0f, e + 1.0f);
}
__device__ __forceinline__ float sigmoid_fast(float x) {
    return __fdividef(1.0f, 1.0f + __expf(-x));
}

template<int N>
__device__ __forceinline__ void bfly_add(u64* a, int mask) {
#pragma unroll
    for (int i = 0; i < N; ++i) {
        u64 o = __shfl_xor_sync(0xffffffffu, a[i], mask);
        asm("add.rn.f32x2 %0, %0, %1;" : "+l"(a[i]) : "l"(o));
    }
}

// 4 rows x 2 cols (one u64 acc per row) over k in [k0,k1).
template<int LDW>
__device__ __forceinline__ void acc_r4c2(
    const float* __restrict__ w,
    const float* __restrict__ s0, const float* __restrict__ s1,
    const float* __restrict__ s2, const float* __restrict__ s3,
    int k0, int k1, u64 acc[4])
{
    for (int k = k0; k < k1; k += 4) {
        const float4 y0 = *reinterpret_cast<const float4*>(s0 + k);
        const float4 y1 = *reinterpret_cast<const float4*>(s1 + k);
        const float4 y2 = *reinterpret_cast<const float4*>(s2 + k);
        const float4 y3 = *reinterpret_cast<const float4*>(s3 + k);
        const float y0a[4] = {y0.x, y0.y, y0.z, y0.w};
        const float y1a[4] = {y1.x, y1.y, y1.z, y1.w};
        const float y2a[4] = {y2.x, y2.y, y2.z, y2.w};
        const float y3a[4] = {y3.x, y3.y, y3.z, y3.w};
#pragma unroll
        for (int j = 0; j < 4; ++j) {
            const u64 wv = *reinterpret_cast<const u64*>(w + (k + j) * LDW);
            fma2(acc[0], dup2(y0a[j]), wv);
            fma2(acc[1], dup2(y1a[j]), wv);
            fma2(acc[2], dup2(y2a[j]), wv);
            fma2(acc[3], dup2(y3a[j]), wv);
        }
    }
}

// 4 rows x 4 cols (two u64 accs per row) over k in [k0,k1).
template<int LDW>
__device__ __forceinline__ void acc_r4c4(
    const float* __restrict__ w,
    const float* __restrict__ s0, const float* __restrict__ s1,
    const float* __restrict__ s2, const float* __restrict__ s3,
    int k0, int k1, u64 acc[8])
{
    for (int k = k0; k < k1; k += 4) {
        const float4 y0 = *reinterpret_cast<const float4*>(s0 + k);
        const float4 y1 = *reinterpret_cast<const float4*>(s1 + k);
        const float4 y2 = *reinterpret_cast<const float4*>(s2 + k);
        const float4 y3 = *reinterpret_cast<const float4*>(s3 + k);
        const float y0a[4] = {y0.x, y0.y, y0.z, y0.w};
        const float y1a[4] = {y1.x, y1.y, y1.z, y1.w};
        const float y2a[4] = {y2.x, y2.y, y2.z, y2.w};
        const float y3a[4] = {y3.x, y3.y, y3.z, y3.w};
#pragma unroll
        for (int j = 0; j < 4; ++j) {
            const ulonglong2 wv = *reinterpret_cast<const ulonglong2*>(w + (k + j) * LDW);
            const u64 d0 = dup2(y0a[j]);
            const u64 d1 = dup2(y1a[j]);
            const u64 d2 = dup2(y2a[j]);
            const u64 d3 = dup2(y3a[j]);
            fma2(acc[0], d0, wv.x); fma2(acc[1], d0, wv.y);
            fma2(acc[2], d1, wv.x); fma2(acc[3], d1, wv.y);
            fma2(acc[4], d2, wv.x); fma2(acc[5], d2, wv.y);
            fma2(acc[6], d3, wv.x); fma2(acc[7], d3, wv.y);
        }
    }
}

__global__ void __launch_bounds__(256, 2) ode_rnn_kernel(
    const float* __restrict__ data, const float* __restrict__ ts,
    const float* __restrict__ Wf1, const float* __restrict__ bf1,
    const float* __restrict__ Wf2, const float* __restrict__ bf2,
    const float* __restrict__ Wz1, const float* __restrict__ bz1,
    const float* __restrict__ Wz2, const float* __restrict__ bz2,
    const float* __restrict__ Wr1, const float* __restrict__ br1,
    const float* __restrict__ Wr2, const float* __restrict__ br2,
    const float* __restrict__ Wh1, const float* __restrict__ bh1,
    const float* __restrict__ Wh2, const float* __restrict__ bh2,
    float* __restrict__ yi_out, float* __restrict__ lat_out)
{
    __shared__ float sY [R_PER_CTA][68];
    __shared__ float sYO[R_PER_CTA][68];
    __shared__ float sC [R_PER_CTA][132];  // [0:64) y_ode / y_ode*r, [64:128) x
    __shared__ float sH [R_PER_CTA][204];
    __shared__ float sZ [R_PER_CTA][68];
    __shared__ float sbf1[HH], sbz1[HH], sbr1[HH], sbh1[HH];
    __shared__ float sbf2[DD], sbz2[DD], sbr2[DD], sbh2[DD];
    __shared__ float sts[TT];

    const int tid = threadIdx.x;
    const int lane = tid & 31;
    const int wid = tid >> 5;
    const int rowbase = blockIdx.x * R_PER_CTA;

    for (int i = tid; i < HH; i += 256) {
        sbf1[i] = bf1[i]; sbz1[i] = bz1[i]; sbr1[i] = br1[i]; sbh1[i] = bh1[i];
    }
    for (int i = tid; i < DD; i += 256) {
        sbf2[i] = bf2[i]; sbz2[i] = bz2[i]; sbr2[i] = br2[i]; sbh2[i] = bh2[i];
    }
    for (int i = tid; i < TT; i += 256) sts[i] = ts[i];
    for (int i = tid; i < R_PER_CTA * 68; i += 256) (&sY[0][0])[i] = 0.0f;
    __syncthreads();

    // copy lanes (x load / latent write): 8 rows x 16 float4 = 128 threads
    const int cr  = tid >> 4;
    const int cd4 = (tid & 15) * 4;

    // split-2 mapping: tile t16 in 0..127, part2 = lane>>4 (bfly 16)
    const int t16   = wid * 16 + (lane & 15);
    const int part2 = lane >> 4;
    // split-4 mapping: tile t8 in 0..63, part4 = lane>>3 (bfly 8, 16)
    const int t8    = wid * 8 + (lane & 7);
    const int part4 = lane >> 3;

    // K=100 4-way split: [0,28) [28,52) [52,76) [76,100)
    const int k0_100_4 = part4 ? 28 + (part4 - 1) * 24 : 0;
    const int k1_100_4 = 28 + part4 * 24;
    // K=100 2-way split: [0,52) [52,100)
    const int k0_100_2 = part2 * 52;
    const int k1_100_2 = part2 ? 100 : 52;

    for (int step = 0; step < NSTEPS; ++step) {
        const float dt = (step == 0) ? (sts[1] - sts[0]) : (sts[step - 1] - sts[step]);

        if (tid < 128) {
            const float4 v = *reinterpret_cast<const float4*>(
                data + (((size_t)(rowbase + cr)) * TT + (step + 1)) * DD + cd4);
            *reinterpret_cast<float4*>(&sC[cr][64 + cd4]) = v;
        }

        // ---- P1: sH[:,0:100) = tanh(bf1 + Y @ Wf1); K=64, r4c2, Ksplit2 (100 tiles) ----
        {
            const int t = (t16 < 100) ? t16 : 99;
            const int r0 = (t / 50) * 4, n0 = (t % 50) * 2;
            const int k0 = part2 * 32, k1 = k0 + 32;
            u64 acc[4] = {};
            acc_r4c2<100>(Wf1 + n0, &sY[r0][0], &sY[r0+1][0], &sY[r0+2][0], &sY[r0+3][0],
                          k0, k1, acc);
            bfly_add<4>(acc, 16);
            if (part2 == 0 && t16 < 100) {
                const u64 bb = *reinterpret_cast<const u64*>(&sbf1[n0]);
                const float2 bv = unpack2(bb);
#pragma unroll
                for (int rr = 0; rr < 4; ++rr) {
                    const float2 p = unpack2(acc[rr]);
                    float2 o; o.x = tanh_fast(p.x + bv.x); o.y = tanh_fast(p.y + bv.y);
                    *reinterpret_cast<float2*>(&sH[r0+rr][n0]) = o;
                }
            }
        }
        __syncthreads();

        // ---- P2: y_ode = Y + dt*(bf2 + H @ Wf2); K=100, N=64, r4c2, Ksplit4 (64 tiles) ----
        {
            const int r0 = (t8 >> 5) * 4, n0 = (t8 & 31) * 2;
            u64 acc[4] = {};
            acc_r4c2<64>(Wf2 + n0, &sH[r0][0], &sH[r0+1][0], &sH[r0+2][0], &sH[r0+3][0],
                         k0_100_4, k1_100_4, acc);
            bfly_add<4>(acc, 8); bfly_add<4>(acc, 16);
            if (part4 == 0) {
                const float2 bv = unpack2(*reinterpret_cast<const u64*>(&sbf2[n0]));
#pragma unroll
                for (int rr = 0; rr < 4; ++rr) {
                    const float2 p = unpack2(acc[rr]);
                    float2 o;
                    o.x = sY[r0+rr][n0  ] + dt * (p.x + bv.x);
                    o.y = sY[r0+rr][n0+1] + dt * (p.y + bv.y);
                    *reinterpret_cast<float2*>(&sYO[r0+rr][n0]) = o;
                    *reinterpret_cast<float2*>(&sC [r0+rr][n0]) = o;
                }
            }
        }
        __syncthreads();

        // ---- P3: z/r hidden = tanh(b + C @ W1); K=128, 200 cols, r4c4, Ksplit2 (100 tiles) ----
        {
            const int t = (t16 < 100) ? t16 : 99;
            const int r0 = (t / 50) * 4;
            const int n0l = (t % 50) * 4;
            const bool isz = (n0l < 100);
            const int m0 = isz ? n0l : n0l - 100;
            const float* w  = (isz ? Wz1 : Wr1) + m0;
            const float* bb = isz ? sbz1 : sbr1;
            const int k0 = part2 * 64, k1 = k0 + 64;
            u64 acc[8] = {};
            acc_r4c4<100>(w, &sC[r0][0], &sC[r0+1][0], &sC[r0+2][0], &sC[r0+3][0],
                          k0, k1, acc);
            bfly_add<8>(acc, 16);
            if (part2 == 0 && t16 < 100) {
#pragma unroll
                for (int rr = 0; rr < 4; ++rr) {
                    const float2 p0 = unpack2(acc[rr*2]), p1 = unpack2(acc[rr*2+1]);
                    float4 o;
                    o.x = tanh_fast(p0.x + bb[m0  ]);
                    o.y = tanh_fast(p0.y + bb[m0+1]);
                    o.z = tanh_fast(p1.x + bb[m0+2]);
                    o.w = tanh_fast(p1.y + bb[m0+3]);
                    *reinterpret_cast<float4*>(&sH[r0+rr][n0l]) = o;
                }
            }
        }
        __syncthreads();

        // ---- P4: z -> sZ; r -> sC[:,0:64) = y_ode*r; K=100, 128 cols, r4c2, Ksplit2 (128 tiles) ----
        {
            const int r0 = (t16 >> 6) * 4;
            const int n0 = (t16 & 63) * 2;
            const bool isr = (n0 >= 64);
            const int m0 = n0 & 63;
            const float* w = (isr ? Wr2 : Wz2) + m0;
            const int ho = isr ? 100 : 0;
            u64 acc[4] = {};
            acc_r4c2<64>(w, &sH[r0][ho], &sH[r0+1][ho], &sH[r0+2][ho], &sH[r0+3][ho],
                         k0_100_2, k1_100_2, acc);
            bfly_add<4>(acc, 16);
            if (part2 == 0) {
                if (!isr) {
                    const float2 bv = unpack2(*reinterpret_cast<const u64*>(&sbz2[m0]));
#pragma unroll
                    for (int rr = 0; rr < 4; ++rr) {
                        const float2 p = unpack2(acc[rr]);
                        float2 o;
                        o.x = sigmoid_fast(p.x + bv.x);
                        o.y = sigmoid_fast(p.y + bv.y);
                        *reinterpret_cast<float2*>(&sZ[r0+rr][m0]) = o;
                    }
                } else {
                    const float2 bv = unpack2(*reinterpret_cast<const u64*>(&sbr2[m0]));
#pragma unroll
                    for (int rr = 0; rr < 4; ++rr) {
                        const float2 p = unpack2(acc[rr]);
                        float2 o;
                        o.x = sYO[r0+rr][m0  ] * sigmoid_fast(p.x + bv.x);
                        o.y = sYO[r0+rr][m0+1] * sigmoid_fast(p.y + bv.y);
                        *reinterpret_cast<float2*>(&sC[r0+rr][m0]) = o;
                    }
                }
            }
        }
        __syncthreads();

        // ---- P6: sH[:,0:100) = tanh(bh1 + CH @ Wh1); K=128, r4c2, Ksplit2 (100 tiles) ----
        {
            const int t = (t16 < 100) ? t16 : 99;
            const int r0 = (t / 50) * 4, n0 = (t % 50) * 2;
            const int k0 = part2 * 64, k1 = k0 + 64;
            u64 acc[4] = {};
            acc_r4c2<100>(Wh1 + n0, &sC[r0][0], &sC[r0+1][0], &sC[r0+2][0], &sC[r0+3][0],
                          k0, k1, acc);
            bfly_add<4>(acc, 16);
            if (part2 == 0 && t16 < 100) {
                const float2 bv = unpack2(*reinterpret_cast<const u64*>(&sbh1[n0]));
#pragma unroll
                for (int rr = 0; rr < 4; ++rr) {
                    const float2 p = unpack2(acc[rr]);
                    float2 o; o.x = tanh_fast(p.x + bv.x); o.y = tanh_fast(p.y + bv.y);
                    *reinterpret_cast<float2*>(&sH[r0+rr][n0]) = o;
                }
            }
        }
        __syncthreads();

        // ---- P7: h = tanh(bh2 + H @ Wh2); y = (1-z)*h + z*y_ode; K=100, N=64, r4c2, Ksplit4 ----
        {
            const int r0 = (t8 >> 5) * 4, n0 = (t8 & 31) * 2;
            u64 acc[4] = {};
            acc_r4c2<64>(Wh2 + n0, &sH[r0][0], &sH[r0+1][0], &sH[r0+2][0], &sH[r0+3][0],
                         k0_100_4, k1_100_4, acc);
            bfly_add<4>(acc, 8); bfly_add<4>(acc, 16);
            if (part4 == 0) {
                const float2 bv = unpack2(*reinterpret_cast<const u64*>(&sbh2[n0]));
#pragma unroll
                for (int rr = 0; rr < 4; ++rr) {
                    const float2 p = unpack2(acc[rr]);
                    const float h0 = tanh_fast(p.x + bv.x);
                    const float h1 = tanh_fast(p.y + bv.y);
                    const float z0 = sZ[r0+rr][n0  ], z1 = sZ[r0+rr][n0+1];
                    float2 o;
                    o.x = (1.0f - z0) * h0 + z0 * sYO[r0+rr][n0  ];
                    o.y = (1.0f - z1) * h1 + z1 * sYO[r0+rr][n0+1];
                    *reinterpret_cast<float2*>(&sY[r0+rr][n0]) = o;
                }
            }
        }
        __syncthreads();

        if (lat_out && tid < 128) {
            const float4 v = *reinterpret_cast<const float4*>(&sY[cr][cd4]);
            *reinterpret_cast<float4*>(
                lat_out + (((size_t)(rowbase + cr)) * NSTEPS + step) * DD + cd4) = v;
        }
    }

    if (yi_out && tid < 128) {
        const float4 v = *reinterpret_cast<const float4*>(&sY[cr][cd4]);
        *reinterpret_cast<float4*>(yi_out + ((size_t)(rowbase + cr)) * DD + cd4) = v;
    }
}

extern "C" void kernel_launch(void* const* d_in, const int* in_sizes, int n_in,
                              void* d_out, int out_size)
{
    const float* data = (const float*)d_in[0];
    const float* ts   = (const float*)d_in[1];
    const float* Wf1  = (const float*)d_in[2];
    const float* bf1  = (const float*)d_in[3];
    const float* Wf2  = (const float*)d_in[4];
    const float* bf2  = (const float*)d_in[5];
    const float* Wz1  = (const float*)d_in[6];
    const float* bz1  = (const float*)d_in[7];
    const float* Wz2  = (const float*)d_in[8];
    const float* bz2  = (const float*)d_in[9];
    const float* Wr1  = (const float*)d_in[10];
    const float* br1  = (const float*)d_in[11];
    const float* Wr2  = (const float*)d_in[12];
    const float* br2  = (const float*)d_in[13];
    const float* Wh1  = (const float*)d_in[14];
    const float* bh1  = (const float*)d_in[15];
    const float* Wh2  = (const float*)d_in[16];
    const float* bh2  = (const float*)d_in[17];

    const long long latN = 2048LL * 199 * 64;
    const long long yiN  = 2048LL * 64;
    float* out = (float*)d_out;
    float* yi_out = nullptr;
    float* lat_out = nullptr;
    if ((long long)out_size == latN + yiN) { yi_out = out; lat_out = out + yiN; }
    else if ((long long)out_size == latN)  { lat_out = out; }
    else if ((long long)out_size == yiN)   { yi_out = out; }
    else if ((long long)out_size > latN)   { yi_out = out; lat_out = out + yiN; }
    else                                   { lat_out = out; }

    ode_rnn_kernel<<<2048 / R_PER_CTA, 256>>>(
        data, ts, Wf1, bf1, Wf2, bf2, Wz1, bz1, Wz2, bz2,
        Wr1, br1, Wr2, br2, Wh1, bh1, Wh2, bh2, yi_out, lat_out);
}

// round 6
// speedup vs baseline: 1.7934x; 1.7023x over previous
#include <cuda_runtime.h>
#include <cstdint>

// ODE-RNN fused scan, round 6: tensor-core path.
// 128 CTAs x 256 threads (8 warps), 16 rows/CTA, mma.sync m16n8k16 bf16 with
// 3-term hi/lo split (A_hi*B_hi + A_hi*B_lo + A_lo*B_hi) for ~2^-18 accuracy.
// Weights pre-split into fragment order by a prep kernel; hi resident in SMEM,
// lo streamed from L2 with one-chunk prefetch.

typedef unsigned int u32;
typedef unsigned long long u64;

#define NSTEPS 199
#define TT 200

// fragment-array geometry: per matrix [KC][NT][32 lanes][2 regs] of u32(bf16x2)
#define OFF_F1   0        // Wf1 : KC=4, NT=13  (K=64,  N=100)
#define OFF_F2   3328     // Wf2 : KC=7, NT=8   (K=100, N=64)
#define OFF_ZR1  6912     // Wz1|Wr1 combined: KC=8, NT=25 (K=128, N=200)
#define OFF_Z2   19712    // Wz2 : KC=7, NT=8
#define OFF_R2   23296    // Wr2 : KC=7, NT=8
#define OFF_H1   26880    // Wh1 : KC=8, NT=13  (K=128, N=100)
#define OFF_H2   33536    // Wh2 : KC=7, NT=8
#define W_TOTAL  37120    // u32 count (148,480 bytes)

__device__ __align__(16) u32 g_whi[W_TOTAL];
__device__ __align__(16) u32 g_wlo[W_TOTAL];

// ---------------- helpers ----------------

__device__ __forceinline__ u32 bf16_hi_bits(float x) {
    const u32 u = __float_as_uint(x);
    return (u + 0x7fffu + ((u >> 16) & 1u)) >> 16;   // rn to bf16 (no inf/nan inputs)
}

__device__ __forceinline__ float tanh_fast(float x) {
    const float e = __expf(2.0f * x);
    return 1.0f - __fdividef(2.0f, e + 1.0f);
}
__device__ __forceinline__ float sigmoid_fast(float x) {
    return __fdividef(1.0f, 1.0f + __expf(-x));
}

// split float2 -> bf16x2 hi + bf16x2 lo (low half of reg = first element)
__device__ __forceinline__ void bsplit(float2 x, u32& h, u32& l) {
    u32 hh;
    asm("cvt.rn.bf16x2.f32 %0, %1, %2;" : "=r"(hh) : "f"(x.y), "f"(x.x));
    const float r0 = x.x - __uint_as_float(hh << 16);
    const float r1 = x.y - __uint_as_float(hh & 0xffff0000u);
    u32 ll;
    asm("cvt.rn.bf16x2.f32 %0, %1, %2;" : "=r"(ll) : "f"(r1), "f"(r0));
    h = hh; l = ll;
}

__device__ __forceinline__ void mma4(float d[4], const u32 a[4], u32 b0, u32 b1) {
    asm("mma.sync.aligned.m16n8k16.row.col.f32.bf16.bf16.f32 "
        "{%0,%1,%2,%3}, {%4,%5,%6,%7}, {%8,%9}, {%0,%1,%2,%3};"
        : "+f"(d[0]), "+f"(d[1]), "+f"(d[2]), "+f"(d[3])
        : "r"(a[0]), "r"(a[1]), "r"(a[2]), "r"(a[3]), "r"(b0), "r"(b1));
}

// GEMM over this warp's n-tiles: D[i] = A(16 x 16*KC) * B(:, tile nt0+i*NTS)
template<int KC, int NT, int MAXT, int NTS>
__device__ __forceinline__ void run_gemm(
    const float* __restrict__ sA, const int lda,
    const u32* __restrict__ sBhi, const u32* __restrict__ gBlo,
    const int nt0, const int g, const int tg, const int lane,
    float D[MAXT][4])
{
    const float* rA  = sA + g * lda + tg * 2;
    const float* rA8 = rA + 8 * lda;
#pragma unroll
    for (int i = 0; i < MAXT; ++i)
        D[i][0] = D[i][1] = D[i][2] = D[i][3] = 0.0f;

    u64 blo[MAXT];
#pragma unroll
    for (int i = 0; i < MAXT; ++i) {
        blo[i] = 0ull;
        const int nt = nt0 + i * NTS;
        if (nt < NT) blo[i] = *(const u64*)(gBlo + (nt * 32 + lane) * 2);
    }
#pragma unroll 2
    for (int kc = 0; kc < KC; ++kc) {
        u64 blo_n[MAXT];
#pragma unroll
        for (int i = 0; i < MAXT; ++i) blo_n[i] = 0ull;
        if (kc + 1 < KC) {
#pragma unroll
            for (int i = 0; i < MAXT; ++i) {
                const int nt = nt0 + i * NTS;
                if (nt < NT)
                    blo_n[i] = *(const u64*)(gBlo + (((kc + 1) * NT + nt) * 32 + lane) * 2);
            }
        }
        const int kb = kc * 16;
        u32 ah[4], al[4];
        bsplit(*(const float2*)(rA  + kb    ), ah[0], al[0]);
        bsplit(*(const float2*)(rA8 + kb    ), ah[1], al[1]);
        bsplit(*(const float2*)(rA  + kb + 8), ah[2], al[2]);
        bsplit(*(const float2*)(rA8 + kb + 8), ah[3], al[3]);
#pragma unroll
        for (int i = 0; i < MAXT; ++i) {
            const int nt = nt0 + i * NTS;
            if (nt < NT) {
                const u64 bh = *(const u64*)(sBhi + ((kc * NT + nt) * 32 + lane) * 2);
                const u32 bh0 = (u32)bh, bh1 = (u32)(bh >> 32);
                const u32 bl0 = (u32)blo[i], bl1 = (u32)(blo[i] >> 32);
                mma4(D[i], ah, bh0, bh1);
                mma4(D[i], ah, bl0, bl1);
                mma4(D[i], al, bh0, bh1);
            }
        }
#pragma unroll
        for (int i = 0; i < MAXT; ++i) blo[i] = blo_n[i];
    }
}

// ---------------- prep kernel: split weights into fragment order ----------------

__global__ void prep_kernel(
    const float* __restrict__ Wf1, const float* __restrict__ Wf2,
    const float* __restrict__ Wz1, const float* __restrict__ Wz2,
    const float* __restrict__ Wr1, const float* __restrict__ Wr2,
    const float* __restrict__ Wh1, const float* __restrict__ Wh2)
{
    const int i = blockIdx.x * blockDim.x + threadIdx.x;
    if (i >= W_TOTAL) return;

    int off, NT, Kr, Nr, ld;
    const float *S1 = nullptr, *S2 = nullptr;
    if (i < OFF_F2)        { off = OFF_F1;  NT = 13; Kr = 64;  Nr = 100; S1 = Wf1; ld = 100; }
    else if (i < OFF_ZR1)  { off = OFF_F2;  NT = 8;  Kr = 100; Nr = 64;  S1 = Wf2; ld = 64;  }
    else if (i < OFF_Z2)   { off = OFF_ZR1; NT = 25; Kr = 128; Nr = 200; S1 = Wz1; S2 = Wr1; ld = 100; }
    else if (i < OFF_R2)   { off = OFF_Z2;  NT = 8;  Kr = 100; Nr = 64;  S1 = Wz2; ld = 64;  }
    else if (i < OFF_H1)   { off = OFF_R2;  NT = 8;  Kr = 100; Nr = 64;  S1 = Wr2; ld = 64;  }
    else if (i < OFF_H2)   { off = OFF_H1;  NT = 13; Kr = 128; Nr = 100; S1 = Wh1; ld = 100; }
    else                   { off = OFF_H2;  NT = 8;  Kr = 100; Nr = 64;  S1 = Wh2; ld = 64;  }

    const int idx  = i - off;
    const int r    = idx & 1;
    const int lane = (idx >> 1) & 31;
    const int rest = idx >> 6;
    const int nt   = rest % NT;
    const int kc   = rest / NT;
    const int k0   = kc * 16 + (lane & 3) * 2 + (r ? 8 : 0);
    const int n    = nt * 8 + (lane >> 2);

    float x0 = 0.0f, x1 = 0.0f;
    if (n < Nr) {
        const float* S = S1; int nn = n;
        if (S2 && n >= 100) { S = S2; nn = n - 100; }
        if (k0     < Kr) x0 = S[(size_t)k0 * ld + nn];
        if (k0 + 1 < Kr) x1 = S[(size_t)(k0 + 1) * ld + nn];
    }
    const u32 h0 = bf16_hi_bits(x0), h1 = bf16_hi_bits(x1);
    const float r0 = x0 - __uint_as_float(h0 << 16);
    const float r1 = x1 - __uint_as_float(h1 << 16);
    const u32 l0 = bf16_hi_bits(r0), l1 = bf16_hi_bits(r1);
    g_whi[i] = h0 | (h1 << 16);
    g_wlo[i] = l0 | (l1 << 16);
}

// ---------------- main kernel ----------------

__global__ void __launch_bounds__(256, 1) ode_main(
    const float* __restrict__ data, const float* __restrict__ ts,
    const float* __restrict__ bf1, const float* __restrict__ bf2,
    const float* __restrict__ bz1, const float* __restrict__ bz2,
    const float* __restrict__ br1, const float* __restrict__ br2,
    const float* __restrict__ bh1, const float* __restrict__ bh2,
    float* __restrict__ yi_out, float* __restrict__ lat_out)
{
    __shared__ float sY [16][68];
    __shared__ float sYO[16][68];
    __shared__ float sZ [16][68];
    __shared__ float sC [16][132];   // [0:64) y_ode (then y_ode*r), [64:128) x
    __shared__ float sHA[16][116];   // f-hidden (P1->P2) and h-hidden (P6->P7)
    __shared__ float sHz[16][116];
    __shared__ float sHr[16][116];
    __shared__ float sbf1[100], sbz1[100], sbr1[100], sbh1[100];
    __shared__ float sbf2[64],  sbz2[64],  sbr2[64],  sbh2[64];
    __shared__ float sts_s[TT];
    extern __shared__ __align__(16) u32 dynW[];   // hi weights, fragment order

    const int tid  = threadIdx.x;
    const int lane = tid & 31;
    const int w    = tid >> 5;
    const int g    = lane >> 2;      // 0..7
    const int tg   = lane & 3;       // 0..3
    const int rowbase = blockIdx.x * 16;

    // zero activation arrays with zero-padding requirements + sY
    for (int i = tid; i < 16 * 68;  i += 256) (&sY[0][0])[i]  = 0.0f;
    for (int i = tid; i < 16 * 116; i += 256) (&sHA[0][0])[i] = 0.0f;
    for (int i = tid; i < 16 * 116; i += 256) (&sHz[0][0])[i] = 0.0f;
    for (int i = tid; i < 16 * 116; i += 256) (&sHr[0][0])[i] = 0.0f;
    for (int i = tid; i < 100; i += 256) {
        sbf1[i] = bf1[i]; sbz1[i] = bz1[i]; sbr1[i] = br1[i]; sbh1[i] = bh1[i];
    }
    for (int i = tid; i < 64; i += 256) {
        sbf2[i] = bf2[i]; sbz2[i] = bz2[i]; sbr2[i] = br2[i]; sbh2[i] = bh2[i];
    }
    for (int i = tid; i < TT; i += 256) sts_s[i] = ts[i];
    // hi weights -> SMEM
    {
        const float4* s = (const float4*)g_whi;
        float4* d = (float4*)dynW;
        for (int i = tid; i < W_TOTAL / 4; i += 256) d[i] = s[i];
    }
    __syncthreads();

    const int cr  = tid >> 4;         // 0..15
    const int cd4 = (tid & 15) * 4;   // 0..60

    for (int step = 0; step < NSTEPS; ++step) {
        const float dt = (step == 0) ? (sts_s[1] - sts_s[0])
                                     : (sts_s[step - 1] - sts_s[step]);

        // x(t=step+1) -> sC[:,64:128)
        {
            const float4 v = *reinterpret_cast<const float4*>(
                data + (((size_t)(rowbase + cr)) * TT + (step + 1)) * 64 + cd4);
            *reinterpret_cast<float4*>(&sC[cr][64 + cd4]) = v;
        }

        // ---- P1: sHA = tanh(bf1 + Y @ Wf1)  [K=64, N=100] ----
        {
            float D[2][4];
            run_gemm<4, 13, 2, 8>(&sY[0][0], 68, dynW + OFF_F1, g_wlo + OFF_F1,
                                  w, g, tg, lane, D);
#pragma unroll
            for (int i = 0; i < 2; ++i) {
                const int nt = w + i * 8;
                if (nt < 13) {
                    const int c0 = nt * 8 + tg * 2;
                    if (c0 < 100) {
                        const float b0 = sbf1[c0], b1 = sbf1[c0 + 1];
                        float2 v0, v1;
                        v0.x = tanh_fast(D[i][0] + b0); v0.y = tanh_fast(D[i][1] + b1);
                        v1.x = tanh_fast(D[i][2] + b0); v1.y = tanh_fast(D[i][3] + b1);
                        *(float2*)&sHA[g][c0]     = v0;
                        *(float2*)&sHA[g + 8][c0] = v1;
                    }
                }
            }
        }
        __syncthreads();

        // ---- P2: y_ode = Y + dt*(bf2 + HA @ Wf2)  [K=100, N=64] ----
        {
            float D[1][4];
            run_gemm<7, 8, 1, 8>(&sHA[0][0], 116, dynW + OFF_F2, g_wlo + OFF_F2,
                                 w, g, tg, lane, D);
            const int c0 = w * 8 + tg * 2;
            const float b0 = sbf2[c0], b1 = sbf2[c0 + 1];
            float2 v0, v1;
            v0.x = sY[g][c0]     + dt * (D[0][0] + b0);
            v0.y = sY[g][c0 + 1] + dt * (D[0][1] + b1);
            v1.x = sY[g + 8][c0]     + dt * (D[0][2] + b0);
            v1.y = sY[g + 8][c0 + 1] + dt * (D[0][3] + b1);
            *(float2*)&sYO[g][c0] = v0;     *(float2*)&sC[g][c0] = v0;
            *(float2*)&sYO[g + 8][c0] = v1; *(float2*)&sC[g + 8][c0] = v1;
        }
        __syncthreads();

        // ---- P3: z/r hidden = tanh(b + C @ [Wz1|Wr1])  [K=128, N=200] ----
        {
            float D[4][4];
            run_gemm<8, 25, 4, 8>(&sC[0][0], 132, dynW + OFF_ZR1, g_wlo + OFF_ZR1,
                                  w, g, tg, lane, D);
#pragma unroll
            for (int i = 0; i < 4; ++i) {
                const int nt = w + i * 8;
                if (nt < 25) {
                    const int c0 = nt * 8 + tg * 2;
                    if (c0 < 100) {
                        const float b0 = sbz1[c0], b1 = sbz1[c0 + 1];
                        float2 v0, v1;
                        v0.x = tanh_fast(D[i][0] + b0); v0.y = tanh_fast(D[i][1] + b1);
                        v1.x = tanh_fast(D[i][2] + b0); v1.y = tanh_fast(D[i][3] + b1);
                        *(float2*)&sHz[g][c0]     = v0;
                        *(float2*)&sHz[g + 8][c0] = v1;
                    } else {
                        const int c = c0 - 100;
                        const float b0 = sbr1[c], b1 = sbr1[c + 1];
                        float2 v0, v1;
                        v0.x = tanh_fast(D[i][0] + b0); v0.y = tanh_fast(D[i][1] + b1);
                        v1.x = tanh_fast(D[i][2] + b0); v1.y = tanh_fast(D[i][3] + b1);
                        *(float2*)&sHr[g][c]     = v0;
                        *(float2*)&sHr[g + 8][c] = v1;
                    }
                }
            }
        }
        __syncthreads();

        // ---- P4: z = sig(bz2 + Hz @ Wz2) -> sZ ; r: sC[:,0:64) = yO * sig(br2 + Hr @ Wr2) ----
        {
            const bool isz = (w < 4);
            const float* Ab = isz ? &sHz[0][0] : &sHr[0][0];
            const u32* bh = dynW  + (isz ? OFF_Z2 : OFF_R2);
            const u32* bl = g_wlo + (isz ? OFF_Z2 : OFF_R2);
            const int nt0 = (w & 3) * 2;
            float D[2][4];
            run_gemm<7, 8, 2, 1>(Ab, 116, bh, bl, nt0, g, tg, lane, D);
#pragma unroll
            for (int i = 0; i < 2; ++i) {
                const int c0 = (nt0 + i) * 8 + tg * 2;
                if (isz) {
                    const float b0 = sbz2[c0], b1 = sbz2[c0 + 1];
                    float2 v0, v1;
                    v0.x = sigmoid_fast(D[i][0] + b0); v0.y = sigmoid_fast(D[i][1] + b1);
                    v1.x = sigmoid_fast(D[i][2] + b0); v1.y = sigmoid_fast(D[i][3] + b1);
                    *(float2*)&sZ[g][c0]     = v0;
                    *(float2*)&sZ[g + 8][c0] = v1;
                } else {
                    const float b0 = sbr2[c0], b1 = sbr2[c0 + 1];
                    float2 v0, v1;
                    v0.x = sYO[g][c0]     * sigmoid_fast(D[i][0] + b0);
                    v0.y = sYO[g][c0 + 1] * sigmoid_fast(D[i][1] + b1);
                    v1.x = sYO[g + 8][c0]     * sigmoid_fast(D[i][2] + b0);
                    v1.y = sYO[g + 8][c0 + 1] * sigmoid_fast(D[i][3] + b1);
                    *(float2*)&sC[g][c0]     = v0;
                    *(float2*)&sC[g + 8][c0] = v1;
                }
            }
        }
        __syncthreads();

        // ---- P6: sHA = tanh(bh1 + C @ Wh1)  [K=128, N=100] ----
        {
            float D[2][4];
            run_gemm<8, 13, 2, 8>(&sC[0][0], 132, dynW + OFF_H1, g_wlo + OFF_H1,
                                  w, g, tg, lane, D);
#pragma unroll
            for (int i = 0; i < 2; ++i) {
                const int nt = w + i * 8;
                if (nt < 13) {
                    const int c0 = nt * 8 + tg * 2;
                    if (c0 < 100) {
                        const float b0 = sbh1[c0], b1 = sbh1[c0 + 1];
                        float2 v0, v1;
                        v0.x = tanh_fast(D[i][0] + b0); v0.y = tanh_fast(D[i][1] + b1);
                        v1.x = tanh_fast(D[i][2] + b0); v1.y = tanh_fast(D[i][3] + b1);
                        *(float2*)&sHA[g][c0]     = v0;
                        *(float2*)&sHA[g + 8][c0] = v1;
                    }
                }
            }
        }
        __syncthreads();

        // ---- P7: h = tanh(bh2 + HA @ Wh2); y = (1-z)h + z*yO ----
        {
            float D[1][4];
            run_gemm<7, 8, 1, 8>(&sHA[0][0], 116, dynW + OFF_H2, g_wlo + OFF_H2,
                                 w, g, tg, lane, D);
            const int c0 = w * 8 + tg * 2;
            const float b0 = sbh2[c0], b1 = sbh2[c0 + 1];
            {
                const float h0 = tanh_fast(D[0][0] + b0);
                const float h1 = tanh_fast(D[0][1] + b1);
                const float z0 = sZ[g][c0], z1 = sZ[g][c0 + 1];
                float2 v;
                v.x = (1.0f - z0) * h0 + z0 * sYO[g][c0];
                v.y = (1.0f - z1) * h1 + z1 * sYO[g][c0 + 1];
                *(float2*)&sY[g][c0] = v;
            }
            {
                const float h0 = tanh_fast(D[0][2] + b0);
                const float h1 = tanh_fast(D[0][3] + b1);
                const float z0 = sZ[g + 8][c0], z1 = sZ[g + 8][c0 + 1];
                float2 v;
                v.x = (1.0f - z0) * h0 + z0 * sYO[g + 8][c0];
                v.y = (1.0f - z1) * h1 + z1 * sYO[g + 8][c0 + 1];
                *(float2*)&sY[g + 8][c0] = v;
            }
        }
        __syncthreads();

        if (lat_out) {
            const float4 v = *reinterpret_cast<const float4*>(&sY[cr][cd4]);
            *reinterpret_cast<float4*>(
                lat_out + (((size_t)(rowbase + cr)) * NSTEPS + step) * 64 + cd4) = v;
        }
    }

    if (yi_out) {
        const float4 v = *reinterpret_cast<const float4*>(&sY[cr][cd4]);
        *reinterpret_cast<float4*>(yi_out + ((size_t)(rowbase + cr)) * 64 + cd4) = v;
    }
}

extern "C" void kernel_launch(void* const* d_in, const int* in_sizes, int n_in,
                              void* d_out, int out_size)
{
    const float* data = (const float*)d_in[0];
    const float* ts   = (const float*)d_in[1];
    const float* Wf1  = (const float*)d_in[2];
    const float* bf1  = (const float*)d_in[3];
    const float* Wf2  = (const float*)d_in[4];
    const float* bf2  = (const float*)d_in[5];
    const float* Wz1  = (const float*)d_in[6];
    const float* bz1  = (const float*)d_in[7];
    const float* Wz2  = (const float*)d_in[8];
    const float* bz2  = (const float*)d_in[9];
    const float* Wr1  = (const float*)d_in[10];
    const float* br1  = (const float*)d_in[11];
    const float* Wr2  = (const float*)d_in[12];
    const float* br2  = (const float*)d_in[13];
    const float* Wh1  = (const float*)d_in[14];
    const float* bh1  = (const float*)d_in[15];
    const float* Wh2  = (const float*)d_in[16];
    const float* bh2  = (const float*)d_in[17];

    const long long latN = 2048LL * 199 * 64;
    const long long yiN  = 2048LL * 64;
    float* out = (float*)d_out;
    float* yi_out = nullptr;
    float* lat_out = nullptr;
    if ((long long)out_size == latN + yiN) { yi_out = out; lat_out = out + yiN; }
    else if ((long long)out_size == latN)  { lat_out = out; }
    else if ((long long)out_size == yiN)   { yi_out = out; }
    else if ((long long)out_size > latN)   { yi_out = out; lat_out = out + yiN; }
    else                                   { lat_out = out; }

    cudaFuncSetAttribute(ode_main, cudaFuncAttributeMaxDynamicSharedMemorySize,
                         W_TOTAL * 4);

    prep_kernel<<<(W_TOTAL + 255) / 256, 256>>>(Wf1, Wf2, Wz1, Wz2, Wr1, Wr2, Wh1, Wh2);
    ode_main<<<128, 256, W_TOTAL * 4>>>(data, ts, bf1, bf2, bz1, bz2, br1, br2,
                                        bh1, bh2, yi_out, lat_out);
}

// round 10
// speedup vs baseline: 2.0646x; 1.1512x over previous
#include <cuda_runtime.h>
#include <cstdint>

// ODE-RNN fused scan, round 8 (= R7 + x-loader fix: all 256 threads load x).
// Tensor-core path with single-conversion activations: epilogues split
// fp32 -> bf16 hi/lo packed u32 SMEM arrays; MMA A-operands via ldmatrix.x4.
// Weights: hi resident in SMEM (fragment order), lo streamed from L2.

typedef unsigned int u32;
typedef unsigned long long u64;

#define NSTEPS 199
#define TT 200

// fragment-array geometry: per matrix [KC][NT][32 lanes][2 regs] of u32(bf16x2)
#define OFF_F1   0        // Wf1 : KC=4, NT=13
#define OFF_F2   3328     // Wf2 : KC=7, NT=8
#define OFF_ZR1  6912     // Wz1|Wr1 : KC=8, NT=25
#define OFF_Z2   19712    // Wz2 : KC=7, NT=8
#define OFF_R2   23296    // Wr2 : KC=7, NT=8
#define OFF_H1   26880    // Wh1 : KC=8, NT=13
#define OFF_H2   33536    // Wh2 : KC=7, NT=8
#define W_TOTAL  37120    // u32 (148,480 B)

// packed bf16x2 activation arrays (u32 units), strides 4*odd (conflict-free +
// 16B-aligned rows for ldmatrix)
#define SY_U32   36       // K=64 array (aY)
#define SC_U32   68       // K=128 array (aC)
#define SH_U32   60       // K=100 arrays (aHA/aHz/aHr), data padded to 56 u32
#define AY_SZ    (16*SY_U32)   // 576
#define AC_SZ    (16*SC_U32)   // 1088
#define AH_SZ    (16*SH_U32)   // 960
#define ACT_U32  (2*(AY_SZ + AC_SZ + 3*AH_SZ))   // 9088
// byte offsets inside activation region
#define B_AYH  0
#define B_AYL  2304
#define B_ACH  4608
#define B_ACL  8960
#define B_AHAH 13312
#define B_AHAL 17152
#define B_AHZH 20992
#define B_AHZL 24832
#define B_AHRH 28672
#define B_AHRL 32512

#define DYN_U32 (W_TOTAL + ACT_U32)

__device__ __align__(16) u32 g_whi[W_TOTAL];
__device__ __align__(16) u32 g_wlo[W_TOTAL];

// ---------------- helpers ----------------

__device__ __forceinline__ u32 bf16_hi_bits(float x) {
    const u32 u = __float_as_uint(x);
    return (u + 0x7fffu + ((u >> 16) & 1u)) >> 16;
}
__device__ __forceinline__ float tanh_fast(float x) {
    const float e = __expf(2.0f * x);
    return 1.0f - __fdividef(2.0f, e + 1.0f);
}
__device__ __forceinline__ float sigmoid_fast(float x) {
    return __fdividef(1.0f, 1.0f + __expf(-x));
}
// split float2 -> bf16x2 hi + lo (low half = first element)
__device__ __forceinline__ void bsplit(float2 x, u32& h, u32& l) {
    u32 hh;
    asm("cvt.rn.bf16x2.f32 %0, %1, %2;" : "=r"(hh) : "f"(x.y), "f"(x.x));
    const float r0 = x.x - __uint_as_float(hh << 16);
    const float r1 = x.y - __uint_as_float(hh & 0xffff0000u);
    u32 ll;
    asm("cvt.rn.bf16x2.f32 %0, %1, %2;" : "=r"(ll) : "f"(r1), "f"(r0));
    h = hh; l = ll;
}
__device__ __forceinline__ void store_split(u32* hp, u32* lp, int idx, float2 v) {
    u32 h, l; bsplit(v, h, l); hp[idx] = h; lp[idx] = l;
}
__device__ __forceinline__ void mma4(float d[4], const u32 a[4], u32 b0, u32 b1) {
    asm("mma.sync.aligned.m16n8k16.row.col.f32.bf16.bf16.f32 "
        "{%0,%1,%2,%3}, {%4,%5,%6,%7}, {%8,%9}, {%0,%1,%2,%3};"
        : "+f"(d[0]), "+f"(d[1]), "+f"(d[2]), "+f"(d[3])
        : "r"(a[0]), "r"(a[1]), "r"(a[2]), "r"(a[3]), "r"(b0), "r"(b1));
}
__device__ __forceinline__ void ldm4(u32 r[4], u32 addr) {
    asm volatile("ldmatrix.sync.aligned.m8n8.x4.shared.b16 {%0,%1,%2,%3}, [%4];"
        : "=r"(r[0]), "=r"(r[1]), "=r"(r[2]), "=r"(r[3]) : "r"(addr));
}
__device__ __forceinline__ u32 smem_u32(const void* p) {
    return (u32)__cvta_generic_to_shared(p);
}
// lane's ldmatrix row-pointer offset (bytes) for an A tile with row stride strideB
__device__ __forceinline__ int amat_off(int lane, int strideB) {
    const int r = lane & 7, m = lane >> 3;
    return (r + ((m & 1) << 3)) * strideB + ((m >> 1) << 4);
}

// GEMM: A fragments from ldmatrix (hi/lo smem addrs), B hi from SMEM, B lo from L2.
template<int KC, int NT, int MAXT, int NTS>
__device__ __forceinline__ void run_gemm_tc(
    const u32 aHi, const u32 aLo,
    const u32* __restrict__ sBhi, const u32* __restrict__ gBlo,
    const int nt0, const int lane, float D[MAXT][4])
{
#pragma unroll
    for (int i = 0; i < MAXT; ++i)
        D[i][0] = D[i][1] = D[i][2] = D[i][3] = 0.0f;

    u64 blo[MAXT];
#pragma unroll
    for (int i = 0; i < MAXT; ++i) {
        blo[i] = 0ull;
        const int nt = nt0 + i * NTS;
        if (nt < NT) blo[i] = *(const u64*)(gBlo + (nt * 32 + lane) * 2);
    }
#pragma unroll 2
    for (int kc = 0; kc < KC; ++kc) {
        u64 blo_n[MAXT];
#pragma unroll
        for (int i = 0; i < MAXT; ++i) blo_n[i] = 0ull;
        if (kc + 1 < KC) {
#pragma unroll
            for (int i = 0; i < MAXT; ++i) {
                const int nt = nt0 + i * NTS;
                if (nt < NT)
                    blo_n[i] = *(const u64*)(gBlo + (((kc + 1) * NT + nt) * 32 + lane) * 2);
            }
        }
        u32 ah[4], al[4];
        ldm4(ah, aHi + kc * 32);
        ldm4(al, aLo + kc * 32);
#pragma unroll
        for (int i = 0; i < MAXT; ++i) {
            const int nt = nt0 + i * NTS;
            if (nt < NT) {
                const u64 bh = *(const u64*)(sBhi + ((kc * NT + nt) * 32 + lane) * 2);
                const u32 bh0 = (u32)bh, bh1 = (u32)(bh >> 32);
                mma4(D[i], ah, bh0, bh1);
                mma4(D[i], ah, (u32)blo[i], (u32)(blo[i] >> 32));
                mma4(D[i], al, bh0, bh1);
            }
            blo[i] = blo_n[i];
        }
    }
}

// ---------------- prep kernel ----------------

__global__ void prep_kernel(
    const float* __restrict__ Wf1, const float* __restrict__ Wf2,
    const float* __restrict__ Wz1, const float* __restrict__ Wz2,
    const float* __restrict__ Wr1, const float* __restrict__ Wr2,
    const float* __restrict__ Wh1, const float* __restrict__ Wh2)
{
    const int i = blockIdx.x * blockDim.x + threadIdx.x;
    if (i >= W_TOTAL) return;

    int off, NT, Kr, Nr, ld;
    const float *S1 = nullptr, *S2 = nullptr;
    if (i < OFF_F2)        { off = OFF_F1;  NT = 13; Kr = 64;  Nr = 100; S1 = Wf1; ld = 100; }
    else if (i < OFF_ZR1)  { off = OFF_F2;  NT = 8;  Kr = 100; Nr = 64;  S1 = Wf2; ld = 64;  }
    else if (i < OFF_Z2)   { off = OFF_ZR1; NT = 25; Kr = 128; Nr = 200; S1 = Wz1; S2 = Wr1; ld = 100; }
    else if (i < OFF_R2)   { off = OFF_Z2;  NT = 8;  Kr = 100; Nr = 64;  S1 = Wz2; ld = 64;  }
    else if (i < OFF_H1)   { off = OFF_R2;  NT = 8;  Kr = 100; Nr = 64;  S1 = Wr2; ld = 64;  }
    else if (i < OFF_H2)   { off = OFF_H1;  NT = 13; Kr = 128; Nr = 100; S1 = Wh1; ld = 100; }
    else                   { off = OFF_H2;  NT = 8;  Kr = 100; Nr = 64;  S1 = Wh2; ld = 64;  }

    const int idx  = i - off;
    const int r    = idx & 1;
    const int lane = (idx >> 1) & 31;
    const int rest = idx >> 6;
    const int nt   = rest % NT;
    const int kc   = rest / NT;
    const int k0   = kc * 16 + (lane & 3) * 2 + (r ? 8 : 0);
    const int n    = nt * 8 + (lane >> 2);

    float x0 = 0.0f, x1 = 0.0f;
    if (n < Nr) {
        const float* S = S1; int nn = n;
        if (S2 && n >= 100) { S = S2; nn = n - 100; }
        if (k0     < Kr) x0 = S[(size_t)k0 * ld + nn];
        if (k0 + 1 < Kr) x1 = S[(size_t)(k0 + 1) * ld + nn];
    }
    const u32 h0 = bf16_hi_bits(x0), h1 = bf16_hi_bits(x1);
    const float r0 = x0 - __uint_as_float(h0 << 16);
    const float r1 = x1 - __uint_as_float(h1 << 16);
    const u32 l0 = bf16_hi_bits(r0), l1 = bf16_hi_bits(r1);
    g_whi[i] = h0 | (h1 << 16);
    g_wlo[i] = l0 | (l1 << 16);
}

// ---------------- main kernel ----------------

__global__ void __launch_bounds__(256, 1) ode_main(
    const float* __restrict__ data, const float* __restrict__ ts,
    const float* __restrict__ bf1, const float* __restrict__ bf2,
    const float* __restrict__ bz1, const float* __restrict__ bz2,
    const float* __restrict__ br1, const float* __restrict__ br2,
    const float* __restrict__ bh1, const float* __restrict__ bh2,
    float* __restrict__ yi_out, float* __restrict__ lat_out)
{
    __shared__ float sY [16][68];
    __shared__ float sYO[16][68];
    __shared__ float sZ [16][68];
    __shared__ float sbf1[100], sbz1[100], sbr1[100], sbh1[100];
    __shared__ float sbf2[64],  sbz2[64],  sbr2[64],  sbh2[64];
    __shared__ float sts_s[TT];
    extern __shared__ __align__(16) u32 dynW[];   // [hi weights | act arrays]

    const int tid  = threadIdx.x;
    const int lane = tid & 31;
    const int w    = tid >> 5;
    const int g    = lane >> 2;      // 0..7
    const int tg   = lane & 3;       // 0..3
    const int rowbase = blockIdx.x * 16;

    u32* const actW = dynW + W_TOTAL;
    u32* const aYh  = actW;
    u32* const aYl  = actW + (B_AYL  >> 2);
    u32* const aCh  = actW + (B_ACH  >> 2);
    u32* const aCl  = actW + (B_ACL  >> 2);
    u32* const aHAh = actW + (B_AHAH >> 2);
    u32* const aHAl = actW + (B_AHAL >> 2);
    u32* const aHzh = actW + (B_AHZH >> 2);
    u32* const aHzl = actW + (B_AHZL >> 2);
    u32* const aHrh = actW + (B_AHRH >> 2);
    u32* const aHrl = actW + (B_AHRL >> 2);

    // init
    for (int i = tid; i < 16 * 68; i += 256) (&sY[0][0])[i] = 0.0f;
    for (int i = tid; i < ACT_U32; i += 256) actW[i] = 0u;
    for (int i = tid; i < 100; i += 256) {
        sbf1[i] = bf1[i]; sbz1[i] = bz1[i]; sbr1[i] = br1[i]; sbh1[i] = bh1[i];
    }
    for (int i = tid; i < 64; i += 256) {
        sbf2[i] = bf2[i]; sbz2[i] = bz2[i]; sbr2[i] = br2[i]; sbh2[i] = bh2[i];
    }
    for (int i = tid; i < TT; i += 256) sts_s[i] = ts[i];
    {
        const float4* s = (const float4*)g_whi;
        float4* d = (float4*)dynW;
        for (int i = tid; i < W_TOTAL / 4; i += 256) d[i] = s[i];
    }
    __syncthreads();

    // ldmatrix lane addresses (byte, shared space)
    const u32 base_act = smem_u32(actW);
    const int offY = amat_off(lane, SY_U32 * 4);
    const int offC = amat_off(lane, SC_U32 * 4);
    const int offH = amat_off(lane, SH_U32 * 4);
    const u32 adYh  = base_act + B_AYH  + offY, adYl  = base_act + B_AYL  + offY;
    const u32 adCh  = base_act + B_ACH  + offC, adCl  = base_act + B_ACL  + offC;
    const u32 adHAh = base_act + B_AHAH + offH, adHAl = base_act + B_AHAL + offH;
    const u32 adHzh = base_act + B_AHZH + offH, adHzl = base_act + B_AHZL + offH;
    const u32 adHrh = base_act + B_AHRH + offH, adHrl = base_act + B_AHRL + offH;

    const int cr  = tid >> 4;         // 0..15 (all 256 threads!)
    const int cd4 = (tid & 15) * 4;   // 0..60

    for (int step = 0; step < NSTEPS; ++step) {
        const float dt = (step == 0) ? (sts_s[1] - sts_s[0])
                                     : (sts_s[step - 1] - sts_s[step]);

        // x(t=step+1): split to bf16 hi/lo into aC cols [64:128) — ALL 16 rows
        {
            const float4 v = *reinterpret_cast<const float4*>(
                data + (((size_t)(rowbase + cr)) * TT + (step + 1)) * 64 + cd4);
            const int ci = cr * SC_U32 + 32 + (cd4 >> 1);
            store_split(aCh, aCl, ci,     make_float2(v.x, v.y));
            store_split(aCh, aCl, ci + 1, make_float2(v.z, v.w));
        }

        // ---- P1: HA = tanh(bf1 + Y @ Wf1)  [K=64, N=100] ----
        {
            float D[2][4];
            run_gemm_tc<4, 13, 2, 8>(adYh, adYl, dynW + OFF_F1, g_wlo + OFF_F1,
                                     w, lane, D);
#pragma unroll
            for (int i = 0; i < 2; ++i) {
                const int nt = w + i * 8;
                if (nt < 13) {
                    const int c0 = nt * 8 + tg * 2;
                    if (c0 < 100) {
                        const float b0 = sbf1[c0], b1 = sbf1[c0 + 1];
                        const int ci = (c0 >> 1);
                        store_split(aHAh, aHAl, g * SH_U32 + ci,
                            make_float2(tanh_fast(D[i][0] + b0), tanh_fast(D[i][1] + b1)));
                        store_split(aHAh, aHAl, (g + 8) * SH_U32 + ci,
                            make_float2(tanh_fast(D[i][2] + b0), tanh_fast(D[i][3] + b1)));
                    }
                }
            }
        }
        __syncthreads();

        // ---- P2: y_ode = Y + dt*(bf2 + HA @ Wf2)  [K=100, N=64] ----
        {
            float D[1][4];
            run_gemm_tc<7, 8, 1, 8>(adHAh, adHAl, dynW + OFF_F2, g_wlo + OFF_F2,
                                    w, lane, D);
            const int c0 = w * 8 + tg * 2;
            const float b0 = sbf2[c0], b1 = sbf2[c0 + 1];
            float2 v0, v1;
            v0.x = sY[g][c0]     + dt * (D[0][0] + b0);
            v0.y = sY[g][c0 + 1] + dt * (D[0][1] + b1);
            v1.x = sY[g + 8][c0]     + dt * (D[0][2] + b0);
            v1.y = sY[g + 8][c0 + 1] + dt * (D[0][3] + b1);
            *(float2*)&sYO[g][c0]     = v0;
            *(float2*)&sYO[g + 8][c0] = v1;
            store_split(aCh, aCl, g * SC_U32 + (c0 >> 1), v0);
            store_split(aCh, aCl, (g + 8) * SC_U32 + (c0 >> 1), v1);
        }
        __syncthreads();

        // ---- P3: z/r hidden = tanh(b + C @ [Wz1|Wr1])  [K=128, N=200] ----
        {
            float D[4][4];
            run_gemm_tc<8, 25, 4, 8>(adCh, adCl, dynW + OFF_ZR1, g_wlo + OFF_ZR1,
                                     w, lane, D);
#pragma unroll
            for (int i = 0; i < 4; ++i) {
                const int nt = w + i * 8;
                if (nt < 25) {
                    const int c0 = nt * 8 + tg * 2;
                    if (c0 < 100) {
                        const float b0 = sbz1[c0], b1 = sbz1[c0 + 1];
                        const int ci = c0 >> 1;
                        store_split(aHzh, aHzl, g * SH_U32 + ci,
                            make_float2(tanh_fast(D[i][0] + b0), tanh_fast(D[i][1] + b1)));
                        store_split(aHzh, aHzl, (g + 8) * SH_U32 + ci,
                            make_float2(tanh_fast(D[i][2] + b0), tanh_fast(D[i][3] + b1)));
                    } else {
                        const int c = c0 - 100;
                        const float b0 = sbr1[c], b1 = sbr1[c + 1];
                        const int ci = c >> 1;
                        store_split(aHrh, aHrl, g * SH_U32 + ci,
                            make_float2(tanh_fast(D[i][0] + b0), tanh_fast(D[i][1] + b1)));
                        store_split(aHrh, aHrl, (g + 8) * SH_U32 + ci,
                            make_float2(tanh_fast(D[i][2] + b0), tanh_fast(D[i][3] + b1)));
                    }
                }
            }
        }
        __syncthreads();

        // ---- P4: z = sig(bz2 + Hz@Wz2) -> sZ ; r: aC[:,0:64) = yO * sig(br2 + Hr@Wr2) ----
        {
            const bool isz = (w < 4);
            const u32 aH = isz ? adHzh : adHrh;
            const u32 aL = isz ? adHzl : adHrl;
            const u32* bh = dynW  + (isz ? OFF_Z2 : OFF_R2);
            const u32* bl = g_wlo + (isz ? OFF_Z2 : OFF_R2);
            const int nt0 = (w & 3) * 2;
            float D[2][4];
            run_gemm_tc<7, 8, 2, 1>(aH, aL, bh, bl, nt0, lane, D);
#pragma unroll
            for (int i = 0; i < 2; ++i) {
                const int c0 = (nt0 + i) * 8 + tg * 2;
                if (isz) {
                    const float b0 = sbz2[c0], b1 = sbz2[c0 + 1];
                    float2 v0, v1;
                    v0.x = sigmoid_fast(D[i][0] + b0); v0.y = sigmoid_fast(D[i][1] + b1);
                    v1.x = sigmoid_fast(D[i][2] + b0); v1.y = sigmoid_fast(D[i][3] + b1);
                    *(float2*)&sZ[g][c0]     = v0;
                    *(float2*)&sZ[g + 8][c0] = v1;
                } else {
                    const float b0 = sbr2[c0], b1 = sbr2[c0 + 1];
                    float2 v0, v1;
                    v0.x = sYO[g][c0]     * sigmoid_fast(D[i][0] + b0);
                    v0.y = sYO[g][c0 + 1] * sigmoid_fast(D[i][1] + b1);
                    v1.x = sYO[g + 8][c0]     * sigmoid_fast(D[i][2] + b0);
                    v1.y = sYO[g + 8][c0 + 1] * sigmoid_fast(D[i][3] + b1);
                    store_split(aCh, aCl, g * SC_U32 + (c0 >> 1), v0);
                    store_split(aCh, aCl, (g + 8) * SC_U32 + (c0 >> 1), v1);
                }
            }
        }
        __syncthreads();

        // ---- P6: HA = tanh(bh1 + C @ Wh1)  [K=128, N=100] ----
        {
            float D[2][4];
            run_gemm_tc<8, 13, 2, 8>(adCh, adCl, dynW + OFF_H1, g_wlo + OFF_H1,
                                     w, lane, D);
#pragma unroll
            for (int i = 0; i < 2; ++i) {
                const int nt = w + i * 8;
                if (nt < 13) {
                    const int c0 = nt * 8 + tg * 2;
                    if (c0 < 100) {
                        const float b0 = sbh1[c0], b1 = sbh1[c0 + 1];
                        const int ci = c0 >> 1;
                        store_split(aHAh, aHAl, g * SH_U32 + ci,
                            make_float2(tanh_fast(D[i][0] + b0), tanh_fast(D[i][1] + b1)));
                        store_split(aHAh, aHAl, (g + 8) * SH_U32 + ci,
                            make_float2(tanh_fast(D[i][2] + b0), tanh_fast(D[i][3] + b1)));
                    }
                }
            }
        }
        __syncthreads();

        // ---- P7: h = tanh(bh2 + HA @ Wh2); y = (1-z)h + z*yO ----
        {
            float D[1][4];
            run_gemm_tc<7, 8, 1, 8>(adHAh, adHAl, dynW + OFF_H2, g_wlo + OFF_H2,
                                    w, lane, D);
            const int c0 = w * 8 + tg * 2;
            const float b0 = sbh2[c0], b1 = sbh2[c0 + 1];
            {
                const float h0 = tanh_fast(D[0][0] + b0);
                const float h1 = tanh_fast(D[0][1] + b1);
                const float z0 = sZ[g][c0], z1 = sZ[g][c0 + 1];
                float2 v;
                v.x = (1.0f - z0) * h0 + z0 * sYO[g][c0];
                v.y = (1.0f - z1) * h1 + z1 * sYO[g][c0 + 1];
                *(float2*)&sY[g][c0] = v;
                store_split(aYh, aYl, g * SY_U32 + (c0 >> 1), v);
            }
            {
                const float h0 = tanh_fast(D[0][2] + b0);
                const float h1 = tanh_fast(D[0][3] + b1);
                const float z0 = sZ[g + 8][c0], z1 = sZ[g + 8][c0 + 1];
                float2 v;
                v.x = (1.0f - z0) * h0 + z0 * sYO[g + 8][c0];
                v.y = (1.0f - z1) * h1 + z1 * sYO[g + 8][c0 + 1];
                *(float2*)&sY[g + 8][c0] = v;
                store_split(aYh, aYl, (g + 8) * SY_U32 + (c0 >> 1), v);
            }
        }
        __syncthreads();

        if (lat_out) {
            const float4 v = *reinterpret_cast<const float4*>(&sY[cr][cd4]);
            *reinterpret_cast<float4*>(
                lat_out + (((size_t)(rowbase + cr)) * NSTEPS + step) * 64 + cd4) = v;
        }
    }

    if (yi_out) {
        const float4 v = *reinterpret_cast<const float4*>(&sY[cr][cd4]);
        *reinterpret_cast<float4*>(yi_out + ((size_t)(rowbase + cr)) * 64 + cd4) = v;
    }
}

extern "C" void kernel_launch(void* const* d_in, const int* in_sizes, int n_in,
                              void* d_out, int out_size)
{
    const float* data = (const float*)d_in[0];
    const float* ts   = (const float*)d_in[1];
    const float* Wf1  = (const float*)d_in[2];
    const float* bf1  = (const float*)d_in[3];
    const float* Wf2  = (const float*)d_in[4];
    const float* bf2  = (const float*)d_in[5];
    const float* Wz1  = (const float*)d_in[6];
    const float* bz1  = (const float*)d_in[7];
    const float* Wz2  = (const float*)d_in[8];
    const float* bz2  = (const float*)d_in[9];
    const float* Wr1  = (const float*)d_in[10];
    const float* br1  = (const float*)d_in[11];
    const float* Wr2  = (const float*)d_in[12];
    const float* br2  = (const float*)d_in[13];
    const float* Wh1  = (const float*)d_in[14];
    const float* bh1  = (const float*)d_in[15];
    const float* Wh2  = (const float*)d_in[16];
    const float* bh2  = (const float*)d_in[17];

    const long long latN = 2048LL * 199 * 64;
    const long long yiN  = 2048LL * 64;
    float* out = (float*)d_out;
    float* yi_out = nullptr;
    float* lat_out = nullptr;
    if ((long long)out_size == latN + yiN) { yi_out = out; lat_out = out + yiN; }
    else if ((long long)out_size == latN)  { lat_out = out; }
    else if ((long long)out_size == yiN)   { yi_out = out; }
    else if ((long long)out_size > latN)   { yi_out = out; lat_out = out + yiN; }
    else                                   { lat_out = out; }

    cudaFuncSetAttribute(ode_main, cudaFuncAttributeMaxDynamicSharedMemorySize,
                         DYN_U32 * 4);

    prep_kernel<<<(W_TOTAL + 255) / 256, 256>>>(Wf1, Wf2, Wz1, Wz2, Wr1, Wr2, Wh1, Wh2);
    ode_main<<<128, 256, DYN_U32 * 4>>>(data, ts, bf1, bf2, bz1, bz2, br1, br2,
                                        bh1, bh2, yi_out, lat_out);
}

// round 12
// speedup vs baseline: 2.1052x; 1.0197x over previous
#include <cuda_runtime.h>
#include <cstdint>

// ODE-RNN fused scan, round 12 (= R11 resubmitted after infra failure).
// R10 + per-term MMA accumulators (Dhh/Dhl/Dlh) to break the serial HMMA
// dependency chains (3x shorter chains, 3x more ILP).

typedef unsigned int u32;
typedef unsigned long long u64;

#define NSTEPS 199
#define TT 200

// fragment-array geometry: per matrix [KC][NT][32 lanes][2 regs] of u32(bf16x2)
#define OFF_F1   0        // Wf1 : KC=4, NT=13
#define OFF_F2   3328     // Wf2 : KC=7, NT=8
#define OFF_ZR1  6912     // Wz1|Wr1 : KC=8, NT=25
#define OFF_Z2   19712    // Wz2 : KC=7, NT=8
#define OFF_R2   23296    // Wr2 : KC=7, NT=8
#define OFF_H1   26880    // Wh1 : KC=8, NT=13
#define OFF_H2   33536    // Wh2 : KC=7, NT=8
#define W_TOTAL  37120    // u32 (148,480 B)

// packed bf16x2 activation arrays (u32 units), strides 4*odd
#define SY_U32   36
#define SC_U32   68
#define SH_U32   60
#define AY_SZ    (16*SY_U32)
#define AC_SZ    (16*SC_U32)
#define AH_SZ    (16*SH_U32)
#define ACT_U32  (2*(AY_SZ + AC_SZ + 3*AH_SZ))
#define B_AYH  0
#define B_AYL  2304
#define B_ACH  4608
#define B_ACL  8960
#define B_AHAH 13312
#define B_AHAL 17152
#define B_AHZH 20992
#define B_AHZL 24832
#define B_AHRH 28672
#define B_AHRL 32512

#define DYN_U32 (W_TOTAL + ACT_U32)

__device__ __align__(16) u32 g_whi[W_TOTAL];
__device__ __align__(16) u32 g_wlo[W_TOTAL];

// ---------------- helpers ----------------

__device__ __forceinline__ u32 bf16_hi_bits(float x) {
    const u32 u = __float_as_uint(x);
    return (u + 0x7fffu + ((u >> 16) & 1u)) >> 16;
}
__device__ __forceinline__ float tanh_fast(float x) {
    const float e = __expf(2.0f * x);
    return 1.0f - __fdividef(2.0f, e + 1.0f);
}
__device__ __forceinline__ float sigmoid_fast(float x) {
    return __fdividef(1.0f, 1.0f + __expf(-x));
}
__device__ __forceinline__ void bsplit(float2 x, u32& h, u32& l) {
    u32 hh;
    asm("cvt.rn.bf16x2.f32 %0, %1, %2;" : "=r"(hh) : "f"(x.y), "f"(x.x));
    const float r0 = x.x - __uint_as_float(hh << 16);
    const float r1 = x.y - __uint_as_float(hh & 0xffff0000u);
    u32 ll;
    asm("cvt.rn.bf16x2.f32 %0, %1, %2;" : "=r"(ll) : "f"(r1), "f"(r0));
    h = hh; l = ll;
}
__device__ __forceinline__ void store_split(u32* hp, u32* lp, int idx, float2 v) {
    u32 h, l; bsplit(v, h, l); hp[idx] = h; lp[idx] = l;
}
__device__ __forceinline__ void mma4(float d[4], const u32 a[4], u32 b0, u32 b1) {
    asm("mma.sync.aligned.m16n8k16.row.col.f32.bf16.bf16.f32 "
        "{%0,%1,%2,%3}, {%4,%5,%6,%7}, {%8,%9}, {%0,%1,%2,%3};"
        : "+f"(d[0]), "+f"(d[1]), "+f"(d[2]), "+f"(d[3])
        : "r"(a[0]), "r"(a[1]), "r"(a[2]), "r"(a[3]), "r"(b0), "r"(b1));
}
__device__ __forceinline__ void ldm4(u32 r[4], u32 addr) {
    asm volatile("ldmatrix.sync.aligned.m8n8.x4.shared.b16 {%0,%1,%2,%3}, [%4];"
        : "=r"(r[0]), "=r"(r[1]), "=r"(r[2]), "=r"(r[3]) : "r"(addr));
}
__device__ __forceinline__ u32 smem_u32(const void* p) {
    return (u32)__cvta_generic_to_shared(p);
}
__device__ __forceinline__ int amat_off(int lane, int strideB) {
    const int r = lane & 7, m = lane >> 3;
    return (r + ((m & 1) << 3)) * strideB + ((m >> 1) << 4);
}

// GEMM with per-term accumulators: D = A_hi*B_hi + A_hi*B_lo + A_lo*B_hi,
// each term in its own chain; combined at the end.
template<int KC, int NT, int MAXT, int NTS>
__device__ __forceinline__ void run_gemm_tc(
    const u32 aHi, const u32 aLo,
    const u32* __restrict__ sBhi, const u32* __restrict__ gBlo,
    const int nt0, const int lane, float D[MAXT][4])
{
    float Dhh[MAXT][4], Dhl[MAXT][4], Dlh[MAXT][4];
#pragma unroll
    for (int i = 0; i < MAXT; ++i)
#pragma unroll
        for (int j = 0; j < 4; ++j) {
            Dhh[i][j] = 0.0f; Dhl[i][j] = 0.0f; Dlh[i][j] = 0.0f;
        }

    u64 blo[MAXT];
#pragma unroll
    for (int i = 0; i < MAXT; ++i) {
        blo[i] = 0ull;
        const int nt = nt0 + i * NTS;
        if (nt < NT) blo[i] = *(const u64*)(gBlo + (nt * 32 + lane) * 2);
    }
#pragma unroll 2
    for (int kc = 0; kc < KC; ++kc) {
        u64 blo_n[MAXT];
#pragma unroll
        for (int i = 0; i < MAXT; ++i) blo_n[i] = 0ull;
        if (kc + 1 < KC) {
#pragma unroll
            for (int i = 0; i < MAXT; ++i) {
                const int nt = nt0 + i * NTS;
                if (nt < NT)
                    blo_n[i] = *(const u64*)(gBlo + (((kc + 1) * NT + nt) * 32 + lane) * 2);
            }
        }
        u32 ah[4], al[4];
        ldm4(ah, aHi + kc * 32);
        ldm4(al, aLo + kc * 32);
#pragma unroll
        for (int i = 0; i < MAXT; ++i) {
            const int nt = nt0 + i * NTS;
            if (nt < NT) {
                const u64 bh = *(const u64*)(sBhi + ((kc * NT + nt) * 32 + lane) * 2);
                const u32 bh0 = (u32)bh, bh1 = (u32)(bh >> 32);
                mma4(Dhh[i], ah, bh0, bh1);
                mma4(Dhl[i], ah, (u32)blo[i], (u32)(blo[i] >> 32));
                mma4(Dlh[i], al, bh0, bh1);
            }
            blo[i] = blo_n[i];
        }
    }
#pragma unroll
    for (int i = 0; i < MAXT; ++i)
#pragma unroll
        for (int j = 0; j < 4; ++j)
            D[i][j] = (Dhh[i][j] + Dhl[i][j]) + Dlh[i][j];
}

// ---------------- prep kernel ----------------

__global__ void prep_kernel(
    const float* __restrict__ Wf1, const float* __restrict__ Wf2,
    const float* __restrict__ Wz1, const float* __restrict__ Wz2,
    const float* __restrict__ Wr1, const float* __restrict__ Wr2,
    const float* __restrict__ Wh1, const float* __restrict__ Wh2)
{
    const int i = blockIdx.x * blockDim.x + threadIdx.x;
    if (i >= W_TOTAL) return;

    int off, NT, Kr, Nr, ld;
    const float *S1 = nullptr, *S2 = nullptr;
    if (i < OFF_F2)        { off = OFF_F1;  NT = 13; Kr = 64;  Nr = 100; S1 = Wf1; ld = 100; }
    else if (i < OFF_ZR1)  { off = OFF_F2;  NT = 8;  Kr = 100; Nr = 64;  S1 = Wf2; ld = 64;  }
    else if (i < OFF_Z2)   { off = OFF_ZR1; NT = 25; Kr = 128; Nr = 200; S1 = Wz1; S2 = Wr1; ld = 100; }
    else if (i < OFF_R2)   { off = OFF_Z2;  NT = 8;  Kr = 100; Nr = 64;  S1 = Wz2; ld = 64;  }
    else if (i < OFF_H1)   { off = OFF_R2;  NT = 8;  Kr = 100; Nr = 64;  S1 = Wr2; ld = 64;  }
    else if (i < OFF_H2)   { off = OFF_H1;  NT = 13; Kr = 128; Nr = 100; S1 = Wh1; ld = 100; }
    else                   { off = OFF_H2;  NT = 8;  Kr = 100; Nr = 64;  S1 = Wh2; ld = 64;  }

    const int idx  = i - off;
    const int r    = idx & 1;
    const int lane = (idx >> 1) & 31;
    const int rest = idx >> 6;
    const int nt   = rest % NT;
    const int kc   = rest / NT;
    const int k0   = kc * 16 + (lane & 3) * 2 + (r ? 8 : 0);
    const int n    = nt * 8 + (lane >> 2);

    float x0 = 0.0f, x1 = 0.0f;
    if (n < Nr) {
        const float* S = S1; int nn = n;
        if (S2 && n >= 100) { S = S2; nn = n - 100; }
        if (k0     < Kr) x0 = S[(size_t)k0 * ld + nn];
        if (k0 + 1 < Kr) x1 = S[(size_t)(k0 + 1) * ld + nn];
    }
    const u32 h0 = bf16_hi_bits(x0), h1 = bf16_hi_bits(x1);
    const float r0 = x0 - __uint_as_float(h0 << 16);
    const float r1 = x1 - __uint_as_float(h1 << 16);
    const u32 l0 = bf16_hi_bits(r0), l1 = bf16_hi_bits(r1);
    g_whi[i] = h0 | (h1 << 16);
    g_wlo[i] = l0 | (l1 << 16);
}

// ---------------- main kernel ----------------

__global__ void __launch_bounds__(256, 1) ode_main(
    const float* __restrict__ data, const float* __restrict__ ts,
    const float* __restrict__ bf1, const float* __restrict__ bf2,
    const float* __restrict__ bz1, const float* __restrict__ bz2,
    const float* __restrict__ br1, const float* __restrict__ br2,
    const float* __restrict__ bh1, const float* __restrict__ bh2,
    float* __restrict__ yi_out, float* __restrict__ lat_out)
{
    __shared__ float sY [16][68];
    __shared__ float sYO[16][68];
    __shared__ float sZ [16][68];
    __shared__ float sbf1[100], sbz1[100], sbr1[100], sbh1[100];
    __shared__ float sbf2[64],  sbz2[64],  sbr2[64],  sbh2[64];
    __shared__ float sts_s[TT];
    extern __shared__ __align__(16) u32 dynW[];

    const int tid  = threadIdx.x;
    const int lane = tid & 31;
    const int w    = tid >> 5;
    const int g    = lane >> 2;
    const int tg   = lane & 3;
    const int rowbase = blockIdx.x * 16;

    u32* const actW = dynW + W_TOTAL;
    u32* const aYh  = actW;
    u32* const aYl  = actW + (B_AYL  >> 2);
    u32* const aCh  = actW + (B_ACH  >> 2);
    u32* const aCl  = actW + (B_ACL  >> 2);
    u32* const aHAh = actW + (B_AHAH >> 2);
    u32* const aHAl = actW + (B_AHAL >> 2);
    u32* const aHzh = actW + (B_AHZH >> 2);
    u32* const aHzl = actW + (B_AHZL >> 2);
    u32* const aHrh = actW + (B_AHRH >> 2);
    u32* const aHrl = actW + (B_AHRL >> 2);

    for (int i = tid; i < 16 * 68; i += 256) (&sY[0][0])[i] = 0.0f;
    for (int i = tid; i < ACT_U32; i += 256) actW[i] = 0u;
    for (int i = tid; i < 100; i += 256) {
        sbf1[i] = bf1[i]; sbz1[i] = bz1[i]; sbr1[i] = br1[i]; sbh1[i] = bh1[i];
    }
    for (int i = tid; i < 64; i += 256) {
        sbf2[i] = bf2[i]; sbz2[i] = bz2[i]; sbr2[i] = br2[i]; sbh2[i] = bh2[i];
    }
    for (int i = tid; i < TT; i += 256) sts_s[i] = ts[i];
    {
        const float4* s = (const float4*)g_whi;
        float4* d = (float4*)dynW;
        for (int i = tid; i < W_TOTAL / 4; i += 256) d[i] = s[i];
    }
    __syncthreads();

    const u32 base_act = smem_u32(actW);
    const int offY = amat_off(lane, SY_U32 * 4);
    const int offC = amat_off(lane, SC_U32 * 4);
    const int offH = amat_off(lane, SH_U32 * 4);
    const u32 adYh  = base_act + B_AYH  + offY, adYl  = base_act + B_AYL  + offY;
    const u32 adCh  = base_act + B_ACH  + offC, adCl  = base_act + B_ACL  + offC;
    const u32 adHAh = base_act + B_AHAH + offH, adHAl = base_act + B_AHAL + offH;
    const u32 adHzh = base_act + B_AHZH + offH, adHzl = base_act + B_AHZL + offH;
    const u32 adHrh = base_act + B_AHRH + offH, adHrl = base_act + B_AHRL + offH;

    const int cr  = tid >> 4;
    const int cd4 = (tid & 15) * 4;

    for (int step = 0; step < NSTEPS; ++step) {
        const float dt = (step == 0) ? (sts_s[1] - sts_s[0])
                                     : (sts_s[step - 1] - sts_s[step]);

        // x(t=step+1): split into aC cols [64:128) — all 16 rows
        {
            const float4 v = *reinterpret_cast<const float4*>(
                data + (((size_t)(rowbase + cr)) * TT + (step + 1)) * 64 + cd4);
            const int ci = cr * SC_U32 + 32 + (cd4 >> 1);
            store_split(aCh, aCl, ci,     make_float2(v.x, v.y));
            store_split(aCh, aCl, ci + 1, make_float2(v.z, v.w));
        }

        // ---- P1: HA = tanh(bf1 + Y @ Wf1)  [K=64, N=100] ----
        {
            float D[2][4];
            run_gemm_tc<4, 13, 2, 8>(adYh, adYl, dynW + OFF_F1, g_wlo + OFF_F1,
                                     w, lane, D);
#pragma unroll
            for (int i = 0; i < 2; ++i) {
                const int nt = w + i * 8;
                if (nt < 13) {
                    const int c0 = nt * 8 + tg * 2;
                    if (c0 < 100) {
                        const float b0 = sbf1[c0], b1 = sbf1[c0 + 1];
                        const int ci = (c0 >> 1);
                        store_split(aHAh, aHAl, g * SH_U32 + ci,
                            make_float2(tanh_fast(D[i][0] + b0), tanh_fast(D[i][1] + b1)));
                        store_split(aHAh, aHAl, (g + 8) * SH_U32 + ci,
                            make_float2(tanh_fast(D[i][2] + b0), tanh_fast(D[i][3] + b1)));
                    }
                }
            }
        }
        __syncthreads();

        // ---- P2: y_ode = Y + dt*(bf2 + HA @ Wf2)  [K=100, N=64] ----
        {
            float D[1][4];
            run_gemm_tc<7, 8, 1, 8>(adHAh, adHAl, dynW + OFF_F2, g_wlo + OFF_F2,
                                    w, lane, D);
            const int c0 = w * 8 + tg * 2;
            const float b0 = sbf2[c0], b1 = sbf2[c0 + 1];
            float2 v0, v1;
            v0.x = sY[g][c0]     + dt * (D[0][0] + b0);
            v0.y = sY[g][c0 + 1] + dt * (D[0][1] + b1);
            v1.x = sY[g + 8][c0]     + dt * (D[0][2] + b0);
            v1.y = sY[g + 8][c0 + 1] + dt * (D[0][3] + b1);
            *(float2*)&sYO[g][c0]     = v0;
            *(float2*)&sYO[g + 8][c0] = v1;
            store_split(aCh, aCl, g * SC_U32 + (c0 >> 1), v0);
            store_split(aCh, aCl, (g + 8) * SC_U32 + (c0 >> 1), v1);
        }
        __syncthreads();

        // ---- P3: z/r hidden = tanh(b + C @ [Wz1|Wr1])  [K=128, N=200] ----
        {
            float D[4][4];
            run_gemm_tc<8, 25, 4, 8>(adCh, adCl, dynW + OFF_ZR1, g_wlo + OFF_ZR1,
                                     w, lane, D);
#pragma unroll
            for (int i = 0; i < 4; ++i) {
                const int nt = w + i * 8;
                if (nt < 25) {
                    const int c0 = nt * 8 + tg * 2;
                    if (c0 < 100) {
                        const float b0 = sbz1[c0], b1 = sbz1[c0 + 1];
                        const int ci = c0 >> 1;
                        store_split(aHzh, aHzl, g * SH_U32 + ci,
                            make_float2(tanh_fast(D[i][0] + b0), tanh_fast(D[i][1] + b1)));
                        store_split(aHzh, aHzl, (g + 8) * SH_U32 + ci,
                            make_float2(tanh_fast(D[i][2] + b0), tanh_fast(D[i][3] + b1)));
                    } else {
                        const int c = c0 - 100;
                        const float b0 = sbr1[c], b1 = sbr1[c + 1];
                        const int ci = c >> 1;
                        store_split(aHrh, aHrl, g * SH_U32 + ci,
                            make_float2(tanh_fast(D[i][0] + b0), tanh_fast(D[i][1] + b1)));
                        store_split(aHrh, aHrl, (g + 8) * SH_U32 + ci,
                            make_float2(tanh_fast(D[i][2] + b0), tanh_fast(D[i][3] + b1)));
                    }
                }
            }
        }
        __syncthreads();

        // ---- P4: z = sig(bz2 + Hz@Wz2) -> sZ ; r: aC[:,0:64) = yO * sig(br2 + Hr@Wr2) ----
        {
            const bool isz = (w < 4);
            const u32 aH = isz ? adHzh : adHrh;
            const u32 aL = isz ? adHzl : adHrl;
            const u32* bh = dynW  + (isz ? OFF_Z2 : OFF_R2);
            const u32* bl = g_wlo + (isz ? OFF_Z2 : OFF_R2);
            const int nt0 = (w & 3) * 2;
            float D[2][4];
            run_gemm_tc<7, 8, 2, 1>(aH, aL, bh, bl, nt0, lane, D);
#pragma unroll
            for (int i = 0; i < 2; ++i) {
                const int c0 = (nt0 + i) * 8 + tg * 2;
                if (isz) {
                    const float b0 = sbz2[c0], b1 = sbz2[c0 + 1];
                    float2 v0, v1;
                    v0.x = sigmoid_fast(D[i][0] + b0); v0.y = sigmoid_fast(D[i][1] + b1);
                    v1.x = sigmoid_fast(D[i][2] + b0); v1.y = sigmoid_fast(D[i][3] + b1);
                    *(float2*)&sZ[g][c0]     = v0;
                    *(float2*)&sZ[g + 8][c0] = v1;
                } else {
                    const float b0 = sbr2[c0], b1 = sbr2[c0 + 1];
                    float2 v0, v1;
                    v0.x = sYO[g][c0]     * sigmoid_fast(D[i][0] + b0);
                    v0.y = sYO[g][c0 + 1] * sigmoid_fast(D[i][1] + b1);
                    v1.x = sYO[g + 8][c0]     * sigmoid_fast(D[i][2] + b0);
                    v1.y = sYO[g + 8][c0 + 1] * sigmoid_fast(D[i][3] + b1);
                    store_split(aCh, aCl, g * SC_U32 + (c0 >> 1), v0);
                    store_split(aCh, aCl, (g + 8) * SC_U32 + (c0 >> 1), v1);
                }
            }
        }
        __syncthreads();

        // ---- P6: HA = tanh(bh1 + C @ Wh1)  [K=128, N=100] ----
        {
            float D[2][4];
            run_gemm_tc<8, 13, 2, 8>(adCh, adCl, dynW + OFF_H1, g_wlo + OFF_H1,
                                     w, lane, D);
#pragma unroll
            for (int i = 0; i < 2; ++i) {
                const int nt = w + i * 8;
                if (nt < 13) {
                    const int c0 = nt * 8 + tg * 2;
                    if (c0 < 100) {
                        const float b0 = sbh1[c0], b1 = sbh1[c0 + 1];
                        const int ci = c0 >> 1;
                        store_split(aHAh, aHAl, g * SH_U32 + ci,
                            make_float2(tanh_fast(D[i][0] + b0), tanh_fast(D[i][1] + b1)));
                        store_split(aHAh, aHAl, (g + 8) * SH_U32 + ci,
                            make_float2(tanh_fast(D[i][2] + b0), tanh_fast(D[i][3] + b1)));
                    }
                }
            }
        }
        __syncthreads();

        // ---- P7: h = tanh(bh2 + HA @ Wh2); y = (1-z)h + z*yO ----
        {
            float D[1][4];
            run_gemm_tc<7, 8, 1, 8>(adHAh, adHAl, dynW + OFF_H2, g_wlo + OFF_H2,
                                    w, lane, D);
            const int c0 = w * 8 + tg * 2;
            const float b0 = sbh2[c0], b1 = sbh2[c0 + 1];
            {
                const float h0 = tanh_fast(D[0][0] + b0);
                const float h1 = tanh_fast(D[0][1] + b1);
                const float z0 = sZ[g][c0], z1 = sZ[g][c0 + 1];
                float2 v;
                v.x = (1.0f - z0) * h0 + z0 * sYO[g][c0];
                v.y = (1.0f - z1) * h1 + z1 * sYO[g][c0 + 1];
                *(float2*)&sY[g][c0] = v;
                store_split(aYh, aYl, g * SY_U32 + (c0 >> 1), v);
            }
            {
                const float h0 = tanh_fast(D[0][2] + b0);
                const float h1 = tanh_fast(D[0][3] + b1);
                const float z0 = sZ[g + 8][c0], z1 = sZ[g + 8][c0 + 1];
                float2 v;
                v.x = (1.0f - z0) * h0 + z0 * sYO[g + 8][c0];
                v.y = (1.0f - z1) * h1 + z1 * sYO[g + 8][c0 + 1];
                *(float2*)&sY[g + 8][c0] = v;
                store_split(aYh, aYl, (g + 8) * SY_U32 + (c0 >> 1), v);
            }
        }
        __syncthreads();

        if (lat_out) {
            const float4 v = *reinterpret_cast<const float4*>(&sY[cr][cd4]);
            *reinterpret_cast<float4*>(
                lat_out + (((size_t)(rowbase + cr)) * NSTEPS + step) * 64 + cd4) = v;
        }
    }

    if (yi_out) {
        const float4 v = *reinterpret_cast<const float4*>(&sY[cr][cd4]);
        *reinterpret_cast<float4*>(yi_out + ((size_t)(rowbase + cr)) * 64 + cd4) = v;
    }
}

extern "C" void kernel_launch(void* const* d_in, const int* in_sizes, int n_in,
                              void* d_out, int out_size)
{
    const float* data = (const float*)d_in[0];
    const float* ts   = (const float*)d_in[1];
    const float* Wf1  = (const float*)d_in[2];
    const float* bf1  = (const float*)d_in[3];
    const float* Wf2  = (const float*)d_in[4];
    const float* bf2  = (const float*)d_in[5];
    const float* Wz1  = (const float*)d_in[6];
    const float* bz1  = (const float*)d_in[7];
    const float* Wz2  = (const float*)d_in[8];
    const float* bz2  = (const float*)d_in[9];
    const float* Wr1  = (const float*)d_in[10];
    const float* br1  = (const float*)d_in[11];
    const float* Wr2  = (const float*)d_in[12];
    const float* br2  = (const float*)d_in[13];
    const float* Wh1  = (const float*)d_in[14];
    const float* bh1  = (const float*)d_in[15];
    const float* Wh2  = (const float*)d_in[16];
    const float* bh2  = (const float*)d_in[17];

    const long long latN = 2048LL * 199 * 64;
    const long long yiN  = 2048LL * 64;
    float* out = (float*)d_out;
    float* yi_out = nullptr;
    float* lat_out = nullptr;
    if ((long long)out_size == latN + yiN) { yi_out = out; lat_out = out + yiN; }
    else if ((long long)out_size == latN)  { lat_out = out; }
    else if ((long long)out_size == yiN)   { yi_out = out; }
    else if ((long long)out_size > latN)   { yi_out = out; lat_out = out + yiN; }
    else                                   { lat_out = out; }

    cudaFuncSetAttribute(ode_main, cudaFuncAttributeMaxDynamicSharedMemorySize,
                         DYN_U32 * 4);

    prep_kernel<<<(W_TOTAL + 255) / 256, 256>>>(Wf1, Wf2, Wz1, Wz2, Wr1, Wr2, Wh1, Wh2);
    ode_main<<<128, 256, DYN_U32 * 4>>>(data, ts, bf1, bf2, bz1, bz2, br1, br2,
                                        bh1, bh2, yi_out, lat_out);
}

// round 13
// speedup vs baseline: 2.6293x; 1.2490x over previous
#include <cuda_runtime.h>
#include <cstdint>

// ODE-RNN fused scan, round 13: 512 threads / 16 warps per CTA (4 warps/SMSP,
// 2x latency hiding), per-warp work halved on wide phases, x-prefetch
// overlapped with P7. Per-term MMA accumulators, ldmatrix A-path, hi-weights
// in SMEM, lo-weights streamed from L2.

typedef unsigned int u32;
typedef unsigned long long u64;

#define NSTEPS 199
#define TT 200

// fragment-array geometry: per matrix [KC][NT][32 lanes][2 regs] of u32(bf16x2)
#define OFF_F1   0        // Wf1 : KC=4, NT=13
#define OFF_F2   3328     // Wf2 : KC=7, NT=8
#define OFF_ZR1  6912     // Wz1|Wr1 : KC=8, NT=25
#define OFF_Z2   19712    // Wz2 : KC=7, NT=8
#define OFF_R2   23296    // Wr2 : KC=7, NT=8
#define OFF_H1   26880    // Wh1 : KC=8, NT=13
#define OFF_H2   33536    // Wh2 : KC=7, NT=8
#define W_TOTAL  37120    // u32 (148,480 B)

// packed bf16x2 activation arrays (u32 units), strides 4*odd
#define SY_U32   36
#define SC_U32   68
#define SH_U32   60
#define AY_SZ    (16*SY_U32)
#define AC_SZ    (16*SC_U32)
#define AH_SZ    (16*SH_U32)
#define ACT_U32  (2*(AY_SZ + AC_SZ + 3*AH_SZ))
#define B_AYH  0
#define B_AYL  2304
#define B_ACH  4608
#define B_ACL  8960
#define B_AHAH 13312
#define B_AHAL 17152
#define B_AHZH 20992
#define B_AHZL 24832
#define B_AHRH 28672
#define B_AHRL 32512

#define DYN_U32 (W_TOTAL + ACT_U32)

__device__ __align__(16) u32 g_whi[W_TOTAL];
__device__ __align__(16) u32 g_wlo[W_TOTAL];

// ---------------- helpers ----------------

__device__ __forceinline__ u32 bf16_hi_bits(float x) {
    const u32 u = __float_as_uint(x);
    return (u + 0x7fffu + ((u >> 16) & 1u)) >> 16;
}
__device__ __forceinline__ float tanh_fast(float x) {
    const float e = __expf(2.0f * x);
    return 1.0f - __fdividef(2.0f, e + 1.0f);
}
__device__ __forceinline__ float sigmoid_fast(float x) {
    return __fdividef(1.0f, 1.0f + __expf(-x));
}
__device__ __forceinline__ void bsplit(float2 x, u32& h, u32& l) {
    u32 hh;
    asm("cvt.rn.bf16x2.f32 %0, %1, %2;" : "=r"(hh) : "f"(x.y), "f"(x.x));
    const float r0 = x.x - __uint_as_float(hh << 16);
    const float r1 = x.y - __uint_as_float(hh & 0xffff0000u);
    u32 ll;
    asm("cvt.rn.bf16x2.f32 %0, %1, %2;" : "=r"(ll) : "f"(r1), "f"(r0));
    h = hh; l = ll;
}
__device__ __forceinline__ void store_split(u32* hp, u32* lp, int idx, float2 v) {
    u32 h, l; bsplit(v, h, l); hp[idx] = h; lp[idx] = l;
}
__device__ __forceinline__ void mma4(float d[4], const u32 a[4], u32 b0, u32 b1) {
    asm("mma.sync.aligned.m16n8k16.row.col.f32.bf16.bf16.f32 "
        "{%0,%1,%2,%3}, {%4,%5,%6,%7}, {%8,%9}, {%0,%1,%2,%3};"
        : "+f"(d[0]), "+f"(d[1]), "+f"(d[2]), "+f"(d[3])
        : "r"(a[0]), "r"(a[1]), "r"(a[2]), "r"(a[3]), "r"(b0), "r"(b1));
}
__device__ __forceinline__ void ldm4(u32 r[4], u32 addr) {
    asm volatile("ldmatrix.sync.aligned.m8n8.x4.shared.b16 {%0,%1,%2,%3}, [%4];"
        : "=r"(r[0]), "=r"(r[1]), "=r"(r[2]), "=r"(r[3]) : "r"(addr));
}
__device__ __forceinline__ u32 smem_u32(const void* p) {
    return (u32)__cvta_generic_to_shared(p);
}
__device__ __forceinline__ int amat_off(int lane, int strideB) {
    const int r = lane & 7, m = lane >> 3;
    return (r + ((m & 1) << 3)) * strideB + ((m >> 1) << 4);
}

// GEMM with per-term accumulators: D = A_hi*B_hi + A_hi*B_lo + A_lo*B_hi.
template<int KC, int NT, int MAXT, int NTS>
__device__ __forceinline__ void run_gemm_tc(
    const u32 aHi, const u32 aLo,
    const u32* __restrict__ sBhi, const u32* __restrict__ gBlo,
    const int nt0, const int lane, float D[MAXT][4])
{
    float Dhh[MAXT][4], Dhl[MAXT][4], Dlh[MAXT][4];
#pragma unroll
    for (int i = 0; i < MAXT; ++i)
#pragma unroll
        for (int j = 0; j < 4; ++j) {
            Dhh[i][j] = 0.0f; Dhl[i][j] = 0.0f; Dlh[i][j] = 0.0f;
        }

    u64 blo[MAXT];
#pragma unroll
    for (int i = 0; i < MAXT; ++i) {
        blo[i] = 0ull;
        const int nt = nt0 + i * NTS;
        if (nt < NT) blo[i] = *(const u64*)(gBlo + (nt * 32 + lane) * 2);
    }
#pragma unroll 2
    for (int kc = 0; kc < KC; ++kc) {
        u64 blo_n[MAXT];
#pragma unroll
        for (int i = 0; i < MAXT; ++i) blo_n[i] = 0ull;
        if (kc + 1 < KC) {
#pragma unroll
            for (int i = 0; i < MAXT; ++i) {
                const int nt = nt0 + i * NTS;
                if (nt < NT)
                    blo_n[i] = *(const u64*)(gBlo + (((kc + 1) * NT + nt) * 32 + lane) * 2);
            }
        }
        u32 ah[4], al[4];
        ldm4(ah, aHi + kc * 32);
        ldm4(al, aLo + kc * 32);
#pragma unroll
        for (int i = 0; i < MAXT; ++i) {
            const int nt = nt0 + i * NTS;
            if (nt < NT) {
                const u64 bh = *(const u64*)(sBhi + ((kc * NT + nt) * 32 + lane) * 2);
                const u32 bh0 = (u32)bh, bh1 = (u32)(bh >> 32);
                mma4(Dhh[i], ah, bh0, bh1);
                mma4(Dhl[i], ah, (u32)blo[i], (u32)(blo[i] >> 32));
                mma4(Dlh[i], al, bh0, bh1);
            }
            blo[i] = blo_n[i];
        }
    }
#pragma unroll
    for (int i = 0; i < MAXT; ++i)
#pragma unroll
        for (int j = 0; j < 4; ++j)
            D[i][j] = (Dhh[i][j] + Dhl[i][j]) + Dlh[i][j];
}

// ---------------- prep kernel ----------------

__global__ void prep_kernel(
    const float* __restrict__ Wf1, const float* __restrict__ Wf2,
    const float* __restrict__ Wz1, const float* __restrict__ Wz2,
    const float* __restrict__ Wr1, const float* __restrict__ Wr2,
    const float* __restrict__ Wh1, const float* __restrict__ Wh2)
{
    const int i = blockIdx.x * blockDim.x + threadIdx.x;
    if (i >= W_TOTAL) return;

    int off, NT, Kr, Nr, ld;
    const float *S1 = nullptr, *S2 = nullptr;
    if (i < OFF_F2)        { off = OFF_F1;  NT = 13; Kr = 64;  Nr = 100; S1 = Wf1; ld = 100; }
    else if (i < OFF_ZR1)  { off = OFF_F2;  NT = 8;  Kr = 100; Nr = 64;  S1 = Wf2; ld = 64;  }
    else if (i < OFF_Z2)   { off = OFF_ZR1; NT = 25; Kr = 128; Nr = 200; S1 = Wz1; S2 = Wr1; ld = 100; }
    else if (i < OFF_R2)   { off = OFF_Z2;  NT = 8;  Kr = 100; Nr = 64;  S1 = Wz2; ld = 64;  }
    else if (i < OFF_H1)   { off = OFF_R2;  NT = 8;  Kr = 100; Nr = 64;  S1 = Wr2; ld = 64;  }
    else if (i < OFF_H2)   { off = OFF_H1;  NT = 13; Kr = 128; Nr = 100; S1 = Wh1; ld = 100; }
    else                   { off = OFF_H2;  NT = 8;  Kr = 100; Nr = 64;  S1 = Wh2; ld = 64;  }

    const int idx  = i - off;
    const int r    = idx & 1;
    const int lane = (idx >> 1) & 31;
    const int rest = idx >> 6;
    const int nt   = rest % NT;
    const int kc   = rest / NT;
    const int k0   = kc * 16 + (lane & 3) * 2 + (r ? 8 : 0);
    const int n    = nt * 8 + (lane >> 2);

    float x0 = 0.0f, x1 = 0.0f;
    if (n < Nr) {
        const float* S = S1; int nn = n;
        if (S2 && n >= 100) { S = S2; nn = n - 100; }
        if (k0     < Kr) x0 = S[(size_t)k0 * ld + nn];
        if (k0 + 1 < Kr) x1 = S[(size_t)(k0 + 1) * ld + nn];
    }
    const u32 h0 = bf16_hi_bits(x0), h1 = bf16_hi_bits(x1);
    const float r0 = x0 - __uint_as_float(h0 << 16);
    const float r1 = x1 - __uint_as_float(h1 << 16);
    const u32 l0 = bf16_hi_bits(r0), l1 = bf16_hi_bits(r1);
    g_whi[i] = h0 | (h1 << 16);
    g_wlo[i] = l0 | (l1 << 16);
}

// ---------------- main kernel ----------------

__global__ void __launch_bounds__(512, 1) ode_main(
    const float* __restrict__ data, const float* __restrict__ ts,
    const float* __restrict__ bf1, const float* __restrict__ bf2,
    const float* __restrict__ bz1, const float* __restrict__ bz2,
    const float* __restrict__ br1, const float* __restrict__ br2,
    const float* __restrict__ bh1, const float* __restrict__ bh2,
    float* __restrict__ yi_out, float* __restrict__ lat_out)
{
    __shared__ float sY [16][68];
    __shared__ float sYO[16][68];
    __shared__ float sZ [16][68];
    __shared__ float sbf1[100], sbz1[100], sbr1[100], sbh1[100];
    __shared__ float sbf2[64],  sbz2[64],  sbr2[64],  sbh2[64];
    __shared__ float sts_s[TT];
    extern __shared__ __align__(16) u32 dynW[];

    const int tid  = threadIdx.x;
    const int lane = tid & 31;
    const int w    = tid >> 5;       // 0..15
    const int g    = lane >> 2;
    const int tg   = lane & 3;
    const int rowbase = blockIdx.x * 16;

    u32* const actW = dynW + W_TOTAL;
    u32* const aYh  = actW;
    u32* const aYl  = actW + (B_AYL  >> 2);
    u32* const aCh  = actW + (B_ACH  >> 2);
    u32* const aCl  = actW + (B_ACL  >> 2);
    u32* const aHAh = actW + (B_AHAH >> 2);
    u32* const aHAl = actW + (B_AHAL >> 2);
    u32* const aHzh = actW + (B_AHZH >> 2);
    u32* const aHzl = actW + (B_AHZL >> 2);
    u32* const aHrh = actW + (B_AHRH >> 2);
    u32* const aHrl = actW + (B_AHRL >> 2);

    for (int i = tid; i < 16 * 68; i += 512) (&sY[0][0])[i] = 0.0f;
    for (int i = tid; i < ACT_U32; i += 512) actW[i] = 0u;
    for (int i = tid; i < 100; i += 512) {
        sbf1[i] = bf1[i]; sbz1[i] = bz1[i]; sbr1[i] = br1[i]; sbh1[i] = bh1[i];
    }
    for (int i = tid; i < 64; i += 512) {
        sbf2[i] = bf2[i]; sbz2[i] = bz2[i]; sbr2[i] = br2[i]; sbh2[i] = bh2[i];
    }
    for (int i = tid; i < TT; i += 512) sts_s[i] = ts[i];
    {
        const float4* s = (const float4*)g_whi;
        float4* d = (float4*)dynW;
        for (int i = tid; i < W_TOTAL / 4; i += 512) d[i] = s[i];
    }
    __syncthreads();   // actW zeroed before x-load below

    // x for step 0 (data index 1), by first 256 threads
    if (tid < 256) {
        const int cr0  = tid >> 4;
        const int cd40 = (tid & 15) * 4;
        const float4 v = *reinterpret_cast<const float4*>(
            data + (((size_t)(rowbase + cr0)) * TT + 1) * 64 + cd40);
        const int ci = cr0 * SC_U32 + 32 + (cd40 >> 1);
        store_split(aCh, aCl, ci,     make_float2(v.x, v.y));
        store_split(aCh, aCl, ci + 1, make_float2(v.z, v.w));
    }
    __syncthreads();

    const u32 base_act = smem_u32(actW);
    const int offY = amat_off(lane, SY_U32 * 4);
    const int offC = amat_off(lane, SC_U32 * 4);
    const int offH = amat_off(lane, SH_U32 * 4);
    const u32 adYh  = base_act + B_AYH  + offY, adYl  = base_act + B_AYL  + offY;
    const u32 adCh  = base_act + B_ACH  + offC, adCl  = base_act + B_ACL  + offC;
    const u32 adHAh = base_act + B_AHAH + offH, adHAl = base_act + B_AHAL + offH;
    const u32 adHzh = base_act + B_AHZH + offH, adHzl = base_act + B_AHZL + offH;
    const u32 adHrh = base_act + B_AHRH + offH, adHrl = base_act + B_AHRL + offH;

    for (int step = 0; step < NSTEPS; ++step) {
        const float dt = (step == 0) ? (sts_s[1] - sts_s[0])
                                     : (sts_s[step - 1] - sts_s[step]);

        // ---- P1: HA = tanh(bf1 + Y @ Wf1)  [K=64, N=100], warps 0-12 ----
        if (w < 13) {
            float D[1][4];
            run_gemm_tc<4, 13, 1, 1>(adYh, adYl, dynW + OFF_F1, g_wlo + OFF_F1,
                                     w, lane, D);
            const int c0 = w * 8 + tg * 2;
            if (c0 < 100) {
                const float b0 = sbf1[c0], b1 = sbf1[c0 + 1];
                const int ci = c0 >> 1;
                store_split(aHAh, aHAl, g * SH_U32 + ci,
                    make_float2(tanh_fast(D[0][0] + b0), tanh_fast(D[0][1] + b1)));
                store_split(aHAh, aHAl, (g + 8) * SH_U32 + ci,
                    make_float2(tanh_fast(D[0][2] + b0), tanh_fast(D[0][3] + b1)));
            }
        }
        __syncthreads();

        // ---- P2: y_ode = Y + dt*(bf2 + HA @ Wf2)  [K=100, N=64], warps 0-7 ----
        if (w < 8) {
            float D[1][4];
            run_gemm_tc<7, 8, 1, 1>(adHAh, adHAl, dynW + OFF_F2, g_wlo + OFF_F2,
                                    w, lane, D);
            const int c0 = w * 8 + tg * 2;
            const float b0 = sbf2[c0], b1 = sbf2[c0 + 1];
            float2 v0, v1;
            v0.x = sY[g][c0]     + dt * (D[0][0] + b0);
            v0.y = sY[g][c0 + 1] + dt * (D[0][1] + b1);
            v1.x = sY[g + 8][c0]     + dt * (D[0][2] + b0);
            v1.y = sY[g + 8][c0 + 1] + dt * (D[0][3] + b1);
            *(float2*)&sYO[g][c0]     = v0;
            *(float2*)&sYO[g + 8][c0] = v1;
            store_split(aCh, aCl, g * SC_U32 + (c0 >> 1), v0);
            store_split(aCh, aCl, (g + 8) * SC_U32 + (c0 >> 1), v1);
        }
        __syncthreads();

        // ---- P3: z/r hidden = tanh(b + C @ [Wz1|Wr1])  [K=128, N=200], all warps ----
        {
            float D[2][4];
            run_gemm_tc<8, 25, 2, 16>(adCh, adCl, dynW + OFF_ZR1, g_wlo + OFF_ZR1,
                                      w, lane, D);
#pragma unroll
            for (int i = 0; i < 2; ++i) {
                const int nt = w + i * 16;
                if (nt < 25) {
                    const int c0 = nt * 8 + tg * 2;
                    if (c0 < 100) {
                        const float b0 = sbz1[c0], b1 = sbz1[c0 + 1];
                        const int ci = c0 >> 1;
                        store_split(aHzh, aHzl, g * SH_U32 + ci,
                            make_float2(tanh_fast(D[i][0] + b0), tanh_fast(D[i][1] + b1)));
                        store_split(aHzh, aHzl, (g + 8) * SH_U32 + ci,
                            make_float2(tanh_fast(D[i][2] + b0), tanh_fast(D[i][3] + b1)));
                    } else {
                        const int c = c0 - 100;
                        const float b0 = sbr1[c], b1 = sbr1[c + 1];
                        const int ci = c >> 1;
                        store_split(aHrh, aHrl, g * SH_U32 + ci,
                            make_float2(tanh_fast(D[i][0] + b0), tanh_fast(D[i][1] + b1)));
                        store_split(aHrh, aHrl, (g + 8) * SH_U32 + ci,
                            make_float2(tanh_fast(D[i][2] + b0), tanh_fast(D[i][3] + b1)));
                    }
                }
            }
        }
        __syncthreads();

        // ---- P4: z (warps 0-7) / r (warps 8-15)  [K=100, N=64 each] ----
        {
            const bool isz = (w < 8);
            const u32 aH = isz ? adHzh : adHrh;
            const u32 aL = isz ? adHzl : adHrl;
            const u32* bh = dynW  + (isz ? OFF_Z2 : OFF_R2);
            const u32* bl = g_wlo + (isz ? OFF_Z2 : OFF_R2);
            const int nt0 = w & 7;
            float D[1][4];
            run_gemm_tc<7, 8, 1, 1>(aH, aL, bh, bl, nt0, lane, D);
            const int c0 = nt0 * 8 + tg * 2;
            if (isz) {
                const float b0 = sbz2[c0], b1 = sbz2[c0 + 1];
                float2 v0, v1;
                v0.x = sigmoid_fast(D[0][0] + b0); v0.y = sigmoid_fast(D[0][1] + b1);
                v1.x = sigmoid_fast(D[0][2] + b0); v1.y = sigmoid_fast(D[0][3] + b1);
                *(float2*)&sZ[g][c0]     = v0;
                *(float2*)&sZ[g + 8][c0] = v1;
            } else {
                const float b0 = sbr2[c0], b1 = sbr2[c0 + 1];
                float2 v0, v1;
                v0.x = sYO[g][c0]     * sigmoid_fast(D[0][0] + b0);
                v0.y = sYO[g][c0 + 1] * sigmoid_fast(D[0][1] + b1);
                v1.x = sYO[g + 8][c0]     * sigmoid_fast(D[0][2] + b0);
                v1.y = sYO[g + 8][c0 + 1] * sigmoid_fast(D[0][3] + b1);
                store_split(aCh, aCl, g * SC_U32 + (c0 >> 1), v0);
                store_split(aCh, aCl, (g + 8) * SC_U32 + (c0 >> 1), v1);
            }
        }
        __syncthreads();

        // ---- P6: HA = tanh(bh1 + C @ Wh1)  [K=128, N=100], warps 0-12 ----
        if (w < 13) {
            float D[1][4];
            run_gemm_tc<8, 13, 1, 1>(adCh, adCl, dynW + OFF_H1, g_wlo + OFF_H1,
                                     w, lane, D);
            const int c0 = w * 8 + tg * 2;
            if (c0 < 100) {
                const float b0 = sbh1[c0], b1 = sbh1[c0 + 1];
                const int ci = c0 >> 1;
                store_split(aHAh, aHAl, g * SH_U32 + ci,
                    make_float2(tanh_fast(D[0][0] + b0), tanh_fast(D[0][1] + b1)));
                store_split(aHAh, aHAl, (g + 8) * SH_U32 + ci,
                    make_float2(tanh_fast(D[0][2] + b0), tanh_fast(D[0][3] + b1)));
            }
        }
        __syncthreads();

        // ---- P7: h = tanh(bh2 + HA @ Wh2); y = (1-z)h + z*yO, warps 0-7.
        //      Warps 8-15 concurrently prefetch x for step+1 into aC[64:128)
        //      (safe: last consumer of aC this step was P6). ----
        if (w < 8) {
            float D[1][4];
            run_gemm_tc<7, 8, 1, 1>(adHAh, adHAl, dynW + OFF_H2, g_wlo + OFF_H2,
                                    w, lane, D);
            const int c0 = w * 8 + tg * 2;
            const float b0 = sbh2[c0], b1 = sbh2[c0 + 1];
            {
                const float h0 = tanh_fast(D[0][0] + b0);
                const float h1 = tanh_fast(D[0][1] + b1);
                const float z0 = sZ[g][c0], z1 = sZ[g][c0 + 1];
                float2 v;
                v.x = (1.0f - z0) * h0 + z0 * sYO[g][c0];
                v.y = (1.0f - z1) * h1 + z1 * sYO[g][c0 + 1];
                *(float2*)&sY[g][c0] = v;
                store_split(aYh, aYl, g * SY_U32 + (c0 >> 1), v);
            }
            {
                const float h0 = tanh_fast(D[0][2] + b0);
                const float h1 = tanh_fast(D[0][3] + b1);
                const float z0 = sZ[g + 8][c0], z1 = sZ[g + 8][c0 + 1];
                float2 v;
                v.x = (1.0f - z0) * h0 + z0 * sYO[g + 8][c0];
                v.y = (1.0f - z1) * h1 + z1 * sYO[g + 8][c0 + 1];
                *(float2*)&sY[g + 8][c0] = v;
                store_split(aYh, aYl, (g + 8) * SY_U32 + (c0 >> 1), v);
            }
        } else if (step + 2 < TT) {
            const int t2  = tid - 256;           // 0..255
            const int cr2 = t2 >> 4;
            const int cd2 = (t2 & 15) * 4;
            const float4 v = *reinterpret_cast<const float4*>(
                data + (((size_t)(rowbase + cr2)) * TT + (step + 2)) * 64 + cd2);
            const int ci = cr2 * SC_U32 + 32 + (cd2 >> 1);
            store_split(aCh, aCl, ci,     make_float2(v.x, v.y));
            store_split(aCh, aCl, ci + 1, make_float2(v.z, v.w));
        }
        __syncthreads();

        if (lat_out && tid < 256) {
            const int cr0  = tid >> 4;
            const int cd40 = (tid & 15) * 4;
            const float4 v = *reinterpret_cast<const float4*>(&sY[cr0][cd40]);
            *reinterpret_cast<float4*>(
                lat_out + (((size_t)(rowbase + cr0)) * NSTEPS + step) * 64 + cd40) = v;
        }
    }

    if (yi_out && tid < 256) {
        const int cr0  = tid >> 4;
        const int cd40 = (tid & 15) * 4;
        const float4 v = *reinterpret_cast<const float4*>(&sY[cr0][cd40]);
        *reinterpret_cast<float4*>(yi_out + ((size_t)(rowbase + cr0)) * 64 + cd40) = v;
    }
}

extern "C" void kernel_launch(void* const* d_in, const int* in_sizes, int n_in,
                              void* d_out, int out_size)
{
    const float* data = (const float*)d_in[0];
    const float* ts   = (const float*)d_in[1];
    const float* Wf1  = (const float*)d_in[2];
    const float* bf1  = (const float*)d_in[3];
    const float* Wf2  = (const float*)d_in[4];
    const float* bf2  = (const float*)d_in[5];
    const float* Wz1  = (const float*)d_in[6];
    const float* bz1  = (const float*)d_in[7];
    const float* Wz2  = (const float*)d_in[8];
    const float* bz2  = (const float*)d_in[9];
    const float* Wr1  = (const float*)d_in[10];
    const float* br1  = (const float*)d_in[11];
    const float* Wr2  = (const float*)d_in[12];
    const float* br2  = (const float*)d_in[13];
    const float* Wh1  = (const float*)d_in[14];
    const float* bh1  = (const float*)d_in[15];
    const float* Wh2  = (const float*)d_in[16];
    const float* bh2  = (const float*)d_in[17];

    const long long latN = 2048LL * 199 * 64;
    const long long yiN  = 2048LL * 64;
    float* out = (float*)d_out;
    float* yi_out = nullptr;
    float* lat_out = nullptr;
    if ((long long)out_size == latN + yiN) { yi_out = out; lat_out = out + yiN; }
    else if ((long long)out_size == latN)  { lat_out = out; }
    else if ((long long)out_size == yiN)   { yi_out = out; }
    else if ((long long)out_size > latN)   { yi_out = out; lat_out = out + yiN; }
    else                                   { lat_out = out; }

    cudaFuncSetAttribute(ode_main, cudaFuncAttributeMaxDynamicSharedMemorySize,
                         DYN_U32 * 4);

    prep_kernel<<<(W_TOTAL + 255) / 256, 256>>>(Wf1, Wf2, Wz1, Wz2, Wr1, Wr2, Wh1, Wh2);
    ode_main<<<128, 512, DYN_U32 * 4>>>(data, ts, bf1, bf2, bz1, bz2, br1, br2,
                                        bh1, bh2, yi_out, lat_out);
}

// round 14
// speedup vs baseline: 2.9328x; 1.1155x over previous
#include <cuda_runtime.h>
#include <cstdint>

// ODE-RNN fused scan, round 14: R13 + (a) P3 double-tiles moved to warps 8-15
// (idle in P2/P7) so the critical warp drops 49->41 kc, (b) cross-phase
// prefetch of each phase's first lo-weight fragment, (c) paired-reciprocal
// tanh/sigmoid (one MUFU rcp per 2 activations).

typedef unsigned int u32;
typedef unsigned long long u64;

#define NSTEPS 199
#define TT 200

// fragment-array geometry: per matrix [KC][NT][32 lanes][2 regs] of u32(bf16x2)
#define OFF_F1   0        // Wf1 : KC=4, NT=13
#define OFF_F2   3328     // Wf2 : KC=7, NT=8
#define OFF_ZR1  6912     // Wz1|Wr1 : KC=8, NT=25
#define OFF_Z2   19712    // Wz2 : KC=7, NT=8
#define OFF_R2   23296    // Wr2 : KC=7, NT=8
#define OFF_H1   26880    // Wh1 : KC=8, NT=13
#define OFF_H2   33536    // Wh2 : KC=7, NT=8
#define W_TOTAL  37120    // u32 (148,480 B)

// packed bf16x2 activation arrays (u32 units), strides 4*odd
#define SY_U32   36
#define SC_U32   68
#define SH_U32   60
#define AY_SZ    (16*SY_U32)
#define AC_SZ    (16*SC_U32)
#define AH_SZ    (16*SH_U32)
#define ACT_U32  (2*(AY_SZ + AC_SZ + 3*AH_SZ))
#define B_AYH  0
#define B_AYL  2304
#define B_ACH  4608
#define B_ACL  8960
#define B_AHAH 13312
#define B_AHAL 17152
#define B_AHZH 20992
#define B_AHZL 24832
#define B_AHRH 28672
#define B_AHRL 32512

#define DYN_U32 (W_TOTAL + ACT_U32)

__device__ __align__(16) u32 g_whi[W_TOTAL];
__device__ __align__(16) u32 g_wlo[W_TOTAL];

// ---------------- helpers ----------------

__device__ __forceinline__ u32 bf16_hi_bits(float x) {
    const u32 u = __float_as_uint(x);
    return (u + 0x7fffu + ((u >> 16) & 1u)) >> 16;
}
// paired activations: one MUFU rcp per 2 values. Inputs clamped to +-30 so
// a0*a1 stays finite (no inf*0 NaN path).
__device__ __forceinline__ float2 tanh2(float2 x) {
    const float e0 = __expf(2.0f * fminf(fmaxf(x.x, -30.0f), 30.0f));
    const float e1 = __expf(2.0f * fminf(fmaxf(x.y, -30.0f), 30.0f));
    const float a0 = e0 + 1.0f, a1 = e1 + 1.0f;
    const float d = __fdividef(2.0f, a0 * a1);
    return make_float2(1.0f - d * a1, 1.0f - d * a0);
}
__device__ __forceinline__ float2 sigmoid2(float2 x) {
    const float e0 = __expf(-fminf(fmaxf(x.x, -30.0f), 30.0f));
    const float e1 = __expf(-fminf(fmaxf(x.y, -30.0f), 30.0f));
    const float a0 = 1.0f + e0, a1 = 1.0f + e1;
    const float d = __fdividef(1.0f, a0 * a1);
    return make_float2(d * a1, d * a0);
}
__device__ __forceinline__ void bsplit(float2 x, u32& h, u32& l) {
    u32 hh;
    asm("cvt.rn.bf16x2.f32 %0, %1, %2;" : "=r"(hh) : "f"(x.y), "f"(x.x));
    const float r0 = x.x - __uint_as_float(hh << 16);
    const float r1 = x.y - __uint_as_float(hh & 0xffff0000u);
    u32 ll;
    asm("cvt.rn.bf16x2.f32 %0, %1, %2;" : "=r"(ll) : "f"(r1), "f"(r0));
    h = hh; l = ll;
}
__device__ __forceinline__ void store_split(u32* hp, u32* lp, int idx, float2 v) {
    u32 h, l; bsplit(v, h, l); hp[idx] = h; lp[idx] = l;
}
__device__ __forceinline__ void mma4(float d[4], const u32 a[4], u32 b0, u32 b1) {
    asm("mma.sync.aligned.m16n8k16.row.col.f32.bf16.bf16.f32 "
        "{%0,%1,%2,%3}, {%4,%5,%6,%7}, {%8,%9}, {%0,%1,%2,%3};"
        : "+f"(d[0]), "+f"(d[1]), "+f"(d[2]), "+f"(d[3])
        : "r"(a[0]), "r"(a[1]), "r"(a[2]), "r"(a[3]), "r"(b0), "r"(b1));
}
__device__ __forceinline__ void ldm4(u32 r[4], u32 addr) {
    asm volatile("ldmatrix.sync.aligned.m8n8.x4.shared.b16 {%0,%1,%2,%3}, [%4];"
        : "=r"(r[0]), "=r"(r[1]), "=r"(r[2]), "=r"(r[3]) : "r"(addr));
}
__device__ __forceinline__ u32 smem_u32(const void* p) {
    return (u32)__cvta_generic_to_shared(p);
}
__device__ __forceinline__ int amat_off(int lane, int strideB) {
    const int r = lane & 7, m = lane >> 3;
    return (r + ((m & 1) << 3)) * strideB + ((m >> 1) << 4);
}
// prefetch a phase's kc=0 lo-weight fragment (issued before the barrier)
__device__ __forceinline__ u64 pre_blo(const u32* __restrict__ gBlo,
                                       int nt, int NT, int lane) {
    return (nt >= 0 && nt < NT)
        ? *(const u64*)(gBlo + (nt * 32 + lane) * 2) : 0ull;
}

// single-tile GEMM, per-term accumulators, kc=0 lo-weight preloaded.
// Caller guarantees nt < NT.
template<int KC, int NT>
__device__ __forceinline__ void gemm1(
    const u32 aHi, const u32 aLo,
    const u32* __restrict__ sBhi, const u32* __restrict__ gBlo,
    const int nt, const int lane, float D[4], u64 pre)
{
    float Dhh[4] = {0, 0, 0, 0}, Dhl[4] = {0, 0, 0, 0}, Dlh[4] = {0, 0, 0, 0};
    u64 blo = pre;
#pragma unroll
    for (int kc = 0; kc < KC; ++kc) {
        u64 blo_n = 0ull;
        if (kc + 1 < KC)
            blo_n = *(const u64*)(gBlo + (((kc + 1) * NT + nt) * 32 + lane) * 2);
        u32 ah[4], al[4];
        ldm4(ah, aHi + kc * 32);
        ldm4(al, aLo + kc * 32);
        const u64 bh = *(const u64*)(sBhi + ((kc * NT + nt) * 32 + lane) * 2);
        const u32 bh0 = (u32)bh, bh1 = (u32)(bh >> 32);
        mma4(Dhh, ah, bh0, bh1);
        mma4(Dhl, ah, (u32)blo, (u32)(blo >> 32));
        mma4(Dlh, al, bh0, bh1);
        blo = blo_n;
    }
#pragma unroll
    for (int j = 0; j < 4; ++j) D[j] = (Dhh[j] + Dhl[j]) + Dlh[j];
}

// ---------------- prep kernel ----------------

__global__ void prep_kernel(
    const float* __restrict__ Wf1, const float* __restrict__ Wf2,
    const float* __restrict__ Wz1, const float* __restrict__ Wz2,
    const float* __restrict__ Wr1, const float* __restrict__ Wr2,
    const float* __restrict__ Wh1, const float* __restrict__ Wh2)
{
    const int i = blockIdx.x * blockDim.x + threadIdx.x;
    if (i >= W_TOTAL) return;

    int off, NT, Kr, Nr, ld;
    const float *S1 = nullptr, *S2 = nullptr;
    if (i < OFF_F2)        { off = OFF_F1;  NT = 13; Kr = 64;  Nr = 100; S1 = Wf1; ld = 100; }
    else if (i < OFF_ZR1)  { off = OFF_F2;  NT = 8;  Kr = 100; Nr = 64;  S1 = Wf2; ld = 64;  }
    else if (i < OFF_Z2)   { off = OFF_ZR1; NT = 25; Kr = 128; Nr = 200; S1 = Wz1; S2 = Wr1; ld = 100; }
    else if (i < OFF_R2)   { off = OFF_Z2;  NT = 8;  Kr = 100; Nr = 64;  S1 = Wz2; ld = 64;  }
    else if (i < OFF_H1)   { off = OFF_R2;  NT = 8;  Kr = 100; Nr = 64;  S1 = Wr2; ld = 64;  }
    else if (i < OFF_H2)   { off = OFF_H1;  NT = 13; Kr = 128; Nr = 100; S1 = Wh1; ld = 100; }
    else                   { off = OFF_H2;  NT = 8;  Kr = 100; Nr = 64;  S1 = Wh2; ld = 64;  }

    const int idx  = i - off;
    const int r    = idx & 1;
    const int lane = (idx >> 1) & 31;
    const int rest = idx >> 6;
    const int nt   = rest % NT;
    const int kc   = rest / NT;
    const int k0   = kc * 16 + (lane & 3) * 2 + (r ? 8 : 0);
    const int n    = nt * 8 + (lane >> 2);

    float x0 = 0.0f, x1 = 0.0f;
    if (n < Nr) {
        const float* S = S1; int nn = n;
        if (S2 && n >= 100) { S = S2; nn = n - 100; }
        if (k0     < Kr) x0 = S[(size_t)k0 * ld + nn];
        if (k0 + 1 < Kr) x1 = S[(size_t)(k0 + 1) * ld + nn];
    }
    const u32 h0 = bf16_hi_bits(x0), h1 = bf16_hi_bits(x1);
    const float r0 = x0 - __uint_as_float(h0 << 16);
    const float r1 = x1 - __uint_as_float(h1 << 16);
    const u32 l0 = bf16_hi_bits(r0), l1 = bf16_hi_bits(r1);
    g_whi[i] = h0 | (h1 << 16);
    g_wlo[i] = l0 | (l1 << 16);
}

// ---------------- main kernel ----------------

__global__ void __launch_bounds__(512, 1) ode_main(
    const float* __restrict__ data, const float* __restrict__ ts,
    const float* __restrict__ bf1, const float* __restrict__ bf2,
    const float* __restrict__ bz1, const float* __restrict__ bz2,
    const float* __restrict__ br1, const float* __restrict__ br2,
    const float* __restrict__ bh1, const float* __restrict__ bh2,
    float* __restrict__ yi_out, float* __restrict__ lat_out)
{
    __shared__ float sY [16][68];
    __shared__ float sYO[16][68];
    __shared__ float sZ [16][68];
    __shared__ float sbf1[100], sbz1[100], sbr1[100], sbh1[100];
    __shared__ float sbf2[64],  sbz2[64],  sbr2[64],  sbh2[64];
    __shared__ float sts_s[TT];
    extern __shared__ __align__(16) u32 dynW[];

    const int tid  = threadIdx.x;
    const int lane = tid & 31;
    const int w    = tid >> 5;       // 0..15
    const int g    = lane >> 2;
    const int tg   = lane & 3;
    const int rowbase = blockIdx.x * 16;

    u32* const actW = dynW + W_TOTAL;
    u32* const aYh  = actW;
    u32* const aYl  = actW + (B_AYL  >> 2);
    u32* const aCh  = actW + (B_ACH  >> 2);
    u32* const aCl  = actW + (B_ACL  >> 2);
    u32* const aHAh = actW + (B_AHAH >> 2);
    u32* const aHAl = actW + (B_AHAL >> 2);
    u32* const aHzh = actW + (B_AHZH >> 2);
    u32* const aHzl = actW + (B_AHZL >> 2);
    u32* const aHrh = actW + (B_AHRH >> 2);
    u32* const aHrl = actW + (B_AHRL >> 2);

    for (int i = tid; i < 16 * 68; i += 512) (&sY[0][0])[i] = 0.0f;
    for (int i = tid; i < ACT_U32; i += 512) actW[i] = 0u;
    for (int i = tid; i < 100; i += 512) {
        sbf1[i] = bf1[i]; sbz1[i] = bz1[i]; sbr1[i] = br1[i]; sbh1[i] = bh1[i];
    }
    for (int i = tid; i < 64; i += 512) {
        sbf2[i] = bf2[i]; sbz2[i] = bz2[i]; sbr2[i] = br2[i]; sbh2[i] = bh2[i];
    }
    for (int i = tid; i < TT; i += 512) sts_s[i] = ts[i];
    {
        const float4* s = (const float4*)g_whi;
        float4* d = (float4*)dynW;
        for (int i = tid; i < W_TOTAL / 4; i += 512) d[i] = s[i];
    }
    __syncthreads();

    // x for step 0 (data index 1)
    if (tid < 256) {
        const int cr0  = tid >> 4;
        const int cd40 = (tid & 15) * 4;
        const float4 v = *reinterpret_cast<const float4*>(
            data + (((size_t)(rowbase + cr0)) * TT + 1) * 64 + cd40);
        const int ci = cr0 * SC_U32 + 32 + (cd40 >> 1);
        store_split(aCh, aCl, ci,     make_float2(v.x, v.y));
        store_split(aCh, aCl, ci + 1, make_float2(v.z, v.w));
    }
    __syncthreads();

    const u32 base_act = smem_u32(actW);
    const int offY = amat_off(lane, SY_U32 * 4);
    const int offC = amat_off(lane, SC_U32 * 4);
    const int offH = amat_off(lane, SH_U32 * 4);
    const u32 adYh  = base_act + B_AYH  + offY, adYl  = base_act + B_AYL  + offY;
    const u32 adCh  = base_act + B_ACH  + offC, adCl  = base_act + B_ACL  + offC;
    const u32 adHAh = base_act + B_AHAH + offH, adHAl = base_act + B_AHAL + offH;
    const u32 adHzh = base_act + B_AHZH + offH, adHzl = base_act + B_AHZL + offH;
    const u32 adHrh = base_act + B_AHRH + offH, adHrl = base_act + B_AHRL + offH;

    // P3 tile assignment: tile w on all warps; tiles 16-23 on warps 8-15;
    // tile 24 on warp 13 (idle in P1/P6/P7).
    const int p3_nt1 = (w >= 8) ? w + 8 : -1;
    const int p3_nt2 = (w == 13) ? 24 : -1;
    const bool p4_isz = (w < 8);
    const int p4_nt = w & 7;

    // P3 epilogue as a reusable lambda
    auto p3_epi = [&](int nt, const float D[4]) {
        const int c0 = nt * 8 + tg * 2;
        if (c0 < 100) {
            const float2 t0 = tanh2(make_float2(D[0] + sbz1[c0], D[1] + sbz1[c0 + 1]));
            const float2 t1 = tanh2(make_float2(D[2] + sbz1[c0], D[3] + sbz1[c0 + 1]));
            const int ci = c0 >> 1;
            store_split(aHzh, aHzl, g * SH_U32 + ci, t0);
            store_split(aHzh, aHzl, (g + 8) * SH_U32 + ci, t1);
        } else {
            const int c = c0 - 100;
            const float2 t0 = tanh2(make_float2(D[0] + sbr1[c], D[1] + sbr1[c + 1]));
            const float2 t1 = tanh2(make_float2(D[2] + sbr1[c], D[3] + sbr1[c + 1]));
            const int ci = c >> 1;
            store_split(aHrh, aHrl, g * SH_U32 + ci, t0);
            store_split(aHrh, aHrl, (g + 8) * SH_U32 + ci, t1);
        }
    };

    // initial prefetch for P1
    u64 pre1 = pre_blo(g_wlo + OFF_F1, (w < 13) ? w : -1, 13, lane);

    for (int step = 0; step < NSTEPS; ++step) {
        const float dt = (step == 0) ? (sts_s[1] - sts_s[0])
                                     : (sts_s[step - 1] - sts_s[step]);

        // ---- P1: HA = tanh(bf1 + Y @ Wf1)  [K=64, N=100], warps 0-12 ----
        if (w < 13) {
            float D[4];
            gemm1<4, 13>(adYh, adYl, dynW + OFF_F1, g_wlo + OFF_F1, w, lane, D, pre1);
            const int c0 = w * 8 + tg * 2;
            const float2 t0 = tanh2(make_float2(D[0] + sbf1[c0], D[1] + sbf1[c0 + 1]));
            const float2 t1 = tanh2(make_float2(D[2] + sbf1[c0], D[3] + sbf1[c0 + 1]));
            const int ci = c0 >> 1;
            store_split(aHAh, aHAl, g * SH_U32 + ci, t0);
            store_split(aHAh, aHAl, (g + 8) * SH_U32 + ci, t1);
        }
        const u64 pre2 = pre_blo(g_wlo + OFF_F2, (w < 8) ? w : -1, 8, lane);
        __syncthreads();

        // ---- P2: y_ode = Y + dt*(bf2 + HA @ Wf2)  [K=100, N=64], warps 0-7 ----
        if (w < 8) {
            float D[4];
            gemm1<7, 8>(adHAh, adHAl, dynW + OFF_F2, g_wlo + OFF_F2, w, lane, D, pre2);
            const int c0 = w * 8 + tg * 2;
            const float b0 = sbf2[c0], b1 = sbf2[c0 + 1];
            float2 v0, v1;
            v0.x = sY[g][c0]     + dt * (D[0] + b0);
            v0.y = sY[g][c0 + 1] + dt * (D[1] + b1);
            v1.x = sY[g + 8][c0]     + dt * (D[2] + b0);
            v1.y = sY[g + 8][c0 + 1] + dt * (D[3] + b1);
            *(float2*)&sYO[g][c0]     = v0;
            *(float2*)&sYO[g + 8][c0] = v1;
            store_split(aCh, aCl, g * SC_U32 + (c0 >> 1), v0);
            store_split(aCh, aCl, (g + 8) * SC_U32 + (c0 >> 1), v1);
        }
        const u64 pre3a = pre_blo(g_wlo + OFF_ZR1, w, 25, lane);
        const u64 pre3b = pre_blo(g_wlo + OFF_ZR1, p3_nt1, 25, lane);
        const u64 pre3c = pre_blo(g_wlo + OFF_ZR1, p3_nt2, 25, lane);
        __syncthreads();

        // ---- P3: z/r hidden = tanh(b + C @ [Wz1|Wr1])  [K=128, N=200] ----
        {
            float D[4];
            gemm1<8, 25>(adCh, adCl, dynW + OFF_ZR1, g_wlo + OFF_ZR1, w, lane, D, pre3a);
            p3_epi(w, D);
            if (p3_nt1 >= 0) {
                float D1[4];
                gemm1<8, 25>(adCh, adCl, dynW + OFF_ZR1, g_wlo + OFF_ZR1,
                             p3_nt1, lane, D1, pre3b);
                p3_epi(p3_nt1, D1);
            }
            if (p3_nt2 >= 0) {
                float D2[4];
                gemm1<8, 25>(adCh, adCl, dynW + OFF_ZR1, g_wlo + OFF_ZR1,
                             p3_nt2, lane, D2, pre3c);
                p3_epi(p3_nt2, D2);
            }
        }
        const u64 pre4 = pre_blo(g_wlo + (p4_isz ? OFF_Z2 : OFF_R2), p4_nt, 8, lane);
        __syncthreads();

        // ---- P4: z (warps 0-7) / r (warps 8-15)  [K=100, N=64 each] ----
        {
            const u32 aH = p4_isz ? adHzh : adHrh;
            const u32 aL = p4_isz ? adHzl : adHrl;
            const u32* bh = dynW  + (p4_isz ? OFF_Z2 : OFF_R2);
            const u32* bl = g_wlo + (p4_isz ? OFF_Z2 : OFF_R2);
            float D[4];
            gemm1<7, 8>(aH, aL, bh, bl, p4_nt, lane, D, pre4);
            const int c0 = p4_nt * 8 + tg * 2;
            if (p4_isz) {
                const float2 s0 = sigmoid2(make_float2(D[0] + sbz2[c0], D[1] + sbz2[c0 + 1]));
                const float2 s1 = sigmoid2(make_float2(D[2] + sbz2[c0], D[3] + sbz2[c0 + 1]));
                *(float2*)&sZ[g][c0]     = s0;
                *(float2*)&sZ[g + 8][c0] = s1;
            } else {
                const float2 s0 = sigmoid2(make_float2(D[0] + sbr2[c0], D[1] + sbr2[c0 + 1]));
                const float2 s1 = sigmoid2(make_float2(D[2] + sbr2[c0], D[3] + sbr2[c0 + 1]));
                float2 v0, v1;
                v0.x = sYO[g][c0]     * s0.x;
                v0.y = sYO[g][c0 + 1] * s0.y;
                v1.x = sYO[g + 8][c0]     * s1.x;
                v1.y = sYO[g + 8][c0 + 1] * s1.y;
                store_split(aCh, aCl, g * SC_U32 + (c0 >> 1), v0);
                store_split(aCh, aCl, (g + 8) * SC_U32 + (c0 >> 1), v1);
            }
        }
        const u64 pre6 = pre_blo(g_wlo + OFF_H1, (w < 13) ? w : -1, 13, lane);
        __syncthreads();

        // ---- P6: HA = tanh(bh1 + C @ Wh1)  [K=128, N=100], warps 0-12 ----
        if (w < 13) {
            float D[4];
            gemm1<8, 13>(adCh, adCl, dynW + OFF_H1, g_wlo + OFF_H1, w, lane, D, pre6);
            const int c0 = w * 8 + tg * 2;
            const float2 t0 = tanh2(make_float2(D[0] + sbh1[c0], D[1] + sbh1[c0 + 1]));
            const float2 t1 = tanh2(make_float2(D[2] + sbh1[c0], D[3] + sbh1[c0 + 1]));
            const int ci = c0 >> 1;
            store_split(aHAh, aHAl, g * SH_U32 + ci, t0);
            store_split(aHAh, aHAl, (g + 8) * SH_U32 + ci, t1);
        }
        const u64 pre7 = pre_blo(g_wlo + OFF_H2, (w < 8) ? w : -1, 8, lane);
        __syncthreads();

        // ---- P7: h = tanh(bh2 + HA @ Wh2); y = (1-z)h + z*yO, warps 0-7.
        //      Warps 8-15 prefetch x for step+1 into aC[64:128). ----
        if (w < 8) {
            float D[4];
            gemm1<7, 8>(adHAh, adHAl, dynW + OFF_H2, g_wlo + OFF_H2, w, lane, D, pre7);
            const int c0 = w * 8 + tg * 2;
            const float2 h0 = tanh2(make_float2(D[0] + sbh2[c0], D[1] + sbh2[c0 + 1]));
            const float2 h1 = tanh2(make_float2(D[2] + sbh2[c0], D[3] + sbh2[c0 + 1]));
            {
                const float z0 = sZ[g][c0], z1 = sZ[g][c0 + 1];
                float2 v;
                v.x = (1.0f - z0) * h0.x + z0 * sYO[g][c0];
                v.y = (1.0f - z1) * h0.y + z1 * sYO[g][c0 + 1];
                *(float2*)&sY[g][c0] = v;
                store_split(aYh, aYl, g * SY_U32 + (c0 >> 1), v);
            }
            {
                const float z0 = sZ[g + 8][c0], z1 = sZ[g + 8][c0 + 1];
                float2 v;
                v.x = (1.0f - z0) * h1.x + z0 * sYO[g + 8][c0];
                v.y = (1.0f - z1) * h1.y + z1 * sYO[g + 8][c0 + 1];
                *(float2*)&sY[g + 8][c0] = v;
                store_split(aYh, aYl, (g + 8) * SY_U32 + (c0 >> 1), v);
            }
        } else if (step + 2 < TT) {
            const int t2  = tid - 256;
            const int cr2 = t2 >> 4;
            const int cd2 = (t2 & 15) * 4;
            const float4 v = *reinterpret_cast<const float4*>(
                data + (((size_t)(rowbase + cr2)) * TT + (step + 2)) * 64 + cd2);
            const int ci = cr2 * SC_U32 + 32 + (cd2 >> 1);
            store_split(aCh, aCl, ci,     make_float2(v.x, v.y));
            store_split(aCh, aCl, ci + 1, make_float2(v.z, v.w));
        }
        pre1 = pre_blo(g_wlo + OFF_F1, (w < 13) ? w : -1, 13, lane);
        __syncthreads();

        if (lat_out && tid < 256) {
            const int cr0  = tid >> 4;
            const int cd40 = (tid & 15) * 4;
            const float4 v = *reinterpret_cast<const float4*>(&sY[cr0][cd40]);
            *reinterpret_cast<float4*>(
                lat_out + (((size_t)(rowbase + cr0)) * NSTEPS + step) * 64 + cd40) = v;
        }
    }

    if (yi_out && tid < 256) {
        const int cr0  = tid >> 4;
        const int cd40 = (tid & 15) * 4;
        const float4 v = *reinterpret_cast<const float4*>(&sY[cr0][cd40]);
        *reinterpret_cast<float4*>(yi_out + ((size_t)(rowbase + cr0)) * 64 + cd40) = v;
    }
}

extern "C" void kernel_launch(void* const* d_in, const int* in_sizes, int n_in,
                              void* d_out, int out_size)
{
    const float* data = (const float*)d_in[0];
    const float* ts   = (const float*)d_in[1];
    const float* Wf1  = (const float*)d_in[2];
    const float* bf1  = (const float*)d_in[3];
    const float* Wf2  = (const float*)d_in[4];
    const float* bf2  = (const float*)d_in[5];
    const float* Wz1  = (const float*)d_in[6];
    const float* bz1  = (const float*)d_in[7];
    const float* Wz2  = (const float*)d_in[8];
    const float* bz2  = (const float*)d_in[9];
    const float* Wr1  = (const float*)d_in[10];
    const float* br1  = (const float*)d_in[11];
    const float* Wr2  = (const float*)d_in[12];
    const float* br2  = (const float*)d_in[13];
    const float* Wh1  = (const float*)d_in[14];
    const float* bh1  = (const float*)d_in[15];
    const float* Wh2  = (const float*)d_in[16];
    const float* bh2  = (const float*)d_in[17];

    const long long latN = 2048LL * 199 * 64;
    const long long yiN  = 2048LL * 64;
    float* out = (float*)d_out;
    float* yi_out = nullptr;
    float* lat_out = nullptr;
    if ((long long)out_size == latN + yiN) { yi_out = out; lat_out = out + yiN; }
    else if ((long long)out_size == latN)  { lat_out = out; }
    else if ((long long)out_size == yiN)   { yi_out = out; }
    else if ((long long)out_size > latN)   { yi_out = out; lat_out = out + yiN; }
    else                                   { lat_out = out; }

    cudaFuncSetAttribute(ode_main, cudaFuncAttributeMaxDynamicSharedMemorySize,
                         DYN_U32 * 4);

    prep_kernel<<<(W_TOTAL + 255) / 256, 256>>>(Wf1, Wf2, Wz1, Wz2, Wr1, Wr2, Wh1, Wh2);
    ode_main<<<128, 512, DYN_U32 * 4>>>(data, ts, bf1, bf2, bz1, bz2, br1, br2,
                                        bh1, bh2, yi_out, lat_out);
}

// round 15
// speedup vs baseline: 3.0195x; 1.0295x over previous
#include <cuda_runtime.h>
#include <cstdint>

// ODE-RNN fused scan, round 15: R14 + (a) P3 tile 24 moved to warp 0 so every
// warp has <=2 P3 tiles (phase max 24->16 kc), (b) gemm2 with shared A-fragment
// loads for all 2-tile P3 warps (halves P3 ldsm traffic, 6 MMA chains/kc).

typedef unsigned int u32;
typedef unsigned long long u64;

#define NSTEPS 199
#define TT 200

#define OFF_F1   0
#define OFF_F2   3328
#define OFF_ZR1  6912
#define OFF_Z2   19712
#define OFF_R2   23296
#define OFF_H1   26880
#define OFF_H2   33536
#define W_TOTAL  37120

#define SY_U32   36
#define SC_U32   68
#define SH_U32   60
#define AY_SZ    (16*SY_U32)
#define AC_SZ    (16*SC_U32)
#define AH_SZ    (16*SH_U32)
#define ACT_U32  (2*(AY_SZ + AC_SZ + 3*AH_SZ))
#define B_AYH  0
#define B_AYL  2304
#define B_ACH  4608
#define B_ACL  8960
#define B_AHAH 13312
#define B_AHAL 17152
#define B_AHZH 20992
#define B_AHZL 24832
#define B_AHRH 28672
#define B_AHRL 32512

#define DYN_U32 (W_TOTAL + ACT_U32)

__device__ __align__(16) u32 g_whi[W_TOTAL];
__device__ __align__(16) u32 g_wlo[W_TOTAL];

// ---------------- helpers ----------------

__device__ __forceinline__ u32 bf16_hi_bits(float x) {
    const u32 u = __float_as_uint(x);
    return (u + 0x7fffu + ((u >> 16) & 1u)) >> 16;
}
__device__ __forceinline__ float2 tanh2(float2 x) {
    const float e0 = __expf(2.0f * fminf(fmaxf(x.x, -30.0f), 30.0f));
    const float e1 = __expf(2.0f * fminf(fmaxf(x.y, -30.0f), 30.0f));
    const float a0 = e0 + 1.0f, a1 = e1 + 1.0f;
    const float d = __fdividef(2.0f, a0 * a1);
    return make_float2(1.0f - d * a1, 1.0f - d * a0);
}
__device__ __forceinline__ float2 sigmoid2(float2 x) {
    const float e0 = __expf(-fminf(fmaxf(x.x, -30.0f), 30.0f));
    const float e1 = __expf(-fminf(fmaxf(x.y, -30.0f), 30.0f));
    const float a0 = 1.0f + e0, a1 = 1.0f + e1;
    const float d = __fdividef(1.0f, a0 * a1);
    return make_float2(d * a1, d * a0);
}
__device__ __forceinline__ void bsplit(float2 x, u32& h, u32& l) {
    u32 hh;
    asm("cvt.rn.bf16x2.f32 %0, %1, %2;" : "=r"(hh) : "f"(x.y), "f"(x.x));
    const float r0 = x.x - __uint_as_float(hh << 16);
    const float r1 = x.y - __uint_as_float(hh & 0xffff0000u);
    u32 ll;
    asm("cvt.rn.bf16x2.f32 %0, %1, %2;" : "=r"(ll) : "f"(r1), "f"(r0));
    h = hh; l = ll;
}
__device__ __forceinline__ void store_split(u32* hp, u32* lp, int idx, float2 v) {
    u32 h, l; bsplit(v, h, l); hp[idx] = h; lp[idx] = l;
}
__device__ __forceinline__ void mma4(float d[4], const u32 a[4], u32 b0, u32 b1) {
    asm("mma.sync.aligned.m16n8k16.row.col.f32.bf16.bf16.f32 "
        "{%0,%1,%2,%3}, {%4,%5,%6,%7}, {%8,%9}, {%0,%1,%2,%3};"
        : "+f"(d[0]), "+f"(d[1]), "+f"(d[2]), "+f"(d[3])
        : "r"(a[0]), "r"(a[1]), "r"(a[2]), "r"(a[3]), "r"(b0), "r"(b1));
}
__device__ __forceinline__ void ldm4(u32 r[4], u32 addr) {
    asm volatile("ldmatrix.sync.aligned.m8n8.x4.shared.b16 {%0,%1,%2,%3}, [%4];"
        : "=r"(r[0]), "=r"(r[1]), "=r"(r[2]), "=r"(r[3]) : "r"(addr));
}
__device__ __forceinline__ u32 smem_u32(const void* p) {
    return (u32)__cvta_generic_to_shared(p);
}
__device__ __forceinline__ int amat_off(int lane, int strideB) {
    const int r = lane & 7, m = lane >> 3;
    return (r + ((m & 1) << 3)) * strideB + ((m >> 1) << 4);
}
__device__ __forceinline__ u64 pre_blo(const u32* __restrict__ gBlo,
                                       int nt, int NT, int lane) {
    return (nt >= 0 && nt < NT)
        ? *(const u64*)(gBlo + (nt * 32 + lane) * 2) : 0ull;
}

// single-tile GEMM, per-term accumulators, kc=0 lo preloaded.
template<int KC, int NT>
__device__ __forceinline__ void gemm1(
    const u32 aHi, const u32 aLo,
    const u32* __restrict__ sBhi, const u32* __restrict__ gBlo,
    const int nt, const int lane, float D[4], u64 pre)
{
    float Dhh[4] = {0, 0, 0, 0}, Dhl[4] = {0, 0, 0, 0}, Dlh[4] = {0, 0, 0, 0};
    u64 blo = pre;
#pragma unroll
    for (int kc = 0; kc < KC; ++kc) {
        u64 blo_n = 0ull;
        if (kc + 1 < KC)
            blo_n = *(const u64*)(gBlo + (((kc + 1) * NT + nt) * 32 + lane) * 2);
        u32 ah[4], al[4];
        ldm4(ah, aHi + kc * 32);
        ldm4(al, aLo + kc * 32);
        const u64 bh = *(const u64*)(sBhi + ((kc * NT + nt) * 32 + lane) * 2);
        mma4(Dhh, ah, (u32)bh, (u32)(bh >> 32));
        mma4(Dhl, ah, (u32)blo, (u32)(blo >> 32));
        mma4(Dlh, al, (u32)bh, (u32)(bh >> 32));
        blo = blo_n;
    }
#pragma unroll
    for (int j = 0; j < 4; ++j) D[j] = (Dhh[j] + Dhl[j]) + Dlh[j];
}

// two-tile GEMM sharing the A-fragment loads (one ldsm pair per kc).
template<int KC, int NT>
__device__ __forceinline__ void gemm2(
    const u32 aHi, const u32 aLo,
    const u32* __restrict__ sBhi, const u32* __restrict__ gBlo,
    const int nt0, const int nt1, const int lane,
    float D0[4], float D1[4], u64 pre0, u64 pre1)
{
    float Ahh[4] = {0,0,0,0}, Ahl[4] = {0,0,0,0}, Alh[4] = {0,0,0,0};
    float Bhh[4] = {0,0,0,0}, Bhl[4] = {0,0,0,0}, Blh[4] = {0,0,0,0};
    u64 blo0 = pre0, blo1 = pre1;
#pragma unroll
    for (int kc = 0; kc < KC; ++kc) {
        u64 blo0_n = 0ull, blo1_n = 0ull;
        if (kc + 1 < KC) {
            blo0_n = *(const u64*)(gBlo + (((kc + 1) * NT + nt0) * 32 + lane) * 2);
            blo1_n = *(const u64*)(gBlo + (((kc + 1) * NT + nt1) * 32 + lane) * 2);
        }
        u32 ah[4], al[4];
        ldm4(ah, aHi + kc * 32);
        ldm4(al, aLo + kc * 32);
        const u64 bh0 = *(const u64*)(sBhi + ((kc * NT + nt0) * 32 + lane) * 2);
        const u64 bh1 = *(const u64*)(sBhi + ((kc * NT + nt1) * 32 + lane) * 2);
        mma4(Ahh, ah, (u32)bh0, (u32)(bh0 >> 32));
        mma4(Bhh, ah, (u32)bh1, (u32)(bh1 >> 32));
        mma4(Ahl, ah, (u32)blo0, (u32)(blo0 >> 32));
        mma4(Bhl, ah, (u32)blo1, (u32)(blo1 >> 32));
        mma4(Alh, al, (u32)bh0, (u32)(bh0 >> 32));
        mma4(Blh, al, (u32)bh1, (u32)(bh1 >> 32));
        blo0 = blo0_n; blo1 = blo1_n;
    }
#pragma unroll
    for (int j = 0; j < 4; ++j) {
        D0[j] = (Ahh[j] + Ahl[j]) + Alh[j];
        D1[j] = (Bhh[j] + Bhl[j]) + Blh[j];
    }
}

// ---------------- prep kernel ----------------

__global__ void prep_kernel(
    const float* __restrict__ Wf1, const float* __restrict__ Wf2,
    const float* __restrict__ Wz1, const float* __restrict__ Wz2,
    const float* __restrict__ Wr1, const float* __restrict__ Wr2,
    const float* __restrict__ Wh1, const float* __restrict__ Wh2)
{
    const int i = blockIdx.x * blockDim.x + threadIdx.x;
    if (i >= W_TOTAL) return;

    int off, NT, Kr, Nr, ld;
    const float *S1 = nullptr, *S2 = nullptr;
    if (i < OFF_F2)        { off = OFF_F1;  NT = 13; Kr = 64;  Nr = 100; S1 = Wf1; ld = 100; }
    else if (i < OFF_ZR1)  { off = OFF_F2;  NT = 8;  Kr = 100; Nr = 64;  S1 = Wf2; ld = 64;  }
    else if (i < OFF_Z2)   { off = OFF_ZR1; NT = 25; Kr = 128; Nr = 200; S1 = Wz1; S2 = Wr1; ld = 100; }
    else if (i < OFF_R2)   { off = OFF_Z2;  NT = 8;  Kr = 100; Nr = 64;  S1 = Wz2; ld = 64;  }
    else if (i < OFF_H1)   { off = OFF_R2;  NT = 8;  Kr = 100; Nr = 64;  S1 = Wr2; ld = 64;  }
    else if (i < OFF_H2)   { off = OFF_H1;  NT = 13; Kr = 128; Nr = 100; S1 = Wh1; ld = 100; }
    else                   { off = OFF_H2;  NT = 8;  Kr = 100; Nr = 64;  S1 = Wh2; ld = 64;  }

    const int idx  = i - off;
    const int r    = idx & 1;
    const int lane = (idx >> 1) & 31;
    const int rest = idx >> 6;
    const int nt   = rest % NT;
    const int kc   = rest / NT;
    const int k0   = kc * 16 + (lane & 3) * 2 + (r ? 8 : 0);
    const int n    = nt * 8 + (lane >> 2);

    float x0 = 0.0f, x1 = 0.0f;
    if (n < Nr) {
        const float* S = S1; int nn = n;
        if (S2 && n >= 100) { S = S2; nn = n - 100; }
        if (k0     < Kr) x0 = S[(size_t)k0 * ld + nn];
        if (k0 + 1 < Kr) x1 = S[(size_t)(k0 + 1) * ld + nn];
    }
    const u32 h0 = bf16_hi_bits(x0), h1 = bf16_hi_bits(x1);
    const float r0 = x0 - __uint_as_float(h0 << 16);
    const float r1 = x1 - __uint_as_float(h1 << 16);
    const u32 l0 = bf16_hi_bits(r0), l1 = bf16_hi_bits(r1);
    g_whi[i] = h0 | (h1 << 16);
    g_wlo[i] = l0 | (l1 << 16);
}

// ---------------- main kernel ----------------

__global__ void __launch_bounds__(512, 1) ode_main(
    const float* __restrict__ data, const float* __restrict__ ts,
    const float* __restrict__ bf1, const float* __restrict__ bf2,
    const float* __restrict__ bz1, const float* __restrict__ bz2,
    const float* __restrict__ br1, const float* __restrict__ br2,
    const float* __restrict__ bh1, const float* __restrict__ bh2,
    float* __restrict__ yi_out, float* __restrict__ lat_out)
{
    __shared__ float sY [16][68];
    __shared__ float sYO[16][68];
    __shared__ float sZ [16][68];
    __shared__ float sbf1[100], sbz1[100], sbr1[100], sbh1[100];
    __shared__ float sbf2[64],  sbz2[64],  sbr2[64],  sbh2[64];
    __shared__ float sts_s[TT];
    extern __shared__ __align__(16) u32 dynW[];

    const int tid  = threadIdx.x;
    const int lane = tid & 31;
    const int w    = tid >> 5;       // 0..15
    const int g    = lane >> 2;
    const int tg   = lane & 3;
    const int rowbase = blockIdx.x * 16;

    u32* const actW = dynW + W_TOTAL;
    u32* const aYh  = actW;
    u32* const aYl  = actW + (B_AYL  >> 2);
    u32* const aCh  = actW + (B_ACH  >> 2);
    u32* const aCl  = actW + (B_ACL  >> 2);
    u32* const aHAh = actW + (B_AHAH >> 2);
    u32* const aHAl = actW + (B_AHAL >> 2);
    u32* const aHzh = actW + (B_AHZH >> 2);
    u32* const aHzl = actW + (B_AHZL >> 2);
    u32* const aHrh = actW + (B_AHRH >> 2);
    u32* const aHrl = actW + (B_AHRL >> 2);

    for (int i = tid; i < 16 * 68; i += 512) (&sY[0][0])[i] = 0.0f;
    for (int i = tid; i < ACT_U32; i += 512) actW[i] = 0u;
    for (int i = tid; i < 100; i += 512) {
        sbf1[i] = bf1[i]; sbz1[i] = bz1[i]; sbr1[i] = br1[i]; sbh1[i] = bh1[i];
    }
    for (int i = tid; i < 64; i += 512) {
        sbf2[i] = bf2[i]; sbz2[i] = bz2[i]; sbr2[i] = br2[i]; sbh2[i] = bh2[i];
    }
    for (int i = tid; i < TT; i += 512) sts_s[i] = ts[i];
    {
        const float4* s = (const float4*)g_whi;
        float4* d = (float4*)dynW;
        for (int i = tid; i < W_TOTAL / 4; i += 512) d[i] = s[i];
    }
    __syncthreads();

    if (tid < 256) {
        const int cr0  = tid >> 4;
        const int cd40 = (tid & 15) * 4;
        const float4 v = *reinterpret_cast<const float4*>(
            data + (((size_t)(rowbase + cr0)) * TT + 1) * 64 + cd40);
        const int ci = cr0 * SC_U32 + 32 + (cd40 >> 1);
        store_split(aCh, aCl, ci,     make_float2(v.x, v.y));
        store_split(aCh, aCl, ci + 1, make_float2(v.z, v.w));
    }
    __syncthreads();

    const u32 base_act = smem_u32(actW);
    const int offY = amat_off(lane, SY_U32 * 4);
    const int offC = amat_off(lane, SC_U32 * 4);
    const int offH = amat_off(lane, SH_U32 * 4);
    const u32 adYh  = base_act + B_AYH  + offY, adYl  = base_act + B_AYL  + offY;
    const u32 adCh  = base_act + B_ACH  + offC, adCl  = base_act + B_ACL  + offC;
    const u32 adHAh = base_act + B_AHAH + offH, adHAl = base_act + B_AHAL + offH;
    const u32 adHzh = base_act + B_AHZH + offH, adHzl = base_act + B_AHZL + offH;
    const u32 adHrh = base_act + B_AHRH + offH, adHrl = base_act + B_AHRL + offH;

    // P3 tile assignment: every warp owns tile w; second tiles:
    // warp 0 -> 24, warps 8-15 -> w+8. Warps 1-7: single tile.
    const int p3_nt1 = (w == 0) ? 24 : ((w >= 8) ? w + 8 : -1);
    const bool p4_isz = (w < 8);
    const int p4_nt = w & 7;

    auto p3_epi = [&](int nt, const float D[4]) {
        const int c0 = nt * 8 + tg * 2;
        if (c0 < 100) {
            const float2 t0 = tanh2(make_float2(D[0] + sbz1[c0], D[1] + sbz1[c0 + 1]));
            const float2 t1 = tanh2(make_float2(D[2] + sbz1[c0], D[3] + sbz1[c0 + 1]));
            const int ci = c0 >> 1;
            store_split(aHzh, aHzl, g * SH_U32 + ci, t0);
            store_split(aHzh, aHzl, (g + 8) * SH_U32 + ci, t1);
        } else {
            const int c = c0 - 100;
            const float2 t0 = tanh2(make_float2(D[0] + sbr1[c], D[1] + sbr1[c + 1]));
            const float2 t1 = tanh2(make_float2(D[2] + sbr1[c], D[3] + sbr1[c + 1]));
            const int ci = c >> 1;
            store_split(aHrh, aHrl, g * SH_U32 + ci, t0);
            store_split(aHrh, aHrl, (g + 8) * SH_U32 + ci, t1);
        }
    };

    u64 pre1 = pre_blo(g_wlo + OFF_F1, (w < 13) ? w : -1, 13, lane);

    for (int step = 0; step < NSTEPS; ++step) {
        const float dt = (step == 0) ? (sts_s[1] - sts_s[0])
                                     : (sts_s[step - 1] - sts_s[step]);

        // ---- P1: HA = tanh(bf1 + Y @ Wf1)  [K=64, N=100], warps 0-12 ----
        if (w < 13) {
            float D[4];
            gemm1<4, 13>(adYh, adYl, dynW + OFF_F1, g_wlo + OFF_F1, w, lane, D, pre1);
            const int c0 = w * 8 + tg * 2;
            const float2 t0 = tanh2(make_float2(D[0] + sbf1[c0], D[1] + sbf1[c0 + 1]));
            const float2 t1 = tanh2(make_float2(D[2] + sbf1[c0], D[3] + sbf1[c0 + 1]));
            const int ci = c0 >> 1;
            store_split(aHAh, aHAl, g * SH_U32 + ci, t0);
            store_split(aHAh, aHAl, (g + 8) * SH_U32 + ci, t1);
        }
        const u64 pre2 = pre_blo(g_wlo + OFF_F2, (w < 8) ? w : -1, 8, lane);
        __syncthreads();

        // ---- P2: y_ode = Y + dt*(bf2 + HA @ Wf2)  [K=100, N=64], warps 0-7 ----
        if (w < 8) {
            float D[4];
            gemm1<7, 8>(adHAh, adHAl, dynW + OFF_F2, g_wlo + OFF_F2, w, lane, D, pre2);
            const int c0 = w * 8 + tg * 2;
            const float b0 = sbf2[c0], b1 = sbf2[c0 + 1];
            float2 v0, v1;
            v0.x = sY[g][c0]     + dt * (D[0] + b0);
            v0.y = sY[g][c0 + 1] + dt * (D[1] + b1);
            v1.x = sY[g + 8][c0]     + dt * (D[2] + b0);
            v1.y = sY[g + 8][c0 + 1] + dt * (D[3] + b1);
            *(float2*)&sYO[g][c0]     = v0;
            *(float2*)&sYO[g + 8][c0] = v1;
            store_split(aCh, aCl, g * SC_U32 + (c0 >> 1), v0);
            store_split(aCh, aCl, (g + 8) * SC_U32 + (c0 >> 1), v1);
        }
        const u64 pre3a = pre_blo(g_wlo + OFF_ZR1, w, 25, lane);
        const u64 pre3b = pre_blo(g_wlo + OFF_ZR1, p3_nt1, 25, lane);
        __syncthreads();

        // ---- P3: z/r hidden = tanh(b + C @ [Wz1|Wr1])  [K=128, N=200] ----
        if (p3_nt1 >= 0) {
            float D0[4], D1[4];
            gemm2<8, 25>(adCh, adCl, dynW + OFF_ZR1, g_wlo + OFF_ZR1,
                         w, p3_nt1, lane, D0, D1, pre3a, pre3b);
            p3_epi(w, D0);
            p3_epi(p3_nt1, D1);
        } else {
            float D[4];
            gemm1<8, 25>(adCh, adCl, dynW + OFF_ZR1, g_wlo + OFF_ZR1, w, lane, D, pre3a);
            p3_epi(w, D);
        }
        const u64 pre4 = pre_blo(g_wlo + (p4_isz ? OFF_Z2 : OFF_R2), p4_nt, 8, lane);
        __syncthreads();

        // ---- P4: z (warps 0-7) / r (warps 8-15)  [K=100, N=64 each] ----
        {
            const u32 aH = p4_isz ? adHzh : adHrh;
            const u32 aL = p4_isz ? adHzl : adHrl;
            const u32* bh = dynW  + (p4_isz ? OFF_Z2 : OFF_R2);
            const u32* bl = g_wlo + (p4_isz ? OFF_Z2 : OFF_R2);
            float D[4];
            gemm1<7, 8>(aH, aL, bh, bl, p4_nt, lane, D, pre4);
            const int c0 = p4_nt * 8 + tg * 2;
            if (p4_isz) {
                const float2 s0 = sigmoid2(make_float2(D[0] + sbz2[c0], D[1] + sbz2[c0 + 1]));
                const float2 s1 = sigmoid2(make_float2(D[2] + sbz2[c0], D[3] + sbz2[c0 + 1]));
                *(float2*)&sZ[g][c0]     = s0;
                *(float2*)&sZ[g + 8][c0] = s1;
            } else {
                const float2 s0 = sigmoid2(make_float2(D[0] + sbr2[c0], D[1] + sbr2[c0 + 1]));
                const float2 s1 = sigmoid2(make_float2(D[2] + sbr2[c0], D[3] + sbr2[c0 + 1]));
                float2 v0, v1;
                v0.x = sYO[g][c0]     * s0.x;
                v0.y = sYO[g][c0 + 1] * s0.y;
                v1.x = sYO[g + 8][c0]     * s1.x;
                v1.y = sYO[g + 8][c0 + 1] * s1.y;
                store_split(aCh, aCl, g * SC_U32 + (c0 >> 1), v0);
                store_split(aCh, aCl, (g + 8) * SC_U32 + (c0 >> 1), v1);
            }
        }
        const u64 pre6 = pre_blo(g_wlo + OFF_H1, (w < 13) ? w : -1, 13, lane);
        __syncthreads();

        // ---- P6: HA = tanh(bh1 + C @ Wh1)  [K=128, N=100], warps 0-12 ----
        if (w < 13) {
            float D[4];
            gemm1<8, 13>(adCh, adCl, dynW + OFF_H1, g_wlo + OFF_H1, w, lane, D, pre6);
            const int c0 = w * 8 + tg * 2;
            const float2 t0 = tanh2(make_float2(D[0] + sbh1[c0], D[1] + sbh1[c0 + 1]));
            const float2 t1 = tanh2(make_float2(D[2] + sbh1[c0], D[3] + sbh1[c0 + 1]));
            const int ci = c0 >> 1;
            store_split(aHAh, aHAl, g * SH_U32 + ci, t0);
            store_split(aHAh, aHAl, (g + 8) * SH_U32 + ci, t1);
        }
        const u64 pre7 = pre_blo(g_wlo + OFF_H2, (w < 8) ? w : -1, 8, lane);
        __syncthreads();

        // ---- P7: h = tanh(bh2 + HA @ Wh2); y = (1-z)h + z*yO, warps 0-7.
        //      Warps 8-15 prefetch x for step+1. ----
        if (w < 8) {
            float D[4];
            gemm1<7, 8>(adHAh, adHAl, dynW + OFF_H2, g_wlo + OFF_H2, w, lane, D, pre7);
            const int c0 = w * 8 + tg * 2;
            const float2 h0 = tanh2(make_float2(D[0] + sbh2[c0], D[1] + sbh2[c0 + 1]));
            const float2 h1 = tanh2(make_float2(D[2] + sbh2[c0], D[3] + sbh2[c0 + 1]));
            {
                const float z0 = sZ[g][c0], z1 = sZ[g][c0 + 1];
                float2 v;
                v.x = (1.0f - z0) * h0.x + z0 * sYO[g][c0];
                v.y = (1.0f - z1) * h0.y + z1 * sYO[g][c0 + 1];
                *(float2*)&sY[g][c0] = v;
                store_split(aYh, aYl, g * SY_U32 + (c0 >> 1), v);
            }
            {
                const float z0 = sZ[g + 8][c0], z1 = sZ[g + 8][c0 + 1];
                float2 v;
                v.x = (1.0f - z0) * h1.x + z0 * sYO[g + 8][c0];
                v.y = (1.0f - z1) * h1.y + z1 * sYO[g + 8][c0 + 1];
                *(float2*)&sY[g + 8][c0] = v;
                store_split(aYh, aYl, (g + 8) * SY_U32 + (c0 >> 1), v);
            }
        } else if (step + 2 < TT) {
            const int t2  = tid - 256;
            const int cr2 = t2 >> 4;
            const int cd2 = (t2 & 15) * 4;
            const float4 v = *reinterpret_cast<const float4*>(
                data + (((size_t)(rowbase + cr2)) * TT + (step + 2)) * 64 + cd2);
            const int ci = cr2 * SC_U32 + 32 + (cd2 >> 1);
            store_split(aCh, aCl, ci,     make_float2(v.x, v.y));
            store_split(aCh, aCl, ci + 1, make_float2(v.z, v.w));
        }
        pre1 = pre_blo(g_wlo + OFF_F1, (w < 13) ? w : -1, 13, lane);
        __syncthreads();

        if (lat_out && tid < 256) {
            const int cr0  = tid >> 4;
            const int cd40 = (tid & 15) * 4;
            const float4 v = *reinterpret_cast<const float4*>(&sY[cr0][cd40]);
            *reinterpret_cast<float4*>(
                lat_out + (((size_t)(rowbase + cr0)) * NSTEPS + step) * 64 + cd40) = v;
        }
    }

    if (yi_out && tid < 256) {
        const int cr0  = tid >> 4;
        const int cd40 = (tid & 15) * 4;
        const float4 v = *reinterpret_cast<const float4*>(&sY[cr0][cd40]);
        *reinterpret_cast<float4*>(yi_out + ((size_t)(rowbase + cr0)) * 64 + cd40) = v;
    }
}

extern "C" void kernel_launch(void* const* d_in, const int* in_sizes, int n_in,
                              void* d_out, int out_size)
{
    const float* data = (const float*)d_in[0];
    const float* ts   = (const float*)d_in[1];
    const float* Wf1  = (const float*)d_in[2];
    const float* bf1  = (const float*)d_in[3];
    const float* Wf2  = (const float*)d_in[4];
    const float* bf2  = (const float*)d_in[5];
    const float* Wz1  = (const float*)d_in[6];
    const float* bz1  = (const float*)d_in[7];
    const float* Wz2  = (const float*)d_in[8];
    const float* bz2  = (const float*)d_in[9];
    const float* Wr1  = (const float*)d_in[10];
    const float* br1  = (const float*)d_in[11];
    const float* Wr2  = (const float*)d_in[12];
    const float* br2  = (const float*)d_in[13];
    const float* Wh1  = (const float*)d_in[14];
    const float* bh1  = (const float*)d_in[15];
    const float* Wh2  = (const float*)d_in[16];
    const float* bh2  = (const float*)d_in[17];

    const long long latN = 2048LL * 199 * 64;
    const long long yiN  = 2048LL * 64;
    float* out = (float*)d_out;
    float* yi_out = nullptr;
    float* lat_out = nullptr;
    if ((long long)out_size == latN + yiN) { yi_out = out; lat_out = out + yiN; }
    else if ((long long)out_size == latN)  { lat_out = out; }
    else if ((long long)out_size == yiN)   { yi_out = out; }
    else if ((long long)out_size > latN)   { yi_out = out; lat_out = out + yiN; }
    else                                   { lat_out = out; }

    cudaFuncSetAttribute(ode_main, cudaFuncAttributeMaxDynamicSharedMemorySize,
                         DYN_U32 * 4);

    prep_kernel<<<(W_TOTAL + 255) / 256, 256>>>(Wf1, Wf2, Wz1, Wz2, Wr1, Wr2, Wh1, Wh2);
    ode_main<<<128, 512, DYN_U32 * 4>>>(data, ts, bf1, bf2, bz1, bz2, br1, br2,
                                        bh1, bh2, yi_out, lat_out);
}

// round 16
// speedup vs baseline: 3.1424x; 1.0407x over previous
#include <cuda_runtime.h>
#include <cstdint>

// ODE-RNN fused scan, round 16: R15 + P3 K-split across barriers.
// P3's x-half (kc 4-7, reads only aC cols 64-127 which are final from step
// start) is precomputed during the P1/P2 windows by otherwise-idle warps;
// partials staged in SMEM (sXP). P3 window drops from 16 to 8 kc max.

typedef unsigned int u32;
typedef unsigned long long u64;

#define NSTEPS 199
#define TT 200

#define OFF_F1   0
#define OFF_F2   3328
#define OFF_ZR1  6912
#define OFF_Z2   19712
#define OFF_R2   23296
#define OFF_H1   26880
#define OFF_H2   33536
#define W_TOTAL  37120

#define SY_U32   36
#define SC_U32   68
#define SH_U32   60
#define AY_SZ    (16*SY_U32)
#define AC_SZ    (16*SC_U32)
#define AH_SZ    (16*SH_U32)
#define ACT_U32  (2*(AY_SZ + AC_SZ + 3*AH_SZ))
#define B_AYH  0
#define B_AYL  2304
#define B_ACH  4608
#define B_ACL  8960
#define B_AHAH 13312
#define B_AHAL 17152
#define B_AHZH 20992
#define B_AHZL 24832
#define B_AHRH 28672
#define B_AHRL 32512

#define DYN_U32 (W_TOTAL + ACT_U32)

__device__ __align__(16) u32 g_whi[W_TOTAL];
__device__ __align__(16) u32 g_wlo[W_TOTAL];

// ---------------- helpers ----------------

__device__ __forceinline__ u32 bf16_hi_bits(float x) {
    const u32 u = __float_as_uint(x);
    return (u + 0x7fffu + ((u >> 16) & 1u)) >> 16;
}
__device__ __forceinline__ float2 tanh2(float2 x) {
    const float e0 = __expf(2.0f * fminf(fmaxf(x.x, -30.0f), 30.0f));
    const float e1 = __expf(2.0f * fminf(fmaxf(x.y, -30.0f), 30.0f));
    const float a0 = e0 + 1.0f, a1 = e1 + 1.0f;
    const float d = __fdividef(2.0f, a0 * a1);
    return make_float2(1.0f - d * a1, 1.0f - d * a0);
}
__device__ __forceinline__ float2 sigmoid2(float2 x) {
    const float e0 = __expf(-fminf(fmaxf(x.x, -30.0f), 30.0f));
    const float e1 = __expf(-fminf(fmaxf(x.y, -30.0f), 30.0f));
    const float a0 = 1.0f + e0, a1 = 1.0f + e1;
    const float d = __fdividef(1.0f, a0 * a1);
    return make_float2(d * a1, d * a0);
}
__device__ __forceinline__ void bsplit(float2 x, u32& h, u32& l) {
    u32 hh;
    asm("cvt.rn.bf16x2.f32 %0, %1, %2;" : "=r"(hh) : "f"(x.y), "f"(x.x));
    const float r0 = x.x - __uint_as_float(hh << 16);
    const float r1 = x.y - __uint_as_float(hh & 0xffff0000u);
    u32 ll;
    asm("cvt.rn.bf16x2.f32 %0, %1, %2;" : "=r"(ll) : "f"(r1), "f"(r0));
    h = hh; l = ll;
}
__device__ __forceinline__ void store_split(u32* hp, u32* lp, int idx, float2 v) {
    u32 h, l; bsplit(v, h, l); hp[idx] = h; lp[idx] = l;
}
__device__ __forceinline__ void mma4(float d[4], const u32 a[4], u32 b0, u32 b1) {
    asm("mma.sync.aligned.m16n8k16.row.col.f32.bf16.bf16.f32 "
        "{%0,%1,%2,%3}, {%4,%5,%6,%7}, {%8,%9}, {%0,%1,%2,%3};"
        : "+f"(d[0]), "+f"(d[1]), "+f"(d[2]), "+f"(d[3])
        : "r"(a[0]), "r"(a[1]), "r"(a[2]), "r"(a[3]), "r"(b0), "r"(b1));
}
__device__ __forceinline__ void ldm4(u32 r[4], u32 addr) {
    asm volatile("ldmatrix.sync.aligned.m8n8.x4.shared.b16 {%0,%1,%2,%3}, [%4];"
        : "=r"(r[0]), "=r"(r[1]), "=r"(r[2]), "=r"(r[3]) : "r"(addr));
}
__device__ __forceinline__ u32 smem_u32(const void* p) {
    return (u32)__cvta_generic_to_shared(p);
}
__device__ __forceinline__ int amat_off(int lane, int strideB) {
    const int r = lane & 7, m = lane >> 3;
    return (r + ((m & 1) << 3)) * strideB + ((m >> 1) << 4);
}
// lo-weight fragment at (kc, nt)
__device__ __forceinline__ u64 pre_blo_k(const u32* __restrict__ gBlo,
                                         int kc, int nt, int NT, int lane) {
    return (nt >= 0)
        ? *(const u64*)(gBlo + ((kc * NT + nt) * 32 + lane) * 2) : 0ull;
}

// partial GEMM over kc in [KC0,KC1); optional fp32 init added at the end.
template<int KC0, int KC1, int NT>
__device__ __forceinline__ void gemm_part(
    const u32 aHi, const u32 aLo,
    const u32* __restrict__ sBhi, const u32* __restrict__ gBlo,
    const int nt, const int lane, float D[4], u64 pre, const float4* init)
{
    float Dhh[4] = {0,0,0,0}, Dhl[4] = {0,0,0,0}, Dlh[4] = {0,0,0,0};
    u64 blo = pre;
#pragma unroll
    for (int kc = KC0; kc < KC1; ++kc) {
        u64 blo_n = 0ull;
        if (kc + 1 < KC1)
            blo_n = *(const u64*)(gBlo + (((kc + 1) * NT + nt) * 32 + lane) * 2);
        u32 ah[4], al[4];
        ldm4(ah, aHi + kc * 32);
        ldm4(al, aLo + kc * 32);
        const u64 bh = *(const u64*)(sBhi + ((kc * NT + nt) * 32 + lane) * 2);
        mma4(Dhh, ah, (u32)bh, (u32)(bh >> 32));
        mma4(Dhl, ah, (u32)blo, (u32)(blo >> 32));
        mma4(Dlh, al, (u32)bh, (u32)(bh >> 32));
        blo = blo_n;
    }
    float4 iv = init ? *init : make_float4(0.f, 0.f, 0.f, 0.f);
    D[0] = ((Dhh[0] + Dhl[0]) + Dlh[0]) + iv.x;
    D[1] = ((Dhh[1] + Dhl[1]) + Dlh[1]) + iv.y;
    D[2] = ((Dhh[2] + Dhl[2]) + Dlh[2]) + iv.z;
    D[3] = ((Dhh[3] + Dhl[3]) + Dlh[3]) + iv.w;
}

// two-tile partial GEMM sharing A loads; optional inits.
template<int KC0, int KC1, int NT>
__device__ __forceinline__ void gemm2_part(
    const u32 aHi, const u32 aLo,
    const u32* __restrict__ sBhi, const u32* __restrict__ gBlo,
    const int nt0, const int nt1, const int lane,
    float D0[4], float D1[4], u64 pre0, u64 pre1,
    const float4* init0, const float4* init1)
{
    float Ahh[4] = {0,0,0,0}, Ahl[4] = {0,0,0,0}, Alh[4] = {0,0,0,0};
    float Bhh[4] = {0,0,0,0}, Bhl[4] = {0,0,0,0}, Blh[4] = {0,0,0,0};
    u64 blo0 = pre0, blo1 = pre1;
#pragma unroll
    for (int kc = KC0; kc < KC1; ++kc) {
        u64 blo0_n = 0ull, blo1_n = 0ull;
        if (kc + 1 < KC1) {
            blo0_n = *(const u64*)(gBlo + (((kc + 1) * NT + nt0) * 32 + lane) * 2);
            blo1_n = *(const u64*)(gBlo + (((kc + 1) * NT + nt1) * 32 + lane) * 2);
        }
        u32 ah[4], al[4];
        ldm4(ah, aHi + kc * 32);
        ldm4(al, aLo + kc * 32);
        const u64 bh0 = *(const u64*)(sBhi + ((kc * NT + nt0) * 32 + lane) * 2);
        const u64 bh1 = *(const u64*)(sBhi + ((kc * NT + nt1) * 32 + lane) * 2);
        mma4(Ahh, ah, (u32)bh0, (u32)(bh0 >> 32));
        mma4(Bhh, ah, (u32)bh1, (u32)(bh1 >> 32));
        mma4(Ahl, ah, (u32)blo0, (u32)(blo0 >> 32));
        mma4(Bhl, ah, (u32)blo1, (u32)(blo1 >> 32));
        mma4(Alh, al, (u32)bh0, (u32)(bh0 >> 32));
        mma4(Blh, al, (u32)bh1, (u32)(bh1 >> 32));
        blo0 = blo0_n; blo1 = blo1_n;
    }
    float4 i0 = init0 ? *init0 : make_float4(0.f, 0.f, 0.f, 0.f);
    float4 i1 = init1 ? *init1 : make_float4(0.f, 0.f, 0.f, 0.f);
    D0[0] = ((Ahh[0] + Ahl[0]) + Alh[0]) + i0.x;
    D0[1] = ((Ahh[1] + Ahl[1]) + Alh[1]) + i0.y;
    D0[2] = ((Ahh[2] + Ahl[2]) + Alh[2]) + i0.z;
    D0[3] = ((Ahh[3] + Ahl[3]) + Alh[3]) + i0.w;
    D1[0] = ((Bhh[0] + Bhl[0]) + Blh[0]) + i1.x;
    D1[1] = ((Bhh[1] + Bhl[1]) + Blh[1]) + i1.y;
    D1[2] = ((Bhh[2] + Bhl[2]) + Blh[2]) + i1.z;
    D1[3] = ((Bhh[3] + Bhl[3]) + Blh[3]) + i1.w;
}

// ---------------- prep kernel ----------------

__global__ void prep_kernel(
    const float* __restrict__ Wf1, const float* __restrict__ Wf2,
    const float* __restrict__ Wz1, const float* __restrict__ Wz2,
    const float* __restrict__ Wr1, const float* __restrict__ Wr2,
    const float* __restrict__ Wh1, const float* __restrict__ Wh2)
{
    const int i = blockIdx.x * blockDim.x + threadIdx.x;
    if (i >= W_TOTAL) return;

    int off, NT, Kr, Nr, ld;
    const float *S1 = nullptr, *S2 = nullptr;
    if (i < OFF_F2)        { off = OFF_F1;  NT = 13; Kr = 64;  Nr = 100; S1 = Wf1; ld = 100; }
    else if (i < OFF_ZR1)  { off = OFF_F2;  NT = 8;  Kr = 100; Nr = 64;  S1 = Wf2; ld = 64;  }
    else if (i < OFF_Z2)   { off = OFF_ZR1; NT = 25; Kr = 128; Nr = 200; S1 = Wz1; S2 = Wr1; ld = 100; }
    else if (i < OFF_R2)   { off = OFF_Z2;  NT = 8;  Kr = 100; Nr = 64;  S1 = Wz2; ld = 64;  }
    else if (i < OFF_H1)   { off = OFF_R2;  NT = 8;  Kr = 100; Nr = 64;  S1 = Wr2; ld = 64;  }
    else if (i < OFF_H2)   { off = OFF_H1;  NT = 13; Kr = 128; Nr = 100; S1 = Wh1; ld = 100; }
    else                   { off = OFF_H2;  NT = 8;  Kr = 100; Nr = 64;  S1 = Wh2; ld = 64;  }

    const int idx  = i - off;
    const int r    = idx & 1;
    const int lane = (idx >> 1) & 31;
    const int rest = idx >> 6;
    const int nt   = rest % NT;
    const int kc   = rest / NT;
    const int k0   = kc * 16 + (lane & 3) * 2 + (r ? 8 : 0);
    const int n    = nt * 8 + (lane >> 2);

    float x0 = 0.0f, x1 = 0.0f;
    if (n < Nr) {
        const float* S = S1; int nn = n;
        if (S2 && n >= 100) { S = S2; nn = n - 100; }
        if (k0     < Kr) x0 = S[(size_t)k0 * ld + nn];
        if (k0 + 1 < Kr) x1 = S[(size_t)(k0 + 1) * ld + nn];
    }
    const u32 h0 = bf16_hi_bits(x0), h1 = bf16_hi_bits(x1);
    const float r0 = x0 - __uint_as_float(h0 << 16);
    const float r1 = x1 - __uint_as_float(h1 << 16);
    const u32 l0 = bf16_hi_bits(r0), l1 = bf16_hi_bits(r1);
    g_whi[i] = h0 | (h1 << 16);
    g_wlo[i] = l0 | (l1 << 16);
}

// ---------------- main kernel ----------------

__global__ void __launch_bounds__(512, 1) ode_main(
    const float* __restrict__ data, const float* __restrict__ ts,
    const float* __restrict__ bf1, const float* __restrict__ bf2,
    const float* __restrict__ bz1, const float* __restrict__ bz2,
    const float* __restrict__ br1, const float* __restrict__ br2,
    const float* __restrict__ bh1, const float* __restrict__ bh2,
    float* __restrict__ yi_out, float* __restrict__ lat_out)
{
    __shared__ float sY [16][68];
    __shared__ float sYO[16][68];
    __shared__ float sZ [16][68];
    __shared__ float4 sXP[25][32];   // P3 x-half partials per (tile, lane)
    __shared__ float sbf1[100], sbz1[100], sbr1[100], sbh1[100];
    __shared__ float sbf2[64],  sbz2[64],  sbr2[64],  sbh2[64];
    __shared__ float sts_s[TT];
    extern __shared__ __align__(16) u32 dynW[];

    const int tid  = threadIdx.x;
    const int lane = tid & 31;
    const int w    = tid >> 5;       // 0..15
    const int g    = lane >> 2;
    const int tg   = lane & 3;
    const int rowbase = blockIdx.x * 16;

    u32* const actW = dynW + W_TOTAL;
    u32* const aYh  = actW;
    u32* const aYl  = actW + (B_AYL  >> 2);
    u32* const aCh  = actW + (B_ACH  >> 2);
    u32* const aCl  = actW + (B_ACL  >> 2);
    u32* const aHAh = actW + (B_AHAH >> 2);
    u32* const aHAl = actW + (B_AHAL >> 2);
    u32* const aHzh = actW + (B_AHZH >> 2);
    u32* const aHzl = actW + (B_AHZL >> 2);
    u32* const aHrh = actW + (B_AHRH >> 2);
    u32* const aHrl = actW + (B_AHRL >> 2);

    for (int i = tid; i < 16 * 68; i += 512) (&sY[0][0])[i] = 0.0f;
    for (int i = tid; i < ACT_U32; i += 512) actW[i] = 0u;
    for (int i = tid; i < 100; i += 512) {
        sbf1[i] = bf1[i]; sbz1[i] = bz1[i]; sbr1[i] = br1[i]; sbh1[i] = bh1[i];
    }
    for (int i = tid; i < 64; i += 512) {
        sbf2[i] = bf2[i]; sbz2[i] = bz2[i]; sbr2[i] = br2[i]; sbh2[i] = bh2[i];
    }
    for (int i = tid; i < TT; i += 512) sts_s[i] = ts[i];
    {
        const float4* s = (const float4*)g_whi;
        float4* d = (float4*)dynW;
        for (int i = tid; i < W_TOTAL / 4; i += 512) d[i] = s[i];
    }
    __syncthreads();

    // x for step 0 (data index 1)
    if (tid < 256) {
        const int cr0  = tid >> 4;
        const int cd40 = (tid & 15) * 4;
        const float4 v = *reinterpret_cast<const float4*>(
            data + (((size_t)(rowbase + cr0)) * TT + 1) * 64 + cd40);
        const int ci = cr0 * SC_U32 + 32 + (cd40 >> 1);
        store_split(aCh, aCl, ci,     make_float2(v.x, v.y));
        store_split(aCh, aCl, ci + 1, make_float2(v.z, v.w));
    }
    __syncthreads();

    const u32 base_act = smem_u32(actW);
    const int offY = amat_off(lane, SY_U32 * 4);
    const int offC = amat_off(lane, SC_U32 * 4);
    const int offH = amat_off(lane, SH_U32 * 4);
    const u32 adYh  = base_act + B_AYH  + offY, adYl  = base_act + B_AYL  + offY;
    const u32 adCh  = base_act + B_ACH  + offC, adCl  = base_act + B_ACL  + offC;
    const u32 adHAh = base_act + B_AHAH + offH, adHAl = base_act + B_AHAL + offH;
    const u32 adHzh = base_act + B_AHZH + offH, adHzl = base_act + B_AHZL + offH;
    const u32 adHrh = base_act + B_AHRH + offH, adHrl = base_act + B_AHRL + offH;

    const u32* const zr1h = dynW  + OFF_ZR1;
    const u32* const zr1l = g_wlo + OFF_ZR1;

    // W1 cross-precompute tile for warps 13-15 (x-half of P3 tiles 0, 1, 24)
    const int cxt = (w == 13) ? 0 : (w == 14) ? 1 : (w == 15) ? 24 : -1;
    // P3 window tiles: warp 0: y(0) + y(24); warp 1: y(1); warps 2-7: full w;
    // warps 8-15: y(w) + y(w+8)
    const bool p4_isz = (w < 8);
    const int p4_nt = w & 7;

    auto p3_epi = [&](int nt, const float D[4]) {
        const int c0 = nt * 8 + tg * 2;
        if (c0 < 100) {
            const float2 t0 = tanh2(make_float2(D[0] + sbz1[c0], D[1] + sbz1[c0 + 1]));
            const float2 t1 = tanh2(make_float2(D[2] + sbz1[c0], D[3] + sbz1[c0 + 1]));
            const int ci = c0 >> 1;
            store_split(aHzh, aHzl, g * SH_U32 + ci, t0);
            store_split(aHzh, aHzl, (g + 8) * SH_U32 + ci, t1);
        } else {
            const int c = c0 - 100;
            const float2 t0 = tanh2(make_float2(D[0] + sbr1[c], D[1] + sbr1[c + 1]));
            const float2 t1 = tanh2(make_float2(D[2] + sbr1[c], D[3] + sbr1[c + 1]));
            const int ci = c >> 1;
            store_split(aHrh, aHrl, g * SH_U32 + ci, t0);
            store_split(aHrh, aHrl, (g + 8) * SH_U32 + ci, t1);
        }
    };

    // initial pres for W1 of step 0
    u64 pre1  = pre_blo_k(g_wlo + OFF_F1, 0, (w < 13) ? w : -1, 13, lane);
    u64 preCx = pre_blo_k(zr1l, 4, cxt, 25, lane);

    for (int step = 0; step < NSTEPS; ++step) {
        const float dt = (step == 0) ? (sts_s[1] - sts_s[0])
                                     : (sts_s[step - 1] - sts_s[step]);

        // ---- W1: P1 (warps 0-12); cross x-half precompute (warps 13-15) ----
        if (w < 13) {
            float D[4];
            gemm_part<0, 4, 13>(adYh, adYl, dynW + OFF_F1, g_wlo + OFF_F1,
                                w, lane, D, pre1, nullptr);
            const int c0 = w * 8 + tg * 2;
            const float2 t0 = tanh2(make_float2(D[0] + sbf1[c0], D[1] + sbf1[c0 + 1]));
            const float2 t1 = tanh2(make_float2(D[2] + sbf1[c0], D[3] + sbf1[c0 + 1]));
            const int ci = c0 >> 1;
            store_split(aHAh, aHAl, g * SH_U32 + ci, t0);
            store_split(aHAh, aHAl, (g + 8) * SH_U32 + ci, t1);
        } else {
            float D[4];
            gemm_part<4, 8, 25>(adCh, adCl, zr1h, zr1l, cxt, lane, D, preCx, nullptr);
            sXP[cxt][lane] = make_float4(D[0], D[1], D[2], D[3]);
        }
        const u64 pre2 = pre_blo_k(g_wlo + OFF_F2, 0, (w < 8) ? w : -1, 8, lane);
        const u64 preSa = pre_blo_k(zr1l, 4, (w >= 8) ? w : -1, 25, lane);
        const u64 preSb = pre_blo_k(zr1l, 4, (w >= 8) ? w + 8 : -1, 25, lane);
        __syncthreads();

        // ---- W2: P2 (warps 0-7); self x-half precompute (warps 8-15) ----
        if (w < 8) {
            float D[4];
            gemm_part<0, 7, 8>(adHAh, adHAl, dynW + OFF_F2, g_wlo + OFF_F2,
                               w, lane, D, pre2, nullptr);
            const int c0 = w * 8 + tg * 2;
            const float b0 = sbf2[c0], b1 = sbf2[c0 + 1];
            float2 v0, v1;
            v0.x = sY[g][c0]     + dt * (D[0] + b0);
            v0.y = sY[g][c0 + 1] + dt * (D[1] + b1);
            v1.x = sY[g + 8][c0]     + dt * (D[2] + b0);
            v1.y = sY[g + 8][c0 + 1] + dt * (D[3] + b1);
            *(float2*)&sYO[g][c0]     = v0;
            *(float2*)&sYO[g + 8][c0] = v1;
            store_split(aCh, aCl, g * SC_U32 + (c0 >> 1), v0);
            store_split(aCh, aCl, (g + 8) * SC_U32 + (c0 >> 1), v1);
        } else {
            float D0[4], D1[4];
            gemm2_part<4, 8, 25>(adCh, adCl, zr1h, zr1l, w, w + 8, lane,
                                 D0, D1, preSa, preSb, nullptr, nullptr);
            sXP[w][lane]     = make_float4(D0[0], D0[1], D0[2], D0[3]);
            sXP[w + 8][lane] = make_float4(D1[0], D1[1], D1[2], D1[3]);
        }
        // pres for W3 (kc0 lo frags of my y-half / full tiles)
        const int y_nt0 = (w == 0) ? 0 : (w == 1) ? 1 : (w < 8) ? w : w;
        const int y_nt1 = (w == 0) ? 24 : (w >= 8) ? w + 8 : -1;
        const u64 pre3a = pre_blo_k(zr1l, 0, y_nt0, 25, lane);
        const u64 pre3b = pre_blo_k(zr1l, 0, y_nt1, 25, lane);
        __syncthreads();

        // ---- W3: P3 y-halves / full tiles ----
        if (w == 0) {
            float D0[4], D1[4];
            gemm2_part<0, 4, 25>(adCh, adCl, zr1h, zr1l, 0, 24, lane,
                                 D0, D1, pre3a, pre3b, &sXP[0][lane], &sXP[24][lane]);
            p3_epi(0, D0);
            p3_epi(24, D1);
        } else if (w == 1) {
            float D[4];
            gemm_part<0, 4, 25>(adCh, adCl, zr1h, zr1l, 1, lane, D, pre3a,
                                &sXP[1][lane]);
            p3_epi(1, D);
        } else if (w < 8) {
            float D[4];
            gemm_part<0, 8, 25>(adCh, adCl, zr1h, zr1l, w, lane, D, pre3a, nullptr);
            p3_epi(w, D);
        } else {
            float D0[4], D1[4];
            gemm2_part<0, 4, 25>(adCh, adCl, zr1h, zr1l, w, w + 8, lane,
                                 D0, D1, pre3a, pre3b, &sXP[w][lane], &sXP[w + 8][lane]);
            p3_epi(w, D0);
            p3_epi(w + 8, D1);
        }
        const u64 pre4 = pre_blo_k(g_wlo + (p4_isz ? OFF_Z2 : OFF_R2), 0, p4_nt, 8, lane);
        __syncthreads();

        // ---- W4: P4: z (warps 0-7) / r (warps 8-15) ----
        {
            const u32 aH = p4_isz ? adHzh : adHrh;
            const u32 aL = p4_isz ? adHzl : adHrl;
            const u32* bh = dynW  + (p4_isz ? OFF_Z2 : OFF_R2);
            const u32* bl = g_wlo + (p4_isz ? OFF_Z2 : OFF_R2);
            float D[4];
            gemm_part<0, 7, 8>(aH, aL, bh, bl, p4_nt, lane, D, pre4, nullptr);
            const int c0 = p4_nt * 8 + tg * 2;
            if (p4_isz) {
                const float2 s0 = sigmoid2(make_float2(D[0] + sbz2[c0], D[1] + sbz2[c0 + 1]));
                const float2 s1 = sigmoid2(make_float2(D[2] + sbz2[c0], D[3] + sbz2[c0 + 1]));
                *(float2*)&sZ[g][c0]     = s0;
                *(float2*)&sZ[g + 8][c0] = s1;
            } else {
                const float2 s0 = sigmoid2(make_float2(D[0] + sbr2[c0], D[1] + sbr2[c0 + 1]));
                const float2 s1 = sigmoid2(make_float2(D[2] + sbr2[c0], D[3] + sbr2[c0 + 1]));
                float2 v0, v1;
                v0.x = sYO[g][c0]     * s0.x;
                v0.y = sYO[g][c0 + 1] * s0.y;
                v1.x = sYO[g + 8][c0]     * s1.x;
                v1.y = sYO[g + 8][c0 + 1] * s1.y;
                store_split(aCh, aCl, g * SC_U32 + (c0 >> 1), v0);
                store_split(aCh, aCl, (g + 8) * SC_U32 + (c0 >> 1), v1);
            }
        }
        const u64 pre6 = pre_blo_k(g_wlo + OFF_H1, 0, (w < 13) ? w : -1, 13, lane);
        __syncthreads();

        // ---- W5: P6 (warps 0-12) ----
        if (w < 13) {
            float D[4];
            gemm_part<0, 8, 13>(adCh, adCl, dynW + OFF_H1, g_wlo + OFF_H1,
                                w, lane, D, pre6, nullptr);
            const int c0 = w * 8 + tg * 2;
            const float2 t0 = tanh2(make_float2(D[0] + sbh1[c0], D[1] + sbh1[c0 + 1]));
            const float2 t1 = tanh2(make_float2(D[2] + sbh1[c0], D[3] + sbh1[c0 + 1]));
            const int ci = c0 >> 1;
            store_split(aHAh, aHAl, g * SH_U32 + ci, t0);
            store_split(aHAh, aHAl, (g + 8) * SH_U32 + ci, t1);
        }
        const u64 pre7 = pre_blo_k(g_wlo + OFF_H2, 0, (w < 8) ? w : -1, 8, lane);
        __syncthreads();

        // ---- W6: P7 (warps 0-7); x-prefetch (warps 8-15) ----
        if (w < 8) {
            float D[4];
            gemm_part<0, 7, 8>(adHAh, adHAl, dynW + OFF_H2, g_wlo + OFF_H2,
                               w, lane, D, pre7, nullptr);
            const int c0 = w * 8 + tg * 2;
            const float2 h0 = tanh2(make_float2(D[0] + sbh2[c0], D[1] + sbh2[c0 + 1]));
            const float2 h1 = tanh2(make_float2(D[2] + sbh2[c0], D[3] + sbh2[c0 + 1]));
            {
                const float z0 = sZ[g][c0], z1 = sZ[g][c0 + 1];
                float2 v;
                v.x = (1.0f - z0) * h0.x + z0 * sYO[g][c0];
                v.y = (1.0f - z1) * h0.y + z1 * sYO[g][c0 + 1];
                *(float2*)&sY[g][c0] = v;
                store_split(aYh, aYl, g * SY_U32 + (c0 >> 1), v);
            }
            {
                const float z0 = sZ[g + 8][c0], z1 = sZ[g + 8][c0 + 1];
                float2 v;
                v.x = (1.0f - z0) * h1.x + z0 * sYO[g + 8][c0];
                v.y = (1.0f - z1) * h1.y + z1 * sYO[g + 8][c0 + 1];
                *(float2*)&sY[g + 8][c0] = v;
                store_split(aYh, aYl, (g + 8) * SY_U32 + (c0 >> 1), v);
            }
        } else if (step + 2 < TT) {
            const int t2  = tid - 256;
            const int cr2 = t2 >> 4;
            const int cd2 = (t2 & 15) * 4;
            const float4 v = *reinterpret_cast<const float4*>(
                data + (((size_t)(rowbase + cr2)) * TT + (step + 2)) * 64 + cd2);
            const int ci = cr2 * SC_U32 + 32 + (cd2 >> 1);
            store_split(aCh, aCl, ci,     make_float2(v.x, v.y));
            store_split(aCh, aCl, ci + 1, make_float2(v.z, v.w));
        }
        pre1  = pre_blo_k(g_wlo + OFF_F1, 0, (w < 13) ? w : -1, 13, lane);
        preCx = pre_blo_k(zr1l, 4, cxt, 25, lane);
        __syncthreads();

        if (lat_out && tid < 256) {
            const int cr0  = tid >> 4;
            const int cd40 = (tid & 15) * 4;
            const float4 v = *reinterpret_cast<const float4*>(&sY[cr0][cd40]);
            *reinterpret_cast<float4*>(
                lat_out + (((size_t)(rowbase + cr0)) * NSTEPS + step) * 64 + cd40) = v;
        }
    }

    if (yi_out && tid < 256) {
        const int cr0  = tid >> 4;
        const int cd40 = (tid & 15) * 4;
        const float4 v = *reinterpret_cast<const float4*>(&sY[cr0][cd40]);
        *reinterpret_cast<float4*>(yi_out + ((size_t)(rowbase + cr0)) * 64 + cd40) = v;
    }
}

extern "C" void kernel_launch(void* const* d_in, const int* in_sizes, int n_in,
                              void* d_out, int out_size)
{
    const float* data = (const float*)d_in[0];
    const float* ts   = (const float*)d_in[1];
    const float* Wf1  = (const float*)d_in[2];
    const float* bf1  = (const float*)d_in[3];
    const float* Wf2  = (const float*)d_in[4];
    const float* bf2  = (const float*)d_in[5];
    const float* Wz1  = (const float*)d_in[6];
    const float* bz1  = (const float*)d_in[7];
    const float* Wz2  = (const float*)d_in[8];
    const float* bz2  = (const float*)d_in[9];
    const float* Wr1  = (const float*)d_in[10];
    const float* br1  = (const float*)d_in[11];
    const float* Wr2  = (const float*)d_in[12];
    const float* br2  = (const float*)d_in[13];
    const float* Wh1  = (const float*)d_in[14];
    const float* bh1  = (const float*)d_in[15];
    const float* Wh2  = (const float*)d_in[16];
    const float* bh2  = (const float*)d_in[17];

    const long long latN = 2048LL * 199 * 64;
    const long long yiN  = 2048LL * 64;
    float* out = (float*)d_out;
    float* yi_out = nullptr;
    float* lat_out = nullptr;
    if ((long long)out_size == latN + yiN) { yi_out = out; lat_out = out + yiN; }
    else if ((long long)out_size == latN)  { lat_out = out; }
    else if ((long long)out_size == yiN)   { yi_out = out; }
    else if ((long long)out_size > latN)   { yi_out = out; lat_out = out + yiN; }
    else                                   { lat_out = out; }

    cudaFuncSetAttribute(ode_main, cudaFuncAttributeMaxDynamicSharedMemorySize,
                         DYN_U32 * 4);

    prep_kernel<<<(W_TOTAL + 255) / 256, 256>>>(Wf1, Wf2, Wz1, Wz2, Wr1, Wr2, Wh1, Wh2);
    ode_main<<<128, 512, DYN_U32 * 4>>>(data, ts, bf1, bf2, bz1, bz2, br1, br2,
                                        bh1, bh2, yi_out, lat_out);
}

// round 17
// speedup vs baseline: 3.1859x; 1.0138x over previous
#include <cuda_runtime.h>
#include <cstdint>

// ODE-RNN fused scan, round 17: R16 + (a) partial named barrier B1 (warps 0-12
// sync/arrive; warps 13-15 free-run W1+W2), (b) lat_out store fused into the
// P7 epilogue (removes the post-barrier serial tail).

typedef unsigned int u32;
typedef unsigned long long u64;

#define NSTEPS 199
#define TT 200

#define OFF_F1   0
#define OFF_F2   3328
#define OFF_ZR1  6912
#define OFF_Z2   19712
#define OFF_R2   23296
#define OFF_H1   26880
#define OFF_H2   33536
#define W_TOTAL  37120

#define SY_U32   36
#define SC_U32   68
#define SH_U32   60
#define AY_SZ    (16*SY_U32)
#define AC_SZ    (16*SC_U32)
#define AH_SZ    (16*SH_U32)
#define ACT_U32  (2*(AY_SZ + AC_SZ + 3*AH_SZ))
#define B_AYH  0
#define B_AYL  2304
#define B_ACH  4608
#define B_ACL  8960
#define B_AHAH 13312
#define B_AHAL 17152
#define B_AHZH 20992
#define B_AHZL 24832
#define B_AHRH 28672
#define B_AHRL 32512

#define DYN_U32 (W_TOTAL + ACT_U32)

__device__ __align__(16) u32 g_whi[W_TOTAL];
__device__ __align__(16) u32 g_wlo[W_TOTAL];

// ---------------- helpers ----------------

__device__ __forceinline__ u32 bf16_hi_bits(float x) {
    const u32 u = __float_as_uint(x);
    return (u + 0x7fffu + ((u >> 16) & 1u)) >> 16;
}
__device__ __forceinline__ float2 tanh2(float2 x) {
    const float e0 = __expf(2.0f * fminf(fmaxf(x.x, -30.0f), 30.0f));
    const float e1 = __expf(2.0f * fminf(fmaxf(x.y, -30.0f), 30.0f));
    const float a0 = e0 + 1.0f, a1 = e1 + 1.0f;
    const float d = __fdividef(2.0f, a0 * a1);
    return make_float2(1.0f - d * a1, 1.0f - d * a0);
}
__device__ __forceinline__ float2 sigmoid2(float2 x) {
    const float e0 = __expf(-fminf(fmaxf(x.x, -30.0f), 30.0f));
    const float e1 = __expf(-fminf(fmaxf(x.y, -30.0f), 30.0f));
    const float a0 = 1.0f + e0, a1 = 1.0f + e1;
    const float d = __fdividef(1.0f, a0 * a1);
    return make_float2(d * a1, d * a0);
}
__device__ __forceinline__ void bsplit(float2 x, u32& h, u32& l) {
    u32 hh;
    asm("cvt.rn.bf16x2.f32 %0, %1, %2;" : "=r"(hh) : "f"(x.y), "f"(x.x));
    const float r0 = x.x - __uint_as_float(hh << 16);
    const float r1 = x.y - __uint_as_float(hh & 0xffff0000u);
    u32 ll;
    asm("cvt.rn.bf16x2.f32 %0, %1, %2;" : "=r"(ll) : "f"(r1), "f"(r0));
    h = hh; l = ll;
}
__device__ __forceinline__ void store_split(u32* hp, u32* lp, int idx, float2 v) {
    u32 h, l; bsplit(v, h, l); hp[idx] = h; lp[idx] = l;
}
__device__ __forceinline__ void mma4(float d[4], const u32 a[4], u32 b0, u32 b1) {
    asm("mma.sync.aligned.m16n8k16.row.col.f32.bf16.bf16.f32 "
        "{%0,%1,%2,%3}, {%4,%5,%6,%7}, {%8,%9}, {%0,%1,%2,%3};"
        : "+f"(d[0]), "+f"(d[1]), "+f"(d[2]), "+f"(d[3])
        : "r"(a[0]), "r"(a[1]), "r"(a[2]), "r"(a[3]), "r"(b0), "r"(b1));
}
__device__ __forceinline__ void ldm4(u32 r[4], u32 addr) {
    asm volatile("ldmatrix.sync.aligned.m8n8.x4.shared.b16 {%0,%1,%2,%3}, [%4];"
        : "=r"(r[0]), "=r"(r[1]), "=r"(r[2]), "=r"(r[3]) : "r"(addr));
}
__device__ __forceinline__ u32 smem_u32(const void* p) {
    return (u32)__cvta_generic_to_shared(p);
}
__device__ __forceinline__ int amat_off(int lane, int strideB) {
    const int r = lane & 7, m = lane >> 3;
    return (r + ((m & 1) << 3)) * strideB + ((m >> 1) << 4);
}
__device__ __forceinline__ u64 pre_blo_k(const u32* __restrict__ gBlo,
                                         int kc, int nt, int NT, int lane) {
    return (nt >= 0)
        ? *(const u64*)(gBlo + ((kc * NT + nt) * 32 + lane) * 2) : 0ull;
}

// partial GEMM over kc in [KC0,KC1); optional fp32 init added at the end.
template<int KC0, int KC1, int NT>
__device__ __forceinline__ void gemm_part(
    const u32 aHi, const u32 aLo,
    const u32* __restrict__ sBhi, const u32* __restrict__ gBlo,
    const int nt, const int lane, float D[4], u64 pre, const float4* init)
{
    float Dhh[4] = {0,0,0,0}, Dhl[4] = {0,0,0,0}, Dlh[4] = {0,0,0,0};
    u64 blo = pre;
#pragma unroll
    for (int kc = KC0; kc < KC1; ++kc) {
        u64 blo_n = 0ull;
        if (kc + 1 < KC1)
            blo_n = *(const u64*)(gBlo + (((kc + 1) * NT + nt) * 32 + lane) * 2);
        u32 ah[4], al[4];
        ldm4(ah, aHi + kc * 32);
        ldm4(al, aLo + kc * 32);
        const u64 bh = *(const u64*)(sBhi + ((kc * NT + nt) * 32 + lane) * 2);
        mma4(Dhh, ah, (u32)bh, (u32)(bh >> 32));
        mma4(Dhl, ah, (u32)blo, (u32)(blo >> 32));
        mma4(Dlh, al, (u32)bh, (u32)(bh >> 32));
        blo = blo_n;
    }
    float4 iv = init ? *init : make_float4(0.f, 0.f, 0.f, 0.f);
    D[0] = ((Dhh[0] + Dhl[0]) + Dlh[0]) + iv.x;
    D[1] = ((Dhh[1] + Dhl[1]) + Dlh[1]) + iv.y;
    D[2] = ((Dhh[2] + Dhl[2]) + Dlh[2]) + iv.z;
    D[3] = ((Dhh[3] + Dhl[3]) + Dlh[3]) + iv.w;
}

// two-tile partial GEMM sharing A loads; optional inits.
template<int KC0, int KC1, int NT>
__device__ __forceinline__ void gemm2_part(
    const u32 aHi, const u32 aLo,
    const u32* __restrict__ sBhi, const u32* __restrict__ gBlo,
    const int nt0, const int nt1, const int lane,
    float D0[4], float D1[4], u64 pre0, u64 pre1,
    const float4* init0, const float4* init1)
{
    float Ahh[4] = {0,0,0,0}, Ahl[4] = {0,0,0,0}, Alh[4] = {0,0,0,0};
    float Bhh[4] = {0,0,0,0}, Bhl[4] = {0,0,0,0}, Blh[4] = {0,0,0,0};
    u64 blo0 = pre0, blo1 = pre1;
#pragma unroll
    for (int kc = KC0; kc < KC1; ++kc) {
        u64 blo0_n = 0ull, blo1_n = 0ull;
        if (kc + 1 < KC1) {
            blo0_n = *(const u64*)(gBlo + (((kc + 1) * NT + nt0) * 32 + lane) * 2);
            blo1_n = *(const u64*)(gBlo + (((kc + 1) * NT + nt1) * 32 + lane) * 2);
        }
        u32 ah[4], al[4];
        ldm4(ah, aHi + kc * 32);
        ldm4(al, aLo + kc * 32);
        const u64 bh0 = *(const u64*)(sBhi + ((kc * NT + nt0) * 32 + lane) * 2);
        const u64 bh1 = *(const u64*)(sBhi + ((kc * NT + nt1) * 32 + lane) * 2);
        mma4(Ahh, ah, (u32)bh0, (u32)(bh0 >> 32));
        mma4(Bhh, ah, (u32)bh1, (u32)(bh1 >> 32));
        mma4(Ahl, ah, (u32)blo0, (u32)(blo0 >> 32));
        mma4(Bhl, ah, (u32)blo1, (u32)(blo1 >> 32));
        mma4(Alh, al, (u32)bh0, (u32)(bh0 >> 32));
        mma4(Blh, al, (u32)bh1, (u32)(bh1 >> 32));
        blo0 = blo0_n; blo1 = blo1_n;
    }
    float4 i0 = init0 ? *init0 : make_float4(0.f, 0.f, 0.f, 0.f);
    float4 i1 = init1 ? *init1 : make_float4(0.f, 0.f, 0.f, 0.f);
    D0[0] = ((Ahh[0] + Ahl[0]) + Alh[0]) + i0.x;
    D0[1] = ((Ahh[1] + Ahl[1]) + Alh[1]) + i0.y;
    D0[2] = ((Ahh[2] + Ahl[2]) + Alh[2]) + i0.z;
    D0[3] = ((Ahh[3] + Ahl[3]) + Alh[3]) + i0.w;
    D1[0] = ((Bhh[0] + Bhl[0]) + Blh[0]) + i1.x;
    D1[1] = ((Bhh[1] + Bhl[1]) + Blh[1]) + i1.y;
    D1[2] = ((Bhh[2] + Bhl[2]) + Blh[2]) + i1.z;
    D1[3] = ((Bhh[3] + Bhl[3]) + Blh[3]) + i1.w;
}

// ---------------- prep kernel ----------------

__global__ void prep_kernel(
    const float* __restrict__ Wf1, const float* __restrict__ Wf2,
    const float* __restrict__ Wz1, const float* __restrict__ Wz2,
    const float* __restrict__ Wr1, const float* __restrict__ Wr2,
    const float* __restrict__ Wh1, const float* __restrict__ Wh2)
{
    const int i = blockIdx.x * blockDim.x + threadIdx.x;
    if (i >= W_TOTAL) return;

    int off, NT, Kr, Nr, ld;
    const float *S1 = nullptr, *S2 = nullptr;
    if (i < OFF_F2)        { off = OFF_F1;  NT = 13; Kr = 64;  Nr = 100; S1 = Wf1; ld = 100; }
    else if (i < OFF_ZR1)  { off = OFF_F2;  NT = 8;  Kr = 100; Nr = 64;  S1 = Wf2; ld = 64;  }
    else if (i < OFF_Z2)   { off = OFF_ZR1; NT = 25; Kr = 128; Nr = 200; S1 = Wz1; S2 = Wr1; ld = 100; }
    else if (i < OFF_R2)   { off = OFF_Z2;  NT = 8;  Kr = 100; Nr = 64;  S1 = Wz2; ld = 64;  }
    else if (i < OFF_H1)   { off = OFF_R2;  NT = 8;  Kr = 100; Nr = 64;  S1 = Wr2; ld = 64;  }
    else if (i < OFF_H2)   { off = OFF_H1;  NT = 13; Kr = 128; Nr = 100; S1 = Wh1; ld = 100; }
    else                   { off = OFF_H2;  NT = 8;  Kr = 100; Nr = 64;  S1 = Wh2; ld = 64;  }

    const int idx  = i - off;
    const int r    = idx & 1;
    const int lane = (idx >> 1) & 31;
    const int rest = idx >> 6;
    const int nt   = rest % NT;
    const int kc   = rest / NT;
    const int k0   = kc * 16 + (lane & 3) * 2 + (r ? 8 : 0);
    const int n    = nt * 8 + (lane >> 2);

    float x0 = 0.0f, x1 = 0.0f;
    if (n < Nr) {
        const float* S = S1; int nn = n;
        if (S2 && n >= 100) { S = S2; nn = n - 100; }
        if (k0     < Kr) x0 = S[(size_t)k0 * ld + nn];
        if (k0 + 1 < Kr) x1 = S[(size_t)(k0 + 1) * ld + nn];
    }
    const u32 h0 = bf16_hi_bits(x0), h1 = bf16_hi_bits(x1);
    const float r0 = x0 - __uint_as_float(h0 << 16);
    const float r1 = x1 - __uint_as_float(h1 << 16);
    const u32 l0 = bf16_hi_bits(r0), l1 = bf16_hi_bits(r1);
    g_whi[i] = h0 | (h1 << 16);
    g_wlo[i] = l0 | (l1 << 16);
}

// ---------------- main kernel ----------------

__global__ void __launch_bounds__(512, 1) ode_main(
    const float* __restrict__ data, const float* __restrict__ ts,
    const float* __restrict__ bf1, const float* __restrict__ bf2,
    const float* __restrict__ bz1, const float* __restrict__ bz2,
    const float* __restrict__ br1, const float* __restrict__ br2,
    const float* __restrict__ bh1, const float* __restrict__ bh2,
    float* __restrict__ yi_out, float* __restrict__ lat_out)
{
    __shared__ float sY [16][68];
    __shared__ float sYO[16][68];
    __shared__ float sZ [16][68];
    __shared__ float4 sXP[25][32];   // P3 x-half partials per (tile, lane)
    __shared__ float sbf1[100], sbz1[100], sbr1[100], sbh1[100];
    __shared__ float sbf2[64],  sbz2[64],  sbr2[64],  sbh2[64];
    __shared__ float sts_s[TT];
    extern __shared__ __align__(16) u32 dynW[];

    const int tid  = threadIdx.x;
    const int lane = tid & 31;
    const int w    = tid >> 5;       // 0..15
    const int g    = lane >> 2;
    const int tg   = lane & 3;
    const int rowbase = blockIdx.x * 16;

    u32* const actW = dynW + W_TOTAL;
    u32* const aYh  = actW;
    u32* const aYl  = actW + (B_AYL  >> 2);
    u32* const aCh  = actW + (B_ACH  >> 2);
    u32* const aCl  = actW + (B_ACL  >> 2);
    u32* const aHAh = actW + (B_AHAH >> 2);
    u32* const aHAl = actW + (B_AHAL >> 2);
    u32* const aHzh = actW + (B_AHZH >> 2);
    u32* const aHzl = actW + (B_AHZL >> 2);
    u32* const aHrh = actW + (B_AHRH >> 2);
    u32* const aHrl = actW + (B_AHRL >> 2);

    for (int i = tid; i < 16 * 68; i += 512) (&sY[0][0])[i] = 0.0f;
    for (int i = tid; i < ACT_U32; i += 512) actW[i] = 0u;
    for (int i = tid; i < 100; i += 512) {
        sbf1[i] = bf1[i]; sbz1[i] = bz1[i]; sbr1[i] = br1[i]; sbh1[i] = bh1[i];
    }
    for (int i = tid; i < 64; i += 512) {
        sbf2[i] = bf2[i]; sbz2[i] = bz2[i]; sbr2[i] = br2[i]; sbh2[i] = bh2[i];
    }
    for (int i = tid; i < TT; i += 512) sts_s[i] = ts[i];
    {
        const float4* s = (const float4*)g_whi;
        float4* d = (float4*)dynW;
        for (int i = tid; i < W_TOTAL / 4; i += 512) d[i] = s[i];
    }
    __syncthreads();

    // x for step 0 (data index 1)
    if (tid < 256) {
        const int cr0  = tid >> 4;
        const int cd40 = (tid & 15) * 4;
        const float4 v = *reinterpret_cast<const float4*>(
            data + (((size_t)(rowbase + cr0)) * TT + 1) * 64 + cd40);
        const int ci = cr0 * SC_U32 + 32 + (cd40 >> 1);
        store_split(aCh, aCl, ci,     make_float2(v.x, v.y));
        store_split(aCh, aCl, ci + 1, make_float2(v.z, v.w));
    }
    __syncthreads();

    const u32 base_act = smem_u32(actW);
    const int offY = amat_off(lane, SY_U32 * 4);
    const int offC = amat_off(lane, SC_U32 * 4);
    const int offH = amat_off(lane, SH_U32 * 4);
    const u32 adYh  = base_act + B_AYH  + offY, adYl  = base_act + B_AYL  + offY;
    const u32 adCh  = base_act + B_ACH  + offC, adCl  = base_act + B_ACL  + offC;
    const u32 adHAh = base_act + B_AHAH + offH, adHAl = base_act + B_AHAL + offH;
    const u32 adHzh = base_act + B_AHZH + offH, adHzl = base_act + B_AHZL + offH;
    const u32 adHrh = base_act + B_AHRH + offH, adHrl = base_act + B_AHRL + offH;

    const u32* const zr1h = dynW  + OFF_ZR1;
    const u32* const zr1l = g_wlo + OFF_ZR1;

    const int cxt = (w == 13) ? 0 : (w == 14) ? 1 : (w == 15) ? 24 : -1;
    const bool p4_isz = (w < 8);
    const int p4_nt = w & 7;

    auto p3_epi = [&](int nt, const float D[4]) {
        const int c0 = nt * 8 + tg * 2;
        if (c0 < 100) {
            const float2 t0 = tanh2(make_float2(D[0] + sbz1[c0], D[1] + sbz1[c0 + 1]));
            const float2 t1 = tanh2(make_float2(D[2] + sbz1[c0], D[3] + sbz1[c0 + 1]));
            const int ci = c0 >> 1;
            store_split(aHzh, aHzl, g * SH_U32 + ci, t0);
            store_split(aHzh, aHzl, (g + 8) * SH_U32 + ci, t1);
        } else {
            const int c = c0 - 100;
            const float2 t0 = tanh2(make_float2(D[0] + sbr1[c], D[1] + sbr1[c + 1]));
            const float2 t1 = tanh2(make_float2(D[2] + sbr1[c], D[3] + sbr1[c + 1]));
            const int ci = c >> 1;
            store_split(aHrh, aHrl, g * SH_U32 + ci, t0);
            store_split(aHrh, aHrl, (g + 8) * SH_U32 + ci, t1);
        }
    };

    u64 pre1  = pre_blo_k(g_wlo + OFF_F1, 0, (w < 13) ? w : -1, 13, lane);
    u64 preCx = pre_blo_k(zr1l, 4, cxt, 25, lane);

    for (int step = 0; step < NSTEPS; ++step) {
        const float dt = (step == 0) ? (sts_s[1] - sts_s[0])
                                     : (sts_s[step - 1] - sts_s[step]);

        // ---- W1: P1 (warps 0-12); cross x-half precompute (warps 13-15) ----
        if (w < 13) {
            float D[4];
            gemm_part<0, 4, 13>(adYh, adYl, dynW + OFF_F1, g_wlo + OFF_F1,
                                w, lane, D, pre1, nullptr);
            const int c0 = w * 8 + tg * 2;
            const float2 t0 = tanh2(make_float2(D[0] + sbf1[c0], D[1] + sbf1[c0 + 1]));
            const float2 t1 = tanh2(make_float2(D[2] + sbf1[c0], D[3] + sbf1[c0 + 1]));
            const int ci = c0 >> 1;
            store_split(aHAh, aHAl, g * SH_U32 + ci, t0);
            store_split(aHAh, aHAl, (g + 8) * SH_U32 + ci, t1);
        } else {
            float D[4];
            gemm_part<4, 8, 25>(adCh, adCl, zr1h, zr1l, cxt, lane, D, preCx, nullptr);
            sXP[cxt][lane] = make_float4(D[0], D[1], D[2], D[3]);
        }
        const u64 pre2 = pre_blo_k(g_wlo + OFF_F2, 0, (w < 8) ? w : -1, 8, lane);
        const u64 preSa = pre_blo_k(zr1l, 4, (w >= 8) ? w : -1, 25, lane);
        const u64 preSb = pre_blo_k(zr1l, 4, (w >= 8) ? w + 8 : -1, 25, lane);

        // ---- B1: partial barrier. aHA producers = warps 0-12; consumers =
        //      warps 0-7. Warps 13-15 free-run (their work touches only
        //      stable aC-x and private sXP slots; reconverges at B2). ----
        if (w < 8) {
            asm volatile("bar.sync 1, 416;" ::: "memory");
        } else if (w < 13) {
            asm volatile("bar.arrive 1, 416;" ::: "memory");
        }

        // ---- W2: P2 (warps 0-7); self x-half precompute (warps 8-15) ----
        if (w < 8) {
            float D[4];
            gemm_part<0, 7, 8>(adHAh, adHAl, dynW + OFF_F2, g_wlo + OFF_F2,
                               w, lane, D, pre2, nullptr);
            const int c0 = w * 8 + tg * 2;
            const float b0 = sbf2[c0], b1 = sbf2[c0 + 1];
            float2 v0, v1;
            v0.x = sY[g][c0]     + dt * (D[0] + b0);
            v0.y = sY[g][c0 + 1] + dt * (D[1] + b1);
            v1.x = sY[g + 8][c0]     + dt * (D[2] + b0);
            v1.y = sY[g + 8][c0 + 1] + dt * (D[3] + b1);
            *(float2*)&sYO[g][c0]     = v0;
            *(float2*)&sYO[g + 8][c0] = v1;
            store_split(aCh, aCl, g * SC_U32 + (c0 >> 1), v0);
            store_split(aCh, aCl, (g + 8) * SC_U32 + (c0 >> 1), v1);
        } else {
            float D0[4], D1[4];
            gemm2_part<4, 8, 25>(adCh, adCl, zr1h, zr1l, w, w + 8, lane,
                                 D0, D1, preSa, preSb, nullptr, nullptr);
            sXP[w][lane]     = make_float4(D0[0], D0[1], D0[2], D0[3]);
            sXP[w + 8][lane] = make_float4(D1[0], D1[1], D1[2], D1[3]);
        }
        const int y_nt0 = (w == 0) ? 0 : (w == 1) ? 1 : (w < 8) ? w : w;
        const int y_nt1 = (w == 0) ? 24 : (w >= 8) ? w + 8 : -1;
        const u64 pre3a = pre_blo_k(zr1l, 0, y_nt0, 25, lane);
        const u64 pre3b = pre_blo_k(zr1l, 0, y_nt1, 25, lane);
        __syncthreads();

        // ---- W3: P3 y-halves / full tiles ----
        if (w == 0) {
            float D0[4], D1[4];
            gemm2_part<0, 4, 25>(adCh, adCl, zr1h, zr1l, 0, 24, lane,
                                 D0, D1, pre3a, pre3b, &sXP[0][lane], &sXP[24][lane]);
            p3_epi(0, D0);
            p3_epi(24, D1);
        } else if (w == 1) {
            float D[4];
            gemm_part<0, 4, 25>(adCh, adCl, zr1h, zr1l, 1, lane, D, pre3a,
                                &sXP[1][lane]);
            p3_epi(1, D);
        } else if (w < 8) {
            float D[4];
            gemm_part<0, 8, 25>(adCh, adCl, zr1h, zr1l, w, lane, D, pre3a, nullptr);
            p3_epi(w, D);
        } else {
            float D0[4], D1[4];
            gemm2_part<0, 4, 25>(adCh, adCl, zr1h, zr1l, w, w + 8, lane,
                                 D0, D1, pre3a, pre3b, &sXP[w][lane], &sXP[w + 8][lane]);
            p3_epi(w, D0);
            p3_epi(w + 8, D1);
        }
        const u64 pre4 = pre_blo_k(g_wlo + (p4_isz ? OFF_Z2 : OFF_R2), 0, p4_nt, 8, lane);
        __syncthreads();

        // ---- W4: P4: z (warps 0-7) / r (warps 8-15) ----
        {
            const u32 aH = p4_isz ? adHzh : adHrh;
            const u32 aL = p4_isz ? adHzl : adHrl;
            const u32* bh = dynW  + (p4_isz ? OFF_Z2 : OFF_R2);
            const u32* bl = g_wlo + (p4_isz ? OFF_Z2 : OFF_R2);
            float D[4];
            gemm_part<0, 7, 8>(aH, aL, bh, bl, p4_nt, lane, D, pre4, nullptr);
            const int c0 = p4_nt * 8 + tg * 2;
            if (p4_isz) {
                const float2 s0 = sigmoid2(make_float2(D[0] + sbz2[c0], D[1] + sbz2[c0 + 1]));
                const float2 s1 = sigmoid2(make_float2(D[2] + sbz2[c0], D[3] + sbz2[c0 + 1]));
                *(float2*)&sZ[g][c0]     = s0;
                *(float2*)&sZ[g + 8][c0] = s1;
            } else {
                const float2 s0 = sigmoid2(make_float2(D[0] + sbr2[c0], D[1] + sbr2[c0 + 1]));
                const float2 s1 = sigmoid2(make_float2(D[2] + sbr2[c0], D[3] + sbr2[c0 + 1]));
                float2 v0, v1;
                v0.x = sYO[g][c0]     * s0.x;
                v0.y = sYO[g][c0 + 1] * s0.y;
                v1.x = sYO[g + 8][c0]     * s1.x;
                v1.y = sYO[g + 8][c0 + 1] * s1.y;
                store_split(aCh, aCl, g * SC_U32 + (c0 >> 1), v0);
                store_split(aCh, aCl, (g + 8) * SC_U32 + (c0 >> 1), v1);
            }
        }
        const u64 pre6 = pre_blo_k(g_wlo + OFF_H1, 0, (w < 13) ? w : -1, 13, lane);
        __syncthreads();

        // ---- W5: P6 (warps 0-12) ----
        if (w < 13) {
            float D[4];
            gemm_part<0, 8, 13>(adCh, adCl, dynW + OFF_H1, g_wlo + OFF_H1,
                                w, lane, D, pre6, nullptr);
            const int c0 = w * 8 + tg * 2;
            const float2 t0 = tanh2(make_float2(D[0] + sbh1[c0], D[1] + sbh1[c0 + 1]));
            const float2 t1 = tanh2(make_float2(D[2] + sbh1[c0], D[3] + sbh1[c0 + 1]));
            const int ci = c0 >> 1;
            store_split(aHAh, aHAl, g * SH_U32 + ci, t0);
            store_split(aHAh, aHAl, (g + 8) * SH_U32 + ci, t1);
        }
        const u64 pre7 = pre_blo_k(g_wlo + OFF_H2, 0, (w < 8) ? w : -1, 8, lane);
        __syncthreads();

        // ---- W6: P7 (warps 0-7, with fused lat_out store); x-prefetch (8-15) ----
        if (w < 8) {
            float D[4];
            gemm_part<0, 7, 8>(adHAh, adHAl, dynW + OFF_H2, g_wlo + OFF_H2,
                               w, lane, D, pre7, nullptr);
            const int c0 = w * 8 + tg * 2;
            const float2 h0 = tanh2(make_float2(D[0] + sbh2[c0], D[1] + sbh2[c0 + 1]));
            const float2 h1 = tanh2(make_float2(D[2] + sbh2[c0], D[3] + sbh2[c0 + 1]));
            {
                const float z0 = sZ[g][c0], z1 = sZ[g][c0 + 1];
                float2 v;
                v.x = (1.0f - z0) * h0.x + z0 * sYO[g][c0];
                v.y = (1.0f - z1) * h0.y + z1 * sYO[g][c0 + 1];
                *(float2*)&sY[g][c0] = v;
                store_split(aYh, aYl, g * SY_U32 + (c0 >> 1), v);
                if (lat_out)
                    *reinterpret_cast<float2*>(
                        lat_out + (((size_t)(rowbase + g)) * NSTEPS + step) * 64 + c0) = v;
            }
            {
                const float z0 = sZ[g + 8][c0], z1 = sZ[g + 8][c0 + 1];
                float2 v;
                v.x = (1.0f - z0) * h1.x + z0 * sYO[g + 8][c0];
                v.y = (1.0f - z1) * h1.y + z1 * sYO[g + 8][c0 + 1];
                *(float2*)&sY[g + 8][c0] = v;
                store_split(aYh, aYl, (g + 8) * SY_U32 + (c0 >> 1), v);
                if (lat_out)
                    *reinterpret_cast<float2*>(
                        lat_out + (((size_t)(rowbase + g + 8)) * NSTEPS + step) * 64 + c0) = v;
            }
        } else if (step + 2 < TT) {
            const int t2  = tid - 256;
            const int cr2 = t2 >> 4;
            const int cd2 = (t2 & 15) * 4;
            const float4 v = *reinterpret_cast<const float4*>(
                data + (((size_t)(rowbase + cr2)) * TT + (step + 2)) * 64 + cd2);
            const int ci = cr2 * SC_U32 + 32 + (cd2 >> 1);
            store_split(aCh, aCl, ci,     make_float2(v.x, v.y));
            store_split(aCh, aCl, ci + 1, make_float2(v.z, v.w));
        }
        pre1  = pre_blo_k(g_wlo + OFF_F1, 0, (w < 13) ? w : -1, 13, lane);
        preCx = pre_blo_k(zr1l, 4, cxt, 25, lane);
        __syncthreads();
    }

    if (yi_out && tid < 256) {
        const int cr0  = tid >> 4;
        const int cd40 = (tid & 15) * 4;
        const float4 v = *reinterpret_cast<const float4*>(&sY[cr0][cd40]);
        *reinterpret_cast<float4*>(yi_out + ((size_t)(rowbase + cr0)) * 64 + cd40) = v;
    }
}

extern "C" void kernel_launch(void* const* d_in, const int* in_sizes, int n_in,
                              void* d_out, int out_size)
{
    const float* data = (const float*)d_in[0];
    const float* ts   = (const float*)d_in[1];
    const float* Wf1  = (const float*)d_in[2];
    const float* bf1  = (const float*)d_in[3];
    const float* Wf2  = (const float*)d_in[4];
    const float* bf2  = (const float*)d_in[5];
    const float* Wz1  = (const float*)d_in[6];
    const float* bz1  = (const float*)d_in[7];
    const float* Wz2  = (const float*)d_in[8];
    const float* bz2  = (const float*)d_in[9];
    const float* Wr1  = (const float*)d_in[10];
    const float* br1  = (const float*)d_in[11];
    const float* Wr2  = (const float*)d_in[12];
    const float* br2  = (const float*)d_in[13];
    const float* Wh1  = (const float*)d_in[14];
    const float* bh1  = (const float*)d_in[15];
    const float* Wh2  = (const float*)d_in[16];
    const float* bh2  = (const float*)d_in[17];

    const long long latN = 2048LL * 199 * 64;
    const long long yiN  = 2048LL * 64;
    float* out = (float*)d_out;
    float* yi_out = nullptr;
    float* lat_out = nullptr;
    if ((long long)out_size == latN + yiN) { yi_out = out; lat_out = out + yiN; }
    else if ((long long)out_size == latN)  { lat_out = out; }
    else if ((long long)out_size == yiN)   { yi_out = out; }
    else if ((long long)out_size > latN)   { yi_out = out; lat_out = out + yiN; }
    else                                   { lat_out = out; }

    cudaFuncSetAttribute(ode_main, cudaFuncAttributeMaxDynamicSharedMemorySize,
                         DYN_U32 * 4);

    prep_kernel<<<(W_TOTAL + 255) / 256, 256>>>(Wf1, Wf2, Wz1, Wz2, Wr1, Wr2, Wh1, Wh2);
    ode_main<<<128, 512, DYN_U32 * 4>>>(data, ts, bf1, bf2, bz1, bz2, br1, br2,
                                        bh1, bh2, yi_out, lat_out);
}